// round 7
// baseline (speedup 1.0000x reference)
#include <cuda_runtime.h>
#include <cuda_bf16.h>
#include <cstdint>
#include <math.h>

#define NN 4096
#define EE 131072
#define HH 256

#define QSCALE_F (0.17677669529663687f * 1.4426950408889634f)

// ---------------- scratch (static device globals; no allocation) ----------------
__device__ float g_tmp [NN*HH];
__device__ float g_h   [NN*HH];
__device__ float g_h3  [NN*HH];
__device__ float g_deg [NN];
__device__ float g_dinv[NN];
__device__ float g_vtmp[NN*HH];      // V columns of qkv (fp32 staging)
__device__ float g_attn[NN*HH];
__device__ float g_hid [NN*128];
__device__ float g_hid2[NN*128];
__device__ int   g_rowptr[NN+1];
__device__ int   g_cursor[NN];
__device__ int   g_esrc [EE];
__device__ float g_enorm[EE];
__device__ __nv_bfloat16 g_Qb[8*NN*32];   // [h][n][d], pre-scaled by 1/sqrt(32)*log2e
__device__ __nv_bfloat16 g_Kb[8*NN*32];   // [h][n][d]
__device__ __nv_bfloat16 g_Vb[8*32*NN];   // [h][d][n]  (transposed)

// ---------------- async-copy helpers ---------------------------------------------
__device__ __forceinline__ void cp_async16(void* smem, const void* gmem) {
    uint32_t s = (uint32_t)__cvta_generic_to_shared(smem);
    asm volatile("cp.async.ca.shared.global [%0], [%1], 16;\n" :: "r"(s), "l"(gmem));
}
#define CP_COMMIT() asm volatile("cp.async.commit_group;\n" ::: "memory")
#define CP_WAIT(n)  asm volatile("cp.async.wait_group %0;\n" :: "n"(n) : "memory")

// ---------------- mma wrappers ----------------------------------------------------
__device__ __forceinline__ void mma_tf32(float* c, const uint32_t* a, uint32_t b0, uint32_t b1) {
    asm volatile(
        "mma.sync.aligned.m16n8k8.row.col.f32.tf32.tf32.f32 "
        "{%0,%1,%2,%3}, {%4,%5,%6,%7}, {%8,%9}, {%0,%1,%2,%3};\n"
        : "+f"(c[0]), "+f"(c[1]), "+f"(c[2]), "+f"(c[3])
        : "r"(a[0]), "r"(a[1]), "r"(a[2]), "r"(a[3]), "r"(b0), "r"(b1));
}
__device__ __forceinline__ void mma_bf16(float* c, const uint32_t* a, uint32_t b0, uint32_t b1) {
    asm volatile(
        "mma.sync.aligned.m16n8k16.row.col.f32.bf16.bf16.f32 "
        "{%0,%1,%2,%3}, {%4,%5,%6,%7}, {%8,%9}, {%0,%1,%2,%3};\n"
        : "+f"(c[0]), "+f"(c[1]), "+f"(c[2]), "+f"(c[3])
        : "r"(a[0]), "r"(a[1]), "r"(a[2]), "r"(a[3]), "r"(b0), "r"(b1));
}
__device__ __forceinline__ uint32_t pack_bf16(float lo, float hi) {
    __nv_bfloat162 v = __floats2bfloat162_rn(lo, hi);
    return *(uint32_t*)&v;
}

// QKV epilogue store: n in [0,768). Block-uniform type (64-col tiles).
__device__ __forceinline__ void store_qkv(int row, int n, float a, float b) {
    int d = n & 31;
    int hh = (n >> 5) & 7;
    if (n < 256) {
        *(uint32_t*)(g_Qb + ((size_t)hh*NN + row)*32 + d) = pack_bf16(a*QSCALE_F, b*QSCALE_F);
    } else if (n < 512) {
        *(uint32_t*)(g_Kb + ((size_t)hh*NN + row)*32 + d) = pack_bf16(a, b);
    } else {
        *(float2*)(g_vtmp + (size_t)row*256 + (n - 512)) = make_float2(a, b);
    }
}

// ---------------- pipelined tf32 GEMM (64x64 tiles, 3-stage ring) -----------------
// C[M,N] = A[M,K] @ B (+bias)(+SRC)(relu).  TRANSB: B is [N,K] (torch weight).
// 8 warps (4x2), warp tile 16x32 via m16n8k8. One __syncthreads per k-iter.
template<bool TRANSB, bool RELU, bool ADDSRC, bool QKV>
__global__ void __launch_bounds__(256) gemm_tf32(
    const float* __restrict__ A, const float* __restrict__ B,
    const float* __restrict__ bias, const float* __restrict__ SRC,
    float* __restrict__ C, int M, int N, int K)
{
    __shared__ float As[3][64*20];      // [m][k] stride 20
    __shared__ float Bs[3][1280];       // TRANSB: [n][k] s20; else [k][n] s72

    const int tid  = threadIdx.x;
    const int w    = tid >> 5, lane = tid & 31;
    const int g    = lane >> 2, t = lane & 3;
    const int wm   = w & 3, wn = w >> 2;            // 4x2 warp grid
    const int m0   = blockIdx.y * 64, n0 = blockIdx.x * 64;
    const int KT   = K >> 4;

    const int ar  = tid >> 2, ac4 = (tid & 3) * 4;   // A: 64 rows x 4-chunk
    const int bnr = tid >> 2, bnc = (tid & 3) * 4;   // B TRANSB
    const int bkr = tid >> 4, bkc = (tid & 15) * 4;  // B non-TRANSB

    float acc[4][4] = {};

    // prologue: stages 0,1
    #pragma unroll
    for (int p = 0; p < 2; p++) {
        const int k0 = p << 4;
        cp_async16(&As[p][ar*20 + ac4], A + (size_t)(m0 + ar)*K + k0 + ac4);
        if (TRANSB) cp_async16(&Bs[p][bnr*20 + bnc], B + (size_t)(n0 + bnr)*K + k0 + bnc);
        else        cp_async16(&Bs[p][bkr*72 + bkc], B + (size_t)(k0 + bkr)*N + n0 + bkc);
        CP_COMMIT();
    }

    for (int kt = 0; kt < KT; kt++) {
        const int st = kt % 3;
        if (kt + 1 < KT) { CP_WAIT(1); } else { CP_WAIT(0); }
        __syncthreads();                 // tile kt visible; stage (kt+2)%3 free
        if (kt + 2 < KT) {
            const int sp = (kt + 2) % 3;
            const int k0 = (kt + 2) << 4;
            cp_async16(&As[sp][ar*20 + ac4], A + (size_t)(m0 + ar)*K + k0 + ac4);
            if (TRANSB) cp_async16(&Bs[sp][bnr*20 + bnc], B + (size_t)(n0 + bnr)*K + k0 + bnc);
            else        cp_async16(&Bs[sp][bkr*72 + bkc], B + (size_t)(k0 + bkr)*N + n0 + bkc);
            CP_COMMIT();
        }

        const uint32_t* as = (const uint32_t*)As[st];
        const uint32_t* bs = (const uint32_t*)Bs[st];
        #pragma unroll
        for (int ks = 0; ks < 2; ks++) {
            const int kb = ks * 8;
            const int row = wm*16 + g;
            uint32_t a[4];
            a[0] = as[(row  )*20 + kb + t];
            a[1] = as[(row+8)*20 + kb + t];
            a[2] = as[(row  )*20 + kb + t + 4];
            a[3] = as[(row+8)*20 + kb + t + 4];
            #pragma unroll
            for (int nt = 0; nt < 4; nt++) {
                int n = wn*32 + nt*8 + g;
                uint32_t b0, b1;
                if (TRANSB) { b0 = bs[n*20 + kb + t];  b1 = bs[n*20 + kb + t + 4]; }
                else        { b0 = bs[(kb+t)*72 + n];  b1 = bs[(kb+t+4)*72 + n];   }
                mma_tf32(acc[nt], a, b0, b1);
            }
        }
    }

    const int r0 = m0 + wm*16 + g;
    #pragma unroll
    for (int nt = 0; nt < 4; nt++) {
        const int n = n0 + wn*32 + nt*8 + 2*t;
        float bb0 = bias ? bias[n] : 0.f;
        float bb1 = bias ? bias[n+1] : 0.f;
        float v00 = acc[nt][0] + bb0, v01 = acc[nt][1] + bb1;
        float v10 = acc[nt][2] + bb0, v11 = acc[nt][3] + bb1;
        if (ADDSRC) {
            v00 += SRC[(size_t)r0*N + n];     v01 += SRC[(size_t)r0*N + n + 1];
            v10 += SRC[(size_t)(r0+8)*N + n]; v11 += SRC[(size_t)(r0+8)*N + n + 1];
        }
        if (RELU) {
            v00 = fmaxf(v00, 0.f); v01 = fmaxf(v01, 0.f);
            v10 = fmaxf(v10, 0.f); v11 = fmaxf(v11, 0.f);
        }
        if (QKV) {
            store_qkv(r0,     n, v00, v01);
            store_qkv(r0 + 8, n, v10, v11);
        } else {
            *(float2*)(C + (size_t)r0*N + n)     = make_float2(v00, v01);
            *(float2*)(C + (size_t)(r0+8)*N + n) = make_float2(v10, v11);
        }
    }
}

// ---------------- graph preprocessing (CSR build) --------------------------------
__global__ void deg_count(const int* __restrict__ dst) {
    int e = blockIdx.x * 512 + threadIdx.x;
    atomicAdd(&g_deg[dst[e]], 1.0f);
    atomicAdd(&g_deg[dst[e + 256]], 1.0f);
}

// one block, 1024 threads: rowptr scan + cursor + dinv
__global__ void __launch_bounds__(1024) scan_rowptr() {
    __shared__ int warpsum[32];
    const int tid = threadIdx.x;
    const int lane = tid & 31, wid = tid >> 5;
    const int base = tid * 4;
    int c[4], s = 0;
    #pragma unroll
    for (int j = 0; j < 4; j++) {
        c[j] = (int)g_deg[base + j];
        g_dinv[base + j] = rsqrtf((float)c[j] + 1.0f);
        s += c[j];
    }
    int pre = s;
    #pragma unroll
    for (int off = 1; off < 32; off <<= 1) {
        int v = __shfl_up_sync(0xffffffffu, pre, off);
        if (lane >= off) pre += v;
    }
    if (lane == 31) warpsum[wid] = pre;
    __syncthreads();
    if (wid == 0) {
        int v = warpsum[lane];
        #pragma unroll
        for (int off = 1; off < 32; off <<= 1) {
            int u = __shfl_up_sync(0xffffffffu, v, off);
            if (lane >= off) v += u;
        }
        warpsum[lane] = v;
    }
    __syncthreads();
    int excl = pre - s + (wid > 0 ? warpsum[wid-1] : 0);
    int run = excl;
    #pragma unroll
    for (int j = 0; j < 4; j++) {
        g_rowptr[base + j] = run;
        g_cursor[base + j] = run;
        run += c[j];
    }
    if (tid == 1023) g_rowptr[NN] = run;
}

__global__ void csr_scatter(const int* __restrict__ src, const int* __restrict__ dst) {
    int e = blockIdx.x * 512 + threadIdx.x;
    #pragma unroll
    for (int j = 0; j < 2; j++, e += 256) {
        int s = src[e], d = dst[e];
        int p = atomicAdd(&g_cursor[d], 1);
        g_esrc[p]  = s;
        g_enorm[p] = g_dinv[s] * g_dinv[d];
    }
}

// ---------------- GCN gather (one warp per node, unroll x2) ----------------------
template<bool RELU>
__global__ void __launch_bounds__(256) gcn_gather(const float* __restrict__ bias,
                                                  float* __restrict__ out) {
    const int node = blockIdx.x * 8 + (threadIdx.x >> 5);
    const int lane = threadIdx.x & 31;
    const int beg = g_rowptr[node], end = g_rowptr[node+1];

    float a0=0.f,a1=0.f,a2=0.f,a3=0.f,a4=0.f,a5=0.f,a6=0.f,a7=0.f;
    int i = beg;
    for (; i + 2 <= end; i += 2) {
        int s0i = g_esrc[i],   s1i = g_esrc[i+1];
        float w0 = g_enorm[i], w1 = g_enorm[i+1];
        const float4* p0 = (const float4*)(g_tmp + (size_t)s0i*HH + lane*8);
        const float4* p1 = (const float4*)(g_tmp + (size_t)s1i*HH + lane*8);
        float4 x0 = p0[0], x1 = p0[1], y0 = p1[0], y1 = p1[1];
        a0 = fmaf(w0, x0.x, a0); a1 = fmaf(w0, x0.y, a1);
        a2 = fmaf(w0, x0.z, a2); a3 = fmaf(w0, x0.w, a3);
        a4 = fmaf(w0, x1.x, a4); a5 = fmaf(w0, x1.y, a5);
        a6 = fmaf(w0, x1.z, a6); a7 = fmaf(w0, x1.w, a7);
        a0 = fmaf(w1, y0.x, a0); a1 = fmaf(w1, y0.y, a1);
        a2 = fmaf(w1, y0.z, a2); a3 = fmaf(w1, y0.w, a3);
        a4 = fmaf(w1, y1.x, a4); a5 = fmaf(w1, y1.y, a5);
        a6 = fmaf(w1, y1.z, a6); a7 = fmaf(w1, y1.w, a7);
    }
    if (i < end) {
        int s0i = g_esrc[i];
        float w0 = g_enorm[i];
        const float4* p0 = (const float4*)(g_tmp + (size_t)s0i*HH + lane*8);
        float4 x0 = p0[0], x1 = p0[1];
        a0 = fmaf(w0, x0.x, a0); a1 = fmaf(w0, x0.y, a1);
        a2 = fmaf(w0, x0.z, a2); a3 = fmaf(w0, x0.w, a3);
        a4 = fmaf(w0, x1.x, a4); a5 = fmaf(w0, x1.y, a5);
        a6 = fmaf(w0, x1.z, a6); a7 = fmaf(w0, x1.w, a7);
    }
    float di = g_dinv[node];
    float sw = di * di;
    const float4* q = (const float4*)(g_tmp + (size_t)node*HH + lane*8);
    float4 s0 = q[0], s1 = q[1];
    const float4* bp = (const float4*)(bias + lane*8);
    float4 b0 = bp[0], b1 = bp[1];
    float o0 = fmaf(sw, s0.x, a0) + b0.x, o1 = fmaf(sw, s0.y, a1) + b0.y;
    float o2 = fmaf(sw, s0.z, a2) + b0.z, o3 = fmaf(sw, s0.w, a3) + b0.w;
    float o4 = fmaf(sw, s1.x, a4) + b1.x, o5 = fmaf(sw, s1.y, a5) + b1.y;
    float o6 = fmaf(sw, s1.z, a6) + b1.z, o7 = fmaf(sw, s1.w, a7) + b1.w;
    if (RELU) {
        o0 = fmaxf(o0,0.f); o1 = fmaxf(o1,0.f); o2 = fmaxf(o2,0.f); o3 = fmaxf(o3,0.f);
        o4 = fmaxf(o4,0.f); o5 = fmaxf(o5,0.f); o6 = fmaxf(o6,0.f); o7 = fmaxf(o7,0.f);
    }
    float4* op = (float4*)(out + (size_t)node*HH + lane*8);
    op[0] = make_float4(o0,o1,o2,o3);
    op[1] = make_float4(o4,o5,o6,o7);
}

// ---------------- V transpose to bf16 [h][d][n] ----------------------------------
__global__ void __launch_bounds__(256) v_to_bf16() {
    __shared__ __nv_bfloat16 vt[32][72];
    const int h  = blockIdx.y;
    const int n0 = blockIdx.x * 64;
    const int tid = threadIdx.x;
    const int n  = tid >> 2, c8 = (tid & 3) * 8;

    const float* base = g_vtmp + (size_t)(n0 + n)*256 + h*32 + c8;
    float4 v0 = *(const float4*)(base);
    float4 v1 = *(const float4*)(base + 4);
    vt[c8+0][n] = __float2bfloat16(v0.x); vt[c8+1][n] = __float2bfloat16(v0.y);
    vt[c8+2][n] = __float2bfloat16(v0.z); vt[c8+3][n] = __float2bfloat16(v0.w);
    vt[c8+4][n] = __float2bfloat16(v1.x); vt[c8+5][n] = __float2bfloat16(v1.y);
    vt[c8+6][n] = __float2bfloat16(v1.z); vt[c8+7][n] = __float2bfloat16(v1.w);
    __syncthreads();

    const int d = tid >> 3, k8 = (tid & 7) * 8;
    *(uint4*)(g_Vb + ((size_t)h*32 + d)*NN + n0 + k8) = *(uint4*)(&vt[d][k8]);
}

// ---------------- bf16 flash attention (3-stage cp.async, 1 barrier/iter) ---------
__global__ void __launch_bounds__(256) flash_attn_bf16() {
    __shared__ __align__(16) char Ks[3][64*80];
    __shared__ __align__(16) char Vs[3][32*144];

    const int head = blockIdx.y;
    const int q0   = blockIdx.x * 128;
    const int tid  = threadIdx.x;
    const int w    = tid >> 5, lane = tid & 31;
    const int g    = lane >> 2, t = lane & 3;
    const int KT   = NN / 64;

    const __nv_bfloat16* kg = g_Kb + (size_t)head*NN*32;
    const __nv_bfloat16* vg = g_Vb + (size_t)head*32*NN;

    const int kr8 = tid >> 2, kc8 = (tid & 3) * 8;
    const int vd  = tid >> 3, vk8 = (tid & 7) * 8;

    cp_async16(&Ks[0][kr8*80 + kc8*2], kg + (size_t)kr8*32 + kc8);
    cp_async16(&Vs[0][vd*144 + vk8*2], vg + (size_t)vd*NN + vk8);
    CP_COMMIT();
    cp_async16(&Ks[1][kr8*80 + kc8*2], kg + (size_t)(64 + kr8)*32 + kc8);
    cp_async16(&Vs[1][vd*144 + vk8*2], vg + (size_t)vd*NN + 64 + vk8);
    CP_COMMIT();

    uint32_t aq[2][4];
    {
        const __nv_bfloat16* qb = g_Qb + ((size_t)head*NN + q0 + w*16) * 32;
        #pragma unroll
        for (int ks = 0; ks < 2; ks++) {
            int c = ks*16 + 2*t;
            aq[ks][0] = *(const uint32_t*)(qb + (size_t)(g  )*32 + c);
            aq[ks][1] = *(const uint32_t*)(qb + (size_t)(g+8)*32 + c);
            aq[ks][2] = *(const uint32_t*)(qb + (size_t)(g  )*32 + c + 8);
            aq[ks][3] = *(const uint32_t*)(qb + (size_t)(g+8)*32 + c + 8);
        }
    }

    float m0 = -1e30f, m1 = -1e30f, l0 = 0.f, l1 = 0.f;
    float o[4][4] = {};

    for (int kt = 0; kt < KT; kt++) {
        const int st = kt % 3;
        if (kt + 1 < KT) { CP_WAIT(1); } else { CP_WAIT(0); }
        __syncthreads();
        if (kt + 2 < KT) {
            const int sp = (kt + 2) % 3;
            cp_async16(&Ks[sp][kr8*80 + kc8*2], kg + (size_t)((kt+2)*64 + kr8)*32 + kc8);
            cp_async16(&Vs[sp][vd*144 + vk8*2], vg + (size_t)vd*NN + (kt+2)*64 + vk8);
            CP_COMMIT();
        }

        float s[8][4];
        #pragma unroll
        for (int nb = 0; nb < 8; nb++) {
            s[nb][0] = s[nb][1] = s[nb][2] = s[nb][3] = 0.f;
            const char* kr = Ks[st] + (nb*8 + g)*80;
            uint32_t b0 = *(const uint32_t*)(kr + (2*t)*2);
            uint32_t b1 = *(const uint32_t*)(kr + (2*t+8)*2);
            mma_bf16(s[nb], aq[0], b0, b1);
            b0 = *(const uint32_t*)(kr + (16 + 2*t)*2);
            b1 = *(const uint32_t*)(kr + (16 + 2*t+8)*2);
            mma_bf16(s[nb], aq[1], b0, b1);
        }

        float tm0 = -1e30f, tm1 = -1e30f;
        #pragma unroll
        for (int nb = 0; nb < 8; nb++) {
            tm0 = fmaxf(tm0, fmaxf(s[nb][0], s[nb][1]));
            tm1 = fmaxf(tm1, fmaxf(s[nb][2], s[nb][3]));
        }
        tm0 = fmaxf(tm0, __shfl_xor_sync(0xffffffffu, tm0, 1));
        tm0 = fmaxf(tm0, __shfl_xor_sync(0xffffffffu, tm0, 2));
        tm1 = fmaxf(tm1, __shfl_xor_sync(0xffffffffu, tm1, 1));
        tm1 = fmaxf(tm1, __shfl_xor_sync(0xffffffffu, tm1, 2));
        float nm0 = fmaxf(m0, tm0), nm1 = fmaxf(m1, tm1);
        float al0 = exp2f(m0 - nm0), al1 = exp2f(m1 - nm1);
        m0 = nm0; m1 = nm1;
        float ps0 = 0.f, ps1 = 0.f;
        #pragma unroll
        for (int nb = 0; nb < 8; nb++) {
            s[nb][0] = exp2f(s[nb][0] - nm0);
            s[nb][1] = exp2f(s[nb][1] - nm0);
            s[nb][2] = exp2f(s[nb][2] - nm1);
            s[nb][3] = exp2f(s[nb][3] - nm1);
            ps0 += s[nb][0] + s[nb][1];
            ps1 += s[nb][2] + s[nb][3];
        }
        ps0 += __shfl_xor_sync(0xffffffffu, ps0, 1);
        ps0 += __shfl_xor_sync(0xffffffffu, ps0, 2);
        ps1 += __shfl_xor_sync(0xffffffffu, ps1, 1);
        ps1 += __shfl_xor_sync(0xffffffffu, ps1, 2);
        l0 = l0 * al0 + ps0;
        l1 = l1 * al1 + ps1;

        #pragma unroll
        for (int nbv = 0; nbv < 4; nbv++) {
            o[nbv][0] *= al0; o[nbv][1] *= al0;
            o[nbv][2] *= al1; o[nbv][3] *= al1;
        }
        uint32_t ap[4][4];
        #pragma unroll
        for (int s4 = 0; s4 < 4; s4++) {
            ap[s4][0] = pack_bf16(s[2*s4  ][0], s[2*s4  ][1]);
            ap[s4][1] = pack_bf16(s[2*s4  ][2], s[2*s4  ][3]);
            ap[s4][2] = pack_bf16(s[2*s4+1][0], s[2*s4+1][1]);
            ap[s4][3] = pack_bf16(s[2*s4+1][2], s[2*s4+1][3]);
        }

        #pragma unroll
        for (int nbv = 0; nbv < 4; nbv++) {
            const char* vr = Vs[st] + (nbv*8 + g)*144;
            #pragma unroll
            for (int s4 = 0; s4 < 4; s4++) {
                uint32_t b0 = *(const uint32_t*)(vr + (16*s4 + 2*t)*2);
                uint32_t b1 = *(const uint32_t*)(vr + (16*s4 + 2*t + 8)*2);
                mma_bf16(o[nbv], ap[s4], b0, b1);
            }
        }
    }

    float inv0 = 1.0f / l0, inv1 = 1.0f / l1;
    int row0 = q0 + w*16 + g;
    #pragma unroll
    for (int nbv = 0; nbv < 4; nbv++) {
        int col = head*32 + nbv*8 + 2*t;
        *(float2*)(g_attn + (size_t)row0*HH + col)       = make_float2(o[nbv][0]*inv0, o[nbv][1]*inv0);
        *(float2*)(g_attn + (size_t)(row0+8)*HH + col)   = make_float2(o[nbv][2]*inv1, o[nbv][3]*inv1);
    }
}

// ---------------- output heads (warp per node) ------------------------------------
template<int C, bool SOFTMAX>
__global__ void __launch_bounds__(256) head_warp(const float* __restrict__ hid,
                                                 const float* __restrict__ W,
                                                 const float* __restrict__ b,
                                                 float* __restrict__ out) {
    const int node = blockIdx.x * 8 + (threadIdx.x >> 5);
    const int lane = threadIdx.x & 31;
    float4 hv = *(const float4*)(hid + (size_t)node*128 + lane*4);
    float lg[C];
    #pragma unroll
    for (int c = 0; c < C; c++) {
        float4 wv = *(const float4*)(W + c*128 + lane*4);
        float d = hv.x*wv.x + hv.y*wv.y + hv.z*wv.z + hv.w*wv.w;
        #pragma unroll
        for (int m = 16; m >= 1; m >>= 1) d += __shfl_xor_sync(0xffffffffu, d, m);
        lg[c] = d + b[c];
    }
    if (lane == 0) {
        if (SOFTMAX) {
            float mx = lg[0];
            #pragma unroll
            for (int c = 1; c < C; c++) mx = fmaxf(mx, lg[c]);
            float e[C]; float sum = 0.f;
            #pragma unroll
            for (int c = 0; c < C; c++) { e[c] = __expf(lg[c] - mx); sum += e[c]; }
            float inv = 1.0f / sum;
            #pragma unroll
            for (int c = 0; c < C; c++) out[(size_t)node*C + c] = e[c] * inv;
        } else {
            #pragma unroll
            for (int c = 0; c < C; c++)
                out[(size_t)node*C + c] = 1.0f / (1.0f + __expf(-lg[c]));
        }
    }
}

// ---------------- launch ---------------------------------------------------------
extern "C" void kernel_launch(void* const* d_in, const int* in_sizes, int n_in,
                              void* d_out, int out_size)
{
    const float* x     = (const float*)d_in[0];
    const int*   ei    = (const int*)  d_in[1];
    const float* W1    = (const float*)d_in[2];
    const float* b1    = (const float*)d_in[3];
    const float* W2    = (const float*)d_in[4];
    const float* b2    = (const float*)d_in[5];
    const float* W3    = (const float*)d_in[6];
    const float* b3    = (const float*)d_in[7];
    const float* in_w  = (const float*)d_in[8];
    const float* in_b  = (const float*)d_in[9];
    const float* out_w = (const float*)d_in[10];
    const float* out_b = (const float*)d_in[11];
    const float* fp1w  = (const float*)d_in[12];
    const float* fp1b  = (const float*)d_in[13];
    const float* fp2w  = (const float*)d_in[14];
    const float* fp2b  = (const float*)d_in[15];
    const float* pd1w  = (const float*)d_in[16];
    const float* pd1b  = (const float*)d_in[17];
    const float* pd2w  = (const float*)d_in[18];
    const float* pd2b  = (const float*)d_in[19];
    const int* src = ei;
    const int* dst = ei + EE;
    float* outp = (float*)d_out;

    float *tmp, *h, *h3, *deg, *attn, *hid, *hid2;
    cudaGetSymbolAddress((void**)&tmp,  g_tmp);
    cudaGetSymbolAddress((void**)&h,    g_h);
    cudaGetSymbolAddress((void**)&h3,   g_h3);
    cudaGetSymbolAddress((void**)&deg,  g_deg);
    cudaGetSymbolAddress((void**)&attn, g_attn);
    cudaGetSymbolAddress((void**)&hid,  g_hid);
    cudaGetSymbolAddress((void**)&hid2, g_hid2);

    static cudaStream_t s2 = nullptr;
    static cudaEvent_t evF = nullptr, evJ = nullptr, evF2 = nullptr, evJ2 = nullptr;
    if (!s2) {
        cudaStreamCreateWithFlags(&s2, cudaStreamNonBlocking);
        cudaEventCreateWithFlags(&evF,  cudaEventDisableTiming);
        cudaEventCreateWithFlags(&evJ,  cudaEventDisableTiming);
        cudaEventCreateWithFlags(&evF2, cudaEventDisableTiming);
        cudaEventCreateWithFlags(&evJ2, cudaEventDisableTiming);
    }

    const dim3 blk(256);

    // Fork: CSR build on s2  ||  GEMM1 on main stream
    cudaEventRecord(evF, 0);
    cudaStreamWaitEvent(s2, evF, 0);
    cudaMemsetAsync(deg, 0, NN * sizeof(float), s2);
    deg_count<<<EE/512, 256, 0, s2>>>(dst);
    scan_rowptr<<<1, 1024, 0, s2>>>();
    csr_scatter<<<EE/512, 256, 0, s2>>>(src, dst);
    cudaEventRecord(evJ, s2);

    gemm_tf32<false,false,false,false><<<dim3(4,64), blk>>>(x, W1, nullptr, nullptr, tmp, NN, HH, 128);
    cudaStreamWaitEvent(0, evJ, 0);     // join before first gather

    gcn_gather<true><<<NN/8, blk>>>(b1, h);
    gemm_tf32<false,false,false,false><<<dim3(4,64), blk>>>(h, W2, nullptr, nullptr, tmp, NN, HH, HH);
    gcn_gather<true><<<NN/8, blk>>>(b2, h);
    gemm_tf32<false,false,false,false><<<dim3(4,64), blk>>>(h, W3, nullptr, nullptr, tmp, NN, HH, HH);
    gcn_gather<false><<<NN/8, blk>>>(b3, h3);

    // MHA: fused QKV gemm -> (g_Qb, g_Kb, g_vtmp); V transpose; flash attention
    gemm_tf32<true,false,false,true><<<dim3(12,64), blk>>>(h3, in_w, in_b, nullptr, nullptr, NN, 3*HH, HH);
    v_to_bf16<<<dim3(NN/64, 8), blk>>>();
    flash_attn_bf16<<<dim3(NN/128, 8), blk>>>();
    gemm_tf32<true,false,true,false><<<dim3(4,64), blk>>>(attn, out_w, out_b, h3, h, NN, HH, HH);

    // Fork the two head chains
    cudaEventRecord(evF2, 0);
    cudaStreamWaitEvent(s2, evF2, 0);
    gemm_tf32<true,true,false,false><<<dim3(2,64), blk, 0, s2>>>(h, pd1w, pd1b, nullptr, hid2, NN, 128, HH);
    head_warp<10, false><<<NN/8, blk, 0, s2>>>(hid2, pd2w, pd2b, outp + (size_t)NN*3);
    cudaEventRecord(evJ2, s2);

    gemm_tf32<true,true,false,false><<<dim3(2,64), blk>>>(h, fp1w, fp1b, nullptr, hid, NN, 128, HH);
    head_warp<3, true><<<NN/8, blk>>>(hid, fp2w, fp2b, outp);
    cudaStreamWaitEvent(0, evJ2, 0);    // join before returning
}

// round 8
// speedup vs baseline: 1.0432x; 1.0432x over previous
#include <cuda_runtime.h>
#include <cuda_bf16.h>
#include <cstdint>
#include <math.h>

#define NN 4096
#define EE 131072
#define HH 256

#define QSCALE_F (0.17677669529663687f * 1.4426950408889634f)

// ---------------- scratch (static device globals; no allocation) ----------------
__device__ float g_tmp [NN*HH];
__device__ float g_h   [NN*HH];
__device__ float g_h3  [NN*HH];
__device__ float g_deg [NN];
__device__ float g_dinv[NN];
__device__ float g_vtmp[NN*HH];      // V columns of qkv (fp32 staging)
__device__ float g_attn[NN*HH];
__device__ float g_hid [NN*128];
__device__ float g_hid2[NN*128];
__device__ int   g_rowptr[NN+1];
__device__ int   g_cursor[NN];
__device__ int   g_esrc [EE];
__device__ float g_enorm[EE];
__device__ __nv_bfloat16 g_Qb[8*NN*32];   // [h][n][d], pre-scaled by 1/sqrt(32)*log2e
__device__ __nv_bfloat16 g_Kb[8*NN*32];   // [h][n][d]
__device__ __nv_bfloat16 g_Vb[8*32*NN];   // [h][d][n]  (transposed)

// ---------------- async-copy helpers ---------------------------------------------
__device__ __forceinline__ void cp_async16(void* smem, const void* gmem) {
    uint32_t s = (uint32_t)__cvta_generic_to_shared(smem);
    asm volatile("cp.async.ca.shared.global [%0], [%1], 16;\n" :: "r"(s), "l"(gmem));
}
#define CP_COMMIT() asm volatile("cp.async.commit_group;\n" ::: "memory")
#define CP_WAIT(n)  asm volatile("cp.async.wait_group %0;\n" :: "n"(n) : "memory")

// ---------------- mma wrappers ----------------------------------------------------
__device__ __forceinline__ void mma_tf32(float* c, const uint32_t* a, uint32_t b0, uint32_t b1) {
    asm volatile(
        "mma.sync.aligned.m16n8k8.row.col.f32.tf32.tf32.f32 "
        "{%0,%1,%2,%3}, {%4,%5,%6,%7}, {%8,%9}, {%0,%1,%2,%3};\n"
        : "+f"(c[0]), "+f"(c[1]), "+f"(c[2]), "+f"(c[3])
        : "r"(a[0]), "r"(a[1]), "r"(a[2]), "r"(a[3]), "r"(b0), "r"(b1));
}
__device__ __forceinline__ void mma_bf16(float* c, const uint32_t* a, uint32_t b0, uint32_t b1) {
    asm volatile(
        "mma.sync.aligned.m16n8k16.row.col.f32.bf16.bf16.f32 "
        "{%0,%1,%2,%3}, {%4,%5,%6,%7}, {%8,%9}, {%0,%1,%2,%3};\n"
        : "+f"(c[0]), "+f"(c[1]), "+f"(c[2]), "+f"(c[3])
        : "r"(a[0]), "r"(a[1]), "r"(a[2]), "r"(a[3]), "r"(b0), "r"(b1));
}
__device__ __forceinline__ uint32_t pack_bf16(float lo, float hi) {
    __nv_bfloat162 v = __floats2bfloat162_rn(lo, hi);
    return *(uint32_t*)&v;
}

// QKV epilogue store: n in [0,768). Block-uniform type (64-col tiles).
__device__ __forceinline__ void store_qkv(int row, int n, float a, float b) {
    int d = n & 31;
    int hh = (n >> 5) & 7;
    if (n < 256) {
        *(uint32_t*)(g_Qb + ((size_t)hh*NN + row)*32 + d) = pack_bf16(a*QSCALE_F, b*QSCALE_F);
    } else if (n < 512) {
        *(uint32_t*)(g_Kb + ((size_t)hh*NN + row)*32 + d) = pack_bf16(a, b);
    } else {
        *(float2*)(g_vtmp + (size_t)row*256 + (n - 512)) = make_float2(a, b);
    }
}

// ---------------- pipelined tf32 GEMM (round-6 proven: 128x64, 2-stage) -----------
// C[M,N] = A[M,K] @ B (+bias)(+SRC)(relu).  TRANSB: B is [N,K] (torch weight).
// QKV: epilogue routes to g_Qb/g_Kb/g_vtmp.  DUALB: blockIdx.x>=2 switches to B2/bias2/C2.
template<bool TRANSB, bool RELU, bool ADDSRC, bool QKV, bool DUALB>
__global__ void __launch_bounds__(256) gemm_tf32(
    const float* __restrict__ A, const float* __restrict__ B,
    const float* __restrict__ B2, const float* __restrict__ bias,
    const float* __restrict__ bias2, const float* __restrict__ SRC,
    float* __restrict__ C, float* __restrict__ C2, int M, int N, int K)
{
    __shared__ float As[2][128*20];
    __shared__ float Bs[2][1280];

    const int tid  = threadIdx.x;
    const int w    = tid >> 5, lane = tid & 31;
    const int g    = lane >> 2, t = lane & 3;
    const int wm   = w & 3, wn = w >> 2;
    const int m0   = blockIdx.y * 128;
    int n0;
    if (DUALB) {
        n0 = (blockIdx.x & 1) * 64;
        if (blockIdx.x >= 2) { B = B2; bias = bias2; C = C2; }
    } else {
        n0 = blockIdx.x * 64;
    }
    const int KT   = K >> 4;

    const int ar  = tid >> 2, ac4 = (tid & 3) * 4;
    const int bnr = tid >> 2, bnc = (tid & 3) * 4;
    const int bkr = tid >> 4, bkc = (tid & 15) * 4;

    float acc[2][4][4] = {};

    {
        cp_async16(&As[0][ar*20 + ac4],        A + (size_t)(m0 + ar)*K + ac4);
        cp_async16(&As[0][(ar+64)*20 + ac4],   A + (size_t)(m0 + ar + 64)*K + ac4);
        if (TRANSB) cp_async16(&Bs[0][bnr*20 + bnc], B + (size_t)(n0 + bnr)*K + bnc);
        else        cp_async16(&Bs[0][bkr*72 + bkc], B + (size_t)bkr*N + n0 + bkc);
        CP_COMMIT();
    }

    for (int kt = 0; kt < KT; kt++) {
        const int st = kt & 1;
        if (kt + 1 < KT) {
            const int k0 = (kt + 1) << 4;
            cp_async16(&As[st^1][ar*20 + ac4],      A + (size_t)(m0 + ar)*K + k0 + ac4);
            cp_async16(&As[st^1][(ar+64)*20 + ac4], A + (size_t)(m0 + ar + 64)*K + k0 + ac4);
            if (TRANSB) cp_async16(&Bs[st^1][bnr*20 + bnc], B + (size_t)(n0 + bnr)*K + k0 + bnc);
            else        cp_async16(&Bs[st^1][bkr*72 + bkc], B + (size_t)(k0 + bkr)*N + n0 + bkc);
            CP_COMMIT();
            CP_WAIT(1);
        } else {
            CP_WAIT(0);
        }
        __syncthreads();

        const uint32_t* as = (const uint32_t*)As[st];
        const uint32_t* bs = (const uint32_t*)Bs[st];
        #pragma unroll
        for (int ks = 0; ks < 2; ks++) {
            const int kb = ks * 8;
            uint32_t a[2][4];
            #pragma unroll
            for (int mt = 0; mt < 2; mt++) {
                int row = wm*32 + mt*16 + g;
                a[mt][0] = as[(row  )*20 + kb + t];
                a[mt][1] = as[(row+8)*20 + kb + t];
                a[mt][2] = as[(row  )*20 + kb + t + 4];
                a[mt][3] = as[(row+8)*20 + kb + t + 4];
            }
            #pragma unroll
            for (int nt = 0; nt < 4; nt++) {
                int n = wn*32 + nt*8 + g;
                uint32_t b0, b1;
                if (TRANSB) { b0 = bs[n*20 + kb + t];  b1 = bs[n*20 + kb + t + 4]; }
                else        { b0 = bs[(kb+t)*72 + n];  b1 = bs[(kb+t+4)*72 + n];   }
                mma_tf32(acc[0][nt], a[0], b0, b1);
                mma_tf32(acc[1][nt], a[1], b0, b1);
            }
        }
        __syncthreads();
    }

    #pragma unroll
    for (int mt = 0; mt < 2; mt++) {
        const int r0 = m0 + wm*32 + mt*16 + g;
        #pragma unroll
        for (int nt = 0; nt < 4; nt++) {
            const int n = n0 + wn*32 + nt*8 + 2*t;
            float bb0 = bias ? bias[n] : 0.f;
            float bb1 = bias ? bias[n+1] : 0.f;
            float v00 = acc[mt][nt][0] + bb0, v01 = acc[mt][nt][1] + bb1;
            float v10 = acc[mt][nt][2] + bb0, v11 = acc[mt][nt][3] + bb1;
            if (ADDSRC) {
                v00 += SRC[(size_t)r0*N + n];     v01 += SRC[(size_t)r0*N + n + 1];
                v10 += SRC[(size_t)(r0+8)*N + n]; v11 += SRC[(size_t)(r0+8)*N + n + 1];
            }
            if (RELU) {
                v00 = fmaxf(v00, 0.f); v01 = fmaxf(v01, 0.f);
                v10 = fmaxf(v10, 0.f); v11 = fmaxf(v11, 0.f);
            }
            if (QKV) {
                store_qkv(r0,     n, v00, v01);
                store_qkv(r0 + 8, n, v10, v11);
            } else {
                *(float2*)(C + (size_t)r0*N + n)     = make_float2(v00, v01);
                *(float2*)(C + (size_t)(r0+8)*N + n) = make_float2(v10, v11);
            }
        }
    }
}

// ---------------- graph preprocessing (CSR build) --------------------------------
__global__ void deg_count(const int* __restrict__ dst) {
    int e = blockIdx.x * 256 + threadIdx.x;
    if (e < EE) atomicAdd(&g_deg[dst[e]], 1.0f);
}

// one block, 1024 threads: rowptr scan + cursor + dinv
__global__ void __launch_bounds__(1024) scan_rowptr() {
    __shared__ int warpsum[32];
    const int tid = threadIdx.x;
    const int lane = tid & 31, wid = tid >> 5;
    const int base = tid * 4;
    int c[4], s = 0;
    #pragma unroll
    for (int j = 0; j < 4; j++) {
        c[j] = (int)g_deg[base + j];
        g_dinv[base + j] = rsqrtf((float)c[j] + 1.0f);
        s += c[j];
    }
    int pre = s;
    #pragma unroll
    for (int off = 1; off < 32; off <<= 1) {
        int v = __shfl_up_sync(0xffffffffu, pre, off);
        if (lane >= off) pre += v;
    }
    if (lane == 31) warpsum[wid] = pre;
    __syncthreads();
    if (wid == 0) {
        int v = warpsum[lane];
        #pragma unroll
        for (int off = 1; off < 32; off <<= 1) {
            int u = __shfl_up_sync(0xffffffffu, v, off);
            if (lane >= off) v += u;
        }
        warpsum[lane] = v;
    }
    __syncthreads();
    int excl = pre - s + (wid > 0 ? warpsum[wid-1] : 0);
    int run = excl;
    #pragma unroll
    for (int j = 0; j < 4; j++) {
        g_rowptr[base + j] = run;
        g_cursor[base + j] = run;
        run += c[j];
    }
    if (tid == 1023) g_rowptr[NN] = run;
}

__global__ void csr_scatter(const int* __restrict__ src, const int* __restrict__ dst) {
    int e = blockIdx.x * 256 + threadIdx.x;
    if (e >= EE) return;
    int s = src[e], d = dst[e];
    int p = atomicAdd(&g_cursor[d], 1);
    g_esrc[p]  = s;
    g_enorm[p] = g_dinv[s] * g_dinv[d];
}

// ---------------- GCN gather (one warp per node, unroll x2) ----------------------
template<bool RELU>
__global__ void __launch_bounds__(256) gcn_gather(const float* __restrict__ bias,
                                                  float* __restrict__ out) {
    const int node = blockIdx.x * 8 + (threadIdx.x >> 5);
    const int lane = threadIdx.x & 31;
    const int beg = g_rowptr[node], end = g_rowptr[node+1];

    float a0=0.f,a1=0.f,a2=0.f,a3=0.f,a4=0.f,a5=0.f,a6=0.f,a7=0.f;
    int i = beg;
    for (; i + 2 <= end; i += 2) {
        int s0i = g_esrc[i],   s1i = g_esrc[i+1];
        float w0 = g_enorm[i], w1 = g_enorm[i+1];
        const float4* p0 = (const float4*)(g_tmp + (size_t)s0i*HH + lane*8);
        const float4* p1 = (const float4*)(g_tmp + (size_t)s1i*HH + lane*8);
        float4 x0 = p0[0], x1 = p0[1], y0 = p1[0], y1 = p1[1];
        a0 = fmaf(w0, x0.x, a0); a1 = fmaf(w0, x0.y, a1);
        a2 = fmaf(w0, x0.z, a2); a3 = fmaf(w0, x0.w, a3);
        a4 = fmaf(w0, x1.x, a4); a5 = fmaf(w0, x1.y, a5);
        a6 = fmaf(w0, x1.z, a6); a7 = fmaf(w0, x1.w, a7);
        a0 = fmaf(w1, y0.x, a0); a1 = fmaf(w1, y0.y, a1);
        a2 = fmaf(w1, y0.z, a2); a3 = fmaf(w1, y0.w, a3);
        a4 = fmaf(w1, y1.x, a4); a5 = fmaf(w1, y1.y, a5);
        a6 = fmaf(w1, y1.z, a6); a7 = fmaf(w1, y1.w, a7);
    }
    if (i < end) {
        int s0i = g_esrc[i];
        float w0 = g_enorm[i];
        const float4* p0 = (const float4*)(g_tmp + (size_t)s0i*HH + lane*8);
        float4 x0 = p0[0], x1 = p0[1];
        a0 = fmaf(w0, x0.x, a0); a1 = fmaf(w0, x0.y, a1);
        a2 = fmaf(w0, x0.z, a2); a3 = fmaf(w0, x0.w, a3);
        a4 = fmaf(w0, x1.x, a4); a5 = fmaf(w0, x1.y, a5);
        a6 = fmaf(w0, x1.z, a6); a7 = fmaf(w0, x1.w, a7);
    }
    float di = g_dinv[node];
    float sw = di * di;
    const float4* q = (const float4*)(g_tmp + (size_t)node*HH + lane*8);
    float4 s0 = q[0], s1 = q[1];
    const float4* bp = (const float4*)(bias + lane*8);
    float4 b0 = bp[0], b1 = bp[1];
    float o0 = fmaf(sw, s0.x, a0) + b0.x, o1 = fmaf(sw, s0.y, a1) + b0.y;
    float o2 = fmaf(sw, s0.z, a2) + b0.z, o3 = fmaf(sw, s0.w, a3) + b0.w;
    float o4 = fmaf(sw, s1.x, a4) + b1.x, o5 = fmaf(sw, s1.y, a5) + b1.y;
    float o6 = fmaf(sw, s1.z, a6) + b1.z, o7 = fmaf(sw, s1.w, a7) + b1.w;
    if (RELU) {
        o0 = fmaxf(o0,0.f); o1 = fmaxf(o1,0.f); o2 = fmaxf(o2,0.f); o3 = fmaxf(o3,0.f);
        o4 = fmaxf(o4,0.f); o5 = fmaxf(o5,0.f); o6 = fmaxf(o6,0.f); o7 = fmaxf(o7,0.f);
    }
    float4* op = (float4*)(out + (size_t)node*HH + lane*8);
    op[0] = make_float4(o0,o1,o2,o3);
    op[1] = make_float4(o4,o5,o6,o7);
}

// ---------------- V transpose to bf16 [h][d][n] ----------------------------------
__global__ void __launch_bounds__(256) v_to_bf16() {
    __shared__ __nv_bfloat16 vt[32][72];
    const int h  = blockIdx.y;
    const int n0 = blockIdx.x * 64;
    const int tid = threadIdx.x;
    const int n  = tid >> 2, c8 = (tid & 3) * 8;

    const float* base = g_vtmp + (size_t)(n0 + n)*256 + h*32 + c8;
    float4 v0 = *(const float4*)(base);
    float4 v1 = *(const float4*)(base + 4);
    vt[c8+0][n] = __float2bfloat16(v0.x); vt[c8+1][n] = __float2bfloat16(v0.y);
    vt[c8+2][n] = __float2bfloat16(v0.z); vt[c8+3][n] = __float2bfloat16(v0.w);
    vt[c8+4][n] = __float2bfloat16(v1.x); vt[c8+5][n] = __float2bfloat16(v1.y);
    vt[c8+6][n] = __float2bfloat16(v1.z); vt[c8+7][n] = __float2bfloat16(v1.w);
    __syncthreads();

    const int d = tid >> 3, k8 = (tid & 7) * 8;
    *(uint4*)(g_Vb + ((size_t)h*32 + d)*NN + n0 + k8) = *(uint4*)(&vt[d][k8]);
}

// ---------------- bf16 flash attention (3-stage cp.async, 1 barrier/iter) ---------
__global__ void __launch_bounds__(256) flash_attn_bf16() {
    __shared__ __align__(16) char Ks[3][64*80];
    __shared__ __align__(16) char Vs[3][32*144];

    const int head = blockIdx.y;
    const int q0   = blockIdx.x * 128;
    const int tid  = threadIdx.x;
    const int w    = tid >> 5, lane = tid & 31;
    const int g    = lane >> 2, t = lane & 3;
    const int KT   = NN / 64;

    const __nv_bfloat16* kg = g_Kb + (size_t)head*NN*32;
    const __nv_bfloat16* vg = g_Vb + (size_t)head*32*NN;

    const int kr8 = tid >> 2, kc8 = (tid & 3) * 8;
    const int vd  = tid >> 3, vk8 = (tid & 7) * 8;

    cp_async16(&Ks[0][kr8*80 + kc8*2], kg + (size_t)kr8*32 + kc8);
    cp_async16(&Vs[0][vd*144 + vk8*2], vg + (size_t)vd*NN + vk8);
    CP_COMMIT();
    cp_async16(&Ks[1][kr8*80 + kc8*2], kg + (size_t)(64 + kr8)*32 + kc8);
    cp_async16(&Vs[1][vd*144 + vk8*2], vg + (size_t)vd*NN + 64 + vk8);
    CP_COMMIT();

    uint32_t aq[2][4];
    {
        const __nv_bfloat16* qb = g_Qb + ((size_t)head*NN + q0 + w*16) * 32;
        #pragma unroll
        for (int ks = 0; ks < 2; ks++) {
            int c = ks*16 + 2*t;
            aq[ks][0] = *(const uint32_t*)(qb + (size_t)(g  )*32 + c);
            aq[ks][1] = *(const uint32_t*)(qb + (size_t)(g+8)*32 + c);
            aq[ks][2] = *(const uint32_t*)(qb + (size_t)(g  )*32 + c + 8);
            aq[ks][3] = *(const uint32_t*)(qb + (size_t)(g+8)*32 + c + 8);
        }
    }

    float m0 = -1e30f, m1 = -1e30f, l0 = 0.f, l1 = 0.f;
    float o[4][4] = {};

    for (int kt = 0; kt < KT; kt++) {
        const int st = kt % 3;
        if (kt + 1 < KT) { CP_WAIT(1); } else { CP_WAIT(0); }
        __syncthreads();
        if (kt + 2 < KT) {
            const int sp = (kt + 2) % 3;
            cp_async16(&Ks[sp][kr8*80 + kc8*2], kg + (size_t)((kt+2)*64 + kr8)*32 + kc8);
            cp_async16(&Vs[sp][vd*144 + vk8*2], vg + (size_t)vd*NN + (kt+2)*64 + vk8);
            CP_COMMIT();
        }

        float s[8][4];
        #pragma unroll
        for (int nb = 0; nb < 8; nb++) {
            s[nb][0] = s[nb][1] = s[nb][2] = s[nb][3] = 0.f;
            const char* kr = Ks[st] + (nb*8 + g)*80;
            uint32_t b0 = *(const uint32_t*)(kr + (2*t)*2);
            uint32_t b1 = *(const uint32_t*)(kr + (2*t+8)*2);
            mma_bf16(s[nb], aq[0], b0, b1);
            b0 = *(const uint32_t*)(kr + (16 + 2*t)*2);
            b1 = *(const uint32_t*)(kr + (16 + 2*t+8)*2);
            mma_bf16(s[nb], aq[1], b0, b1);
        }

        float tm0 = -1e30f, tm1 = -1e30f;
        #pragma unroll
        for (int nb = 0; nb < 8; nb++) {
            tm0 = fmaxf(tm0, fmaxf(s[nb][0], s[nb][1]));
            tm1 = fmaxf(tm1, fmaxf(s[nb][2], s[nb][3]));
        }
        tm0 = fmaxf(tm0, __shfl_xor_sync(0xffffffffu, tm0, 1));
        tm0 = fmaxf(tm0, __shfl_xor_sync(0xffffffffu, tm0, 2));
        tm1 = fmaxf(tm1, __shfl_xor_sync(0xffffffffu, tm1, 1));
        tm1 = fmaxf(tm1, __shfl_xor_sync(0xffffffffu, tm1, 2));
        float nm0 = fmaxf(m0, tm0), nm1 = fmaxf(m1, tm1);
        float al0 = exp2f(m0 - nm0), al1 = exp2f(m1 - nm1);
        m0 = nm0; m1 = nm1;
        float ps0 = 0.f, ps1 = 0.f;
        #pragma unroll
        for (int nb = 0; nb < 8; nb++) {
            s[nb][0] = exp2f(s[nb][0] - nm0);
            s[nb][1] = exp2f(s[nb][1] - nm0);
            s[nb][2] = exp2f(s[nb][2] - nm1);
            s[nb][3] = exp2f(s[nb][3] - nm1);
            ps0 += s[nb][0] + s[nb][1];
            ps1 += s[nb][2] + s[nb][3];
        }
        ps0 += __shfl_xor_sync(0xffffffffu, ps0, 1);
        ps0 += __shfl_xor_sync(0xffffffffu, ps0, 2);
        ps1 += __shfl_xor_sync(0xffffffffu, ps1, 1);
        ps1 += __shfl_xor_sync(0xffffffffu, ps1, 2);
        l0 = l0 * al0 + ps0;
        l1 = l1 * al1 + ps1;

        #pragma unroll
        for (int nbv = 0; nbv < 4; nbv++) {
            o[nbv][0] *= al0; o[nbv][1] *= al0;
            o[nbv][2] *= al1; o[nbv][3] *= al1;
        }
        uint32_t ap[4][4];
        #pragma unroll
        for (int s4 = 0; s4 < 4; s4++) {
            ap[s4][0] = pack_bf16(s[2*s4  ][0], s[2*s4  ][1]);
            ap[s4][1] = pack_bf16(s[2*s4  ][2], s[2*s4  ][3]);
            ap[s4][2] = pack_bf16(s[2*s4+1][0], s[2*s4+1][1]);
            ap[s4][3] = pack_bf16(s[2*s4+1][2], s[2*s4+1][3]);
        }

        #pragma unroll
        for (int nbv = 0; nbv < 4; nbv++) {
            const char* vr = Vs[st] + (nbv*8 + g)*144;
            #pragma unroll
            for (int s4 = 0; s4 < 4; s4++) {
                uint32_t b0 = *(const uint32_t*)(vr + (16*s4 + 2*t)*2);
                uint32_t b1 = *(const uint32_t*)(vr + (16*s4 + 2*t + 8)*2);
                mma_bf16(o[nbv], ap[s4], b0, b1);
            }
        }
    }

    float inv0 = 1.0f / l0, inv1 = 1.0f / l1;
    int row0 = q0 + w*16 + g;
    #pragma unroll
    for (int nbv = 0; nbv < 4; nbv++) {
        int col = head*32 + nbv*8 + 2*t;
        *(float2*)(g_attn + (size_t)row0*HH + col)       = make_float2(o[nbv][0]*inv0, o[nbv][1]*inv0);
        *(float2*)(g_attn + (size_t)(row0+8)*HH + col)   = make_float2(o[nbv][2]*inv1, o[nbv][3]*inv1);
    }
}

// ---------------- fused output heads (warp per node: softmax3 + sigmoid10) --------
__global__ void __launch_bounds__(256) head_both(const float* __restrict__ W3,
                                                 const float* __restrict__ b3v,
                                                 const float* __restrict__ W10,
                                                 const float* __restrict__ b10,
                                                 float* __restrict__ out) {
    const int node = blockIdx.x * 8 + (threadIdx.x >> 5);
    const int lane = threadIdx.x & 31;

    float4 hv = *(const float4*)(g_hid + (size_t)node*128 + lane*4);
    float lg3[3];
    #pragma unroll
    for (int c = 0; c < 3; c++) {
        float4 wv = *(const float4*)(W3 + c*128 + lane*4);
        float d = hv.x*wv.x + hv.y*wv.y + hv.z*wv.z + hv.w*wv.w;
        #pragma unroll
        for (int m = 16; m >= 1; m >>= 1) d += __shfl_xor_sync(0xffffffffu, d, m);
        lg3[c] = d + b3v[c];
    }
    float4 hv2 = *(const float4*)(g_hid2 + (size_t)node*128 + lane*4);
    float lg10[10];
    #pragma unroll
    for (int c = 0; c < 10; c++) {
        float4 wv = *(const float4*)(W10 + c*128 + lane*4);
        float d = hv2.x*wv.x + hv2.y*wv.y + hv2.z*wv.z + hv2.w*wv.w;
        #pragma unroll
        for (int m = 16; m >= 1; m >>= 1) d += __shfl_xor_sync(0xffffffffu, d, m);
        lg10[c] = d + b10[c];
    }
    if (lane == 0) {
        float mx = fmaxf(fmaxf(lg3[0], lg3[1]), lg3[2]);
        float e0 = __expf(lg3[0]-mx), e1 = __expf(lg3[1]-mx), e2 = __expf(lg3[2]-mx);
        float inv = 1.0f / (e0 + e1 + e2);
        out[(size_t)node*3 + 0] = e0*inv;
        out[(size_t)node*3 + 1] = e1*inv;
        out[(size_t)node*3 + 2] = e2*inv;
        float* o2 = out + (size_t)NN*3 + (size_t)node*10;
        #pragma unroll
        for (int c = 0; c < 10; c++)
            o2[c] = 1.0f / (1.0f + __expf(-lg10[c]));
    }
}

// ---------------- launch ---------------------------------------------------------
extern "C" void kernel_launch(void* const* d_in, const int* in_sizes, int n_in,
                              void* d_out, int out_size)
{
    const float* x     = (const float*)d_in[0];
    const int*   ei    = (const int*)  d_in[1];
    const float* W1    = (const float*)d_in[2];
    const float* b1    = (const float*)d_in[3];
    const float* W2    = (const float*)d_in[4];
    const float* b2    = (const float*)d_in[5];
    const float* W3    = (const float*)d_in[6];
    const float* b3    = (const float*)d_in[7];
    const float* in_w  = (const float*)d_in[8];
    const float* in_b  = (const float*)d_in[9];
    const float* out_w = (const float*)d_in[10];
    const float* out_b = (const float*)d_in[11];
    const float* fp1w  = (const float*)d_in[12];
    const float* fp1b  = (const float*)d_in[13];
    const float* fp2w  = (const float*)d_in[14];
    const float* fp2b  = (const float*)d_in[15];
    const float* pd1w  = (const float*)d_in[16];
    const float* pd1b  = (const float*)d_in[17];
    const float* pd2w  = (const float*)d_in[18];
    const float* pd2b  = (const float*)d_in[19];
    const int* src = ei;
    const int* dst = ei + EE;
    float* outp = (float*)d_out;

    float *tmp, *h, *h3, *deg, *attn, *hid, *hid2;
    cudaGetSymbolAddress((void**)&tmp,  g_tmp);
    cudaGetSymbolAddress((void**)&h,    g_h);
    cudaGetSymbolAddress((void**)&h3,   g_h3);
    cudaGetSymbolAddress((void**)&deg,  g_deg);
    cudaGetSymbolAddress((void**)&attn, g_attn);
    cudaGetSymbolAddress((void**)&hid,  g_hid);
    cudaGetSymbolAddress((void**)&hid2, g_hid2);

    static cudaStream_t s2 = nullptr;
    static cudaEvent_t evF = nullptr, evJ = nullptr;
    if (!s2) {
        cudaStreamCreateWithFlags(&s2, cudaStreamNonBlocking);
        cudaEventCreateWithFlags(&evF, cudaEventDisableTiming);
        cudaEventCreateWithFlags(&evJ, cudaEventDisableTiming);
    }

    const dim3 blk(256);

    // Fork: CSR build on s2  ||  GEMM1 on main stream
    cudaEventRecord(evF, 0);
    cudaStreamWaitEvent(s2, evF, 0);
    cudaMemsetAsync(deg, 0, NN * sizeof(float), s2);
    deg_count<<<EE/256, 256, 0, s2>>>(dst);
    scan_rowptr<<<1, 1024, 0, s2>>>();
    csr_scatter<<<EE/256, 256, 0, s2>>>(src, dst);
    cudaEventRecord(evJ, s2);

    gemm_tf32<false,false,false,false,false><<<dim3(4,32), blk>>>(
        x, W1, nullptr, nullptr, nullptr, nullptr, tmp, nullptr, NN, HH, 128);
    cudaStreamWaitEvent(0, evJ, 0);     // join before first gather

    gcn_gather<true><<<NN/8, blk>>>(b1, h);
    gemm_tf32<false,false,false,false,false><<<dim3(4,32), blk>>>(
        h, W2, nullptr, nullptr, nullptr, nullptr, tmp, nullptr, NN, HH, HH);
    gcn_gather<true><<<NN/8, blk>>>(b2, h);
    gemm_tf32<false,false,false,false,false><<<dim3(4,32), blk>>>(
        h, W3, nullptr, nullptr, nullptr, nullptr, tmp, nullptr, NN, HH, HH);
    gcn_gather<false><<<NN/8, blk>>>(b3, h3);

    // MHA: fused QKV gemm -> (g_Qb, g_Kb, g_vtmp); V transpose; flash attention
    gemm_tf32<true,false,false,true,false><<<dim3(12,32), blk>>>(
        h3, in_w, nullptr, in_b, nullptr, nullptr, nullptr, nullptr, NN, 3*HH, HH);
    v_to_bf16<<<dim3(NN/64, 8), blk>>>();
    flash_attn_bf16<<<dim3(NN/128, 8), blk>>>();
    gemm_tf32<true,false,true,false,false><<<dim3(4,32), blk>>>(
        attn, out_w, nullptr, out_b, nullptr, h3, h, nullptr, NN, HH, HH);

    // Fused dual-head GEMM (blockIdx.x<2: fp1 -> hid; >=2: pd1 -> hid2) + fused heads
    gemm_tf32<true,true,false,false,true><<<dim3(4,32), blk>>>(
        h, fp1w, pd1w, fp1b, pd1b, nullptr, hid, hid2, NN, 128, HH);
    head_both<<<NN/8, blk>>>(fp2w, fp2b, pd2w, pd2b, outp);
}

// round 9
// speedup vs baseline: 1.1257x; 1.0790x over previous
#include <cuda_runtime.h>
#include <cuda_bf16.h>
#include <cuda_fp16.h>
#include <cstdint>
#include <math.h>

#define NN 4096
#define EE 131072
#define HH 256

#define QSCALE_F (0.17677669529663687f * 1.4426950408889634f)

// ---------------- scratch (static device globals; no allocation) ----------------
__device__ __half g_tmpH[NN*HH];     // h @ W, fp16 (pre-aggregation)
__device__ float g_h   [NN*HH];
__device__ float g_h3  [NN*HH];
__device__ float g_deg [NN];
__device__ float g_dinv[NN];
__device__ float g_attn[NN*HH];
__device__ float g_hid [NN*128];
__device__ float g_hid2[NN*128];
__device__ int   g_rowptr[NN+1];
__device__ int   g_cursor[NN];
__device__ int   g_esrc [EE];
__device__ float g_enorm[EE];
__device__ __nv_bfloat16 g_Qb[8*NN*32];   // [h][n][d], pre-scaled by 1/sqrt(32)*log2e
__device__ __nv_bfloat16 g_Kb[8*NN*32];   // [h][n][d]
__device__ __nv_bfloat16 g_Vb[8*32*NN];   // [h][d][n]  (transposed)

// ---------------- async-copy helpers ---------------------------------------------
__device__ __forceinline__ void cp_async16(void* smem, const void* gmem) {
    uint32_t s = (uint32_t)__cvta_generic_to_shared(smem);
    asm volatile("cp.async.ca.shared.global [%0], [%1], 16;\n" :: "r"(s), "l"(gmem));
}
#define CP_COMMIT() asm volatile("cp.async.commit_group;\n" ::: "memory")
#define CP_WAIT(n)  asm volatile("cp.async.wait_group %0;\n" :: "n"(n) : "memory")

// ---------------- mma wrappers ----------------------------------------------------
__device__ __forceinline__ void mma_tf32(float* c, const uint32_t* a, uint32_t b0, uint32_t b1) {
    asm volatile(
        "mma.sync.aligned.m16n8k8.row.col.f32.tf32.tf32.f32 "
        "{%0,%1,%2,%3}, {%4,%5,%6,%7}, {%8,%9}, {%0,%1,%2,%3};\n"
        : "+f"(c[0]), "+f"(c[1]), "+f"(c[2]), "+f"(c[3])
        : "r"(a[0]), "r"(a[1]), "r"(a[2]), "r"(a[3]), "r"(b0), "r"(b1));
}
__device__ __forceinline__ void mma_bf16(float* c, const uint32_t* a, uint32_t b0, uint32_t b1) {
    asm volatile(
        "mma.sync.aligned.m16n8k16.row.col.f32.bf16.bf16.f32 "
        "{%0,%1,%2,%3}, {%4,%5,%6,%7}, {%8,%9}, {%0,%1,%2,%3};\n"
        : "+f"(c[0]), "+f"(c[1]), "+f"(c[2]), "+f"(c[3])
        : "r"(a[0]), "r"(a[1]), "r"(a[2]), "r"(a[3]), "r"(b0), "r"(b1));
}
__device__ __forceinline__ uint32_t pack_bf16(float lo, float hi) {
    __nv_bfloat162 v = __floats2bfloat162_rn(lo, hi);
    return *(uint32_t*)&v;
}

// QKV epilogue store: n in [0,768). Block-uniform branch (64-col tiles).
// V written directly to transposed bf16 layout (no staging kernel).
__device__ __forceinline__ void store_qkv(int row, int n, float a, float b) {
    int d = n & 31;
    int hh = (n >> 5) & 7;
    if (n < 256) {
        *(uint32_t*)(g_Qb + ((size_t)hh*NN + row)*32 + d) = pack_bf16(a*QSCALE_F, b*QSCALE_F);
    } else if (n < 512) {
        *(uint32_t*)(g_Kb + ((size_t)hh*NN + row)*32 + d) = pack_bf16(a, b);
    } else {
        g_Vb[((size_t)hh*32 + d    )*NN + row] = __float2bfloat16(a);
        g_Vb[((size_t)hh*32 + d + 1)*NN + row] = __float2bfloat16(b);
    }
}

// ---------------- pipelined tf32 GEMM (128x64, 2-stage; proven) -------------------
// C[M,N] = A[M,K] @ B (+bias)(+SRC)(relu).  TRANSB: B is [N,K] (torch weight).
// QKV: epilogue routes to g_Qb/g_Kb/g_Vb.  DUALB: blockIdx.x>=2 uses B2/bias2/C2.
// OUTH: C is __half* (packed half2 stores).
template<bool TRANSB, bool RELU, bool ADDSRC, bool QKV, bool DUALB, bool OUTH>
__global__ void __launch_bounds__(256) gemm_tf32(
    const float* __restrict__ A, const float* __restrict__ B,
    const float* __restrict__ B2, const float* __restrict__ bias,
    const float* __restrict__ bias2, const float* __restrict__ SRC,
    void* __restrict__ Cv, void* __restrict__ C2v, int M, int N, int K)
{
    __shared__ float As[2][128*20];
    __shared__ float Bs[2][1280];

    const int tid  = threadIdx.x;
    const int w    = tid >> 5, lane = tid & 31;
    const int g    = lane >> 2, t = lane & 3;
    const int wm   = w & 3, wn = w >> 2;
    const int m0   = blockIdx.y * 128;
    void* Cuse = Cv;
    int n0;
    if (DUALB) {
        n0 = (blockIdx.x & 1) * 64;
        if (blockIdx.x >= 2) { B = B2; bias = bias2; Cuse = C2v; }
    } else {
        n0 = blockIdx.x * 64;
    }
    const int KT   = K >> 4;

    const int ar  = tid >> 2, ac4 = (tid & 3) * 4;
    const int bnr = tid >> 2, bnc = (tid & 3) * 4;
    const int bkr = tid >> 4, bkc = (tid & 15) * 4;

    float acc[2][4][4] = {};

    {
        cp_async16(&As[0][ar*20 + ac4],        A + (size_t)(m0 + ar)*K + ac4);
        cp_async16(&As[0][(ar+64)*20 + ac4],   A + (size_t)(m0 + ar + 64)*K + ac4);
        if (TRANSB) cp_async16(&Bs[0][bnr*20 + bnc], B + (size_t)(n0 + bnr)*K + bnc);
        else        cp_async16(&Bs[0][bkr*72 + bkc], B + (size_t)bkr*N + n0 + bkc);
        CP_COMMIT();
    }

    for (int kt = 0; kt < KT; kt++) {
        const int st = kt & 1;
        if (kt + 1 < KT) {
            const int k0 = (kt + 1) << 4;
            cp_async16(&As[st^1][ar*20 + ac4],      A + (size_t)(m0 + ar)*K + k0 + ac4);
            cp_async16(&As[st^1][(ar+64)*20 + ac4], A + (size_t)(m0 + ar + 64)*K + k0 + ac4);
            if (TRANSB) cp_async16(&Bs[st^1][bnr*20 + bnc], B + (size_t)(n0 + bnr)*K + k0 + bnc);
            else        cp_async16(&Bs[st^1][bkr*72 + bkc], B + (size_t)(k0 + bkr)*N + n0 + bkc);
            CP_COMMIT();
            CP_WAIT(1);
        } else {
            CP_WAIT(0);
        }
        __syncthreads();

        const uint32_t* as = (const uint32_t*)As[st];
        const uint32_t* bs = (const uint32_t*)Bs[st];
        #pragma unroll
        for (int ks = 0; ks < 2; ks++) {
            const int kb = ks * 8;
            uint32_t a[2][4];
            #pragma unroll
            for (int mt = 0; mt < 2; mt++) {
                int row = wm*32 + mt*16 + g;
                a[mt][0] = as[(row  )*20 + kb + t];
                a[mt][1] = as[(row+8)*20 + kb + t];
                a[mt][2] = as[(row  )*20 + kb + t + 4];
                a[mt][3] = as[(row+8)*20 + kb + t + 4];
            }
            #pragma unroll
            for (int nt = 0; nt < 4; nt++) {
                int n = wn*32 + nt*8 + g;
                uint32_t b0, b1;
                if (TRANSB) { b0 = bs[n*20 + kb + t];  b1 = bs[n*20 + kb + t + 4]; }
                else        { b0 = bs[(kb+t)*72 + n];  b1 = bs[(kb+t+4)*72 + n];   }
                mma_tf32(acc[0][nt], a[0], b0, b1);
                mma_tf32(acc[1][nt], a[1], b0, b1);
            }
        }
        __syncthreads();
    }

    #pragma unroll
    for (int mt = 0; mt < 2; mt++) {
        const int r0 = m0 + wm*32 + mt*16 + g;
        #pragma unroll
        for (int nt = 0; nt < 4; nt++) {
            const int n = n0 + wn*32 + nt*8 + 2*t;
            float bb0 = bias ? bias[n] : 0.f;
            float bb1 = bias ? bias[n+1] : 0.f;
            float v00 = acc[mt][nt][0] + bb0, v01 = acc[mt][nt][1] + bb1;
            float v10 = acc[mt][nt][2] + bb0, v11 = acc[mt][nt][3] + bb1;
            if (ADDSRC) {
                v00 += SRC[(size_t)r0*N + n];     v01 += SRC[(size_t)r0*N + n + 1];
                v10 += SRC[(size_t)(r0+8)*N + n]; v11 += SRC[(size_t)(r0+8)*N + n + 1];
            }
            if (RELU) {
                v00 = fmaxf(v00, 0.f); v01 = fmaxf(v01, 0.f);
                v10 = fmaxf(v10, 0.f); v11 = fmaxf(v11, 0.f);
            }
            if (QKV) {
                store_qkv(r0,     n, v00, v01);
                store_qkv(r0 + 8, n, v10, v11);
            } else if (OUTH) {
                __half* C = (__half*)Cuse;
                __half2 h0 = __floats2half2_rn(v00, v01);
                __half2 h1 = __floats2half2_rn(v10, v11);
                *(uint32_t*)(C + (size_t)r0*N + n)     = *(uint32_t*)&h0;
                *(uint32_t*)(C + (size_t)(r0+8)*N + n) = *(uint32_t*)&h1;
            } else {
                float* C = (float*)Cuse;
                *(float2*)(C + (size_t)r0*N + n)     = make_float2(v00, v01);
                *(float2*)(C + (size_t)(r0+8)*N + n) = make_float2(v10, v11);
            }
        }
    }
}

// ---------------- graph preprocessing (CSR build) --------------------------------
__global__ void deg_count(const int* __restrict__ dst) {
    int e = blockIdx.x * 256 + threadIdx.x;
    if (e < EE) atomicAdd(&g_deg[dst[e]], 1.0f);
}

__global__ void __launch_bounds__(1024) scan_rowptr() {
    __shared__ int warpsum[32];
    const int tid = threadIdx.x;
    const int lane = tid & 31, wid = tid >> 5;
    const int base = tid * 4;
    int c[4], s = 0;
    #pragma unroll
    for (int j = 0; j < 4; j++) {
        c[j] = (int)g_deg[base + j];
        g_dinv[base + j] = rsqrtf((float)c[j] + 1.0f);
        s += c[j];
    }
    int pre = s;
    #pragma unroll
    for (int off = 1; off < 32; off <<= 1) {
        int v = __shfl_up_sync(0xffffffffu, pre, off);
        if (lane >= off) pre += v;
    }
    if (lane == 31) warpsum[wid] = pre;
    __syncthreads();
    if (wid == 0) {
        int v = warpsum[lane];
        #pragma unroll
        for (int off = 1; off < 32; off <<= 1) {
            int u = __shfl_up_sync(0xffffffffu, v, off);
            if (lane >= off) v += u;
        }
        warpsum[lane] = v;
    }
    __syncthreads();
    int excl = pre - s + (wid > 0 ? warpsum[wid-1] : 0);
    int run = excl;
    #pragma unroll
    for (int j = 0; j < 4; j++) {
        g_rowptr[base + j] = run;
        g_cursor[base + j] = run;
        run += c[j];
    }
    if (tid == 1023) g_rowptr[NN] = run;
}

__global__ void csr_scatter(const int* __restrict__ src, const int* __restrict__ dst) {
    int e = blockIdx.x * 256 + threadIdx.x;
    if (e >= EE) return;
    int s = src[e], d = dst[e];
    int p = atomicAdd(&g_cursor[d], 1);
    g_esrc[p]  = s;
    g_enorm[p] = g_dinv[s] * g_dinv[d];
}

// ---------------- GCN gather (one warp per node, fp16 source rows) ----------------
__device__ __forceinline__ void acc_row(const uint4 v, float wgt, float* a) {
    float2 f0 = __half22float2(*(const __half2*)&v.x);
    float2 f1 = __half22float2(*(const __half2*)&v.y);
    float2 f2 = __half22float2(*(const __half2*)&v.z);
    float2 f3 = __half22float2(*(const __half2*)&v.w);
    a[0] = fmaf(wgt, f0.x, a[0]); a[1] = fmaf(wgt, f0.y, a[1]);
    a[2] = fmaf(wgt, f1.x, a[2]); a[3] = fmaf(wgt, f1.y, a[3]);
    a[4] = fmaf(wgt, f2.x, a[4]); a[5] = fmaf(wgt, f2.y, a[5]);
    a[6] = fmaf(wgt, f3.x, a[6]); a[7] = fmaf(wgt, f3.y, a[7]);
}

template<bool RELU>
__global__ void __launch_bounds__(256) gcn_gather(const float* __restrict__ bias,
                                                  float* __restrict__ out) {
    const int node = blockIdx.x * 8 + (threadIdx.x >> 5);
    const int lane = threadIdx.x & 31;
    const int beg = g_rowptr[node], end = g_rowptr[node+1];

    float a[8] = {};
    int i = beg;
    for (; i + 2 <= end; i += 2) {
        int s0i = g_esrc[i],   s1i = g_esrc[i+1];
        float w0 = g_enorm[i], w1 = g_enorm[i+1];
        uint4 x = *((const uint4*)(g_tmpH + (size_t)s0i*HH) + lane);
        uint4 y = *((const uint4*)(g_tmpH + (size_t)s1i*HH) + lane);
        acc_row(x, w0, a);
        acc_row(y, w1, a);
    }
    if (i < end) {
        uint4 x = *((const uint4*)(g_tmpH + (size_t)g_esrc[i]*HH) + lane);
        acc_row(x, g_enorm[i], a);
    }
    float di = g_dinv[node];
    float sw = di * di;
    uint4 sv = *((const uint4*)(g_tmpH + (size_t)node*HH) + lane);
    acc_row(sv, sw, a);

    const float4* bp = (const float4*)(bias + lane*8);
    float4 b0 = bp[0], b1 = bp[1];
    float o0 = a[0] + b0.x, o1 = a[1] + b0.y, o2 = a[2] + b0.z, o3 = a[3] + b0.w;
    float o4 = a[4] + b1.x, o5 = a[5] + b1.y, o6 = a[6] + b1.z, o7 = a[7] + b1.w;
    if (RELU) {
        o0 = fmaxf(o0,0.f); o1 = fmaxf(o1,0.f); o2 = fmaxf(o2,0.f); o3 = fmaxf(o3,0.f);
        o4 = fmaxf(o4,0.f); o5 = fmaxf(o5,0.f); o6 = fmaxf(o6,0.f); o7 = fmaxf(o7,0.f);
    }
    float4* op = (float4*)(out + (size_t)node*HH + lane*8);
    op[0] = make_float4(o0,o1,o2,o3);
    op[1] = make_float4(o4,o5,o6,o7);
}

// ---------------- bf16 flash attention (3-stage cp.async, 1 barrier/iter) ---------
__global__ void __launch_bounds__(256) flash_attn_bf16() {
    __shared__ __align__(16) char Ks[3][64*80];
    __shared__ __align__(16) char Vs[3][32*144];

    const int head = blockIdx.y;
    const int q0   = blockIdx.x * 128;
    const int tid  = threadIdx.x;
    const int w    = tid >> 5, lane = tid & 31;
    const int g    = lane >> 2, t = lane & 3;
    const int KT   = NN / 64;

    const __nv_bfloat16* kg = g_Kb + (size_t)head*NN*32;
    const __nv_bfloat16* vg = g_Vb + (size_t)head*32*NN;

    const int kr8 = tid >> 2, kc8 = (tid & 3) * 8;
    const int vd  = tid >> 3, vk8 = (tid & 7) * 8;

    cp_async16(&Ks[0][kr8*80 + kc8*2], kg + (size_t)kr8*32 + kc8);
    cp_async16(&Vs[0][vd*144 + vk8*2], vg + (size_t)vd*NN + vk8);
    CP_COMMIT();
    cp_async16(&Ks[1][kr8*80 + kc8*2], kg + (size_t)(64 + kr8)*32 + kc8);
    cp_async16(&Vs[1][vd*144 + vk8*2], vg + (size_t)vd*NN + 64 + vk8);
    CP_COMMIT();

    uint32_t aq[2][4];
    {
        const __nv_bfloat16* qb = g_Qb + ((size_t)head*NN + q0 + w*16) * 32;
        #pragma unroll
        for (int ks = 0; ks < 2; ks++) {
            int c = ks*16 + 2*t;
            aq[ks][0] = *(const uint32_t*)(qb + (size_t)(g  )*32 + c);
            aq[ks][1] = *(const uint32_t*)(qb + (size_t)(g+8)*32 + c);
            aq[ks][2] = *(const uint32_t*)(qb + (size_t)(g  )*32 + c + 8);
            aq[ks][3] = *(const uint32_t*)(qb + (size_t)(g+8)*32 + c + 8);
        }
    }

    float m0 = -1e30f, m1 = -1e30f, l0 = 0.f, l1 = 0.f;
    float o[4][4] = {};

    for (int kt = 0; kt < KT; kt++) {
        const int st = kt % 3;
        if (kt + 1 < KT) { CP_WAIT(1); } else { CP_WAIT(0); }
        __syncthreads();
        if (kt + 2 < KT) {
            const int sp = (kt + 2) % 3;
            cp_async16(&Ks[sp][kr8*80 + kc8*2], kg + (size_t)((kt+2)*64 + kr8)*32 + kc8);
            cp_async16(&Vs[sp][vd*144 + vk8*2], vg + (size_t)vd*NN + (kt+2)*64 + vk8);
            CP_COMMIT();
        }

        float s[8][4];
        #pragma unroll
        for (int nb = 0; nb < 8; nb++) {
            s[nb][0] = s[nb][1] = s[nb][2] = s[nb][3] = 0.f;
            const char* kr = Ks[st] + (nb*8 + g)*80;
            uint32_t b0 = *(const uint32_t*)(kr + (2*t)*2);
            uint32_t b1 = *(const uint32_t*)(kr + (2*t+8)*2);
            mma_bf16(s[nb], aq[0], b0, b1);
            b0 = *(const uint32_t*)(kr + (16 + 2*t)*2);
            b1 = *(const uint32_t*)(kr + (16 + 2*t+8)*2);
            mma_bf16(s[nb], aq[1], b0, b1);
        }

        float tm0 = -1e30f, tm1 = -1e30f;
        #pragma unroll
        for (int nb = 0; nb < 8; nb++) {
            tm0 = fmaxf(tm0, fmaxf(s[nb][0], s[nb][1]));
            tm1 = fmaxf(tm1, fmaxf(s[nb][2], s[nb][3]));
        }
        tm0 = fmaxf(tm0, __shfl_xor_sync(0xffffffffu, tm0, 1));
        tm0 = fmaxf(tm0, __shfl_xor_sync(0xffffffffu, tm0, 2));
        tm1 = fmaxf(tm1, __shfl_xor_sync(0xffffffffu, tm1, 1));
        tm1 = fmaxf(tm1, __shfl_xor_sync(0xffffffffu, tm1, 2));
        float nm0 = fmaxf(m0, tm0), nm1 = fmaxf(m1, tm1);
        float al0 = exp2f(m0 - nm0), al1 = exp2f(m1 - nm1);
        m0 = nm0; m1 = nm1;
        float ps0 = 0.f, ps1 = 0.f;
        #pragma unroll
        for (int nb = 0; nb < 8; nb++) {
            s[nb][0] = exp2f(s[nb][0] - nm0);
            s[nb][1] = exp2f(s[nb][1] - nm0);
            s[nb][2] = exp2f(s[nb][2] - nm1);
            s[nb][3] = exp2f(s[nb][3] - nm1);
            ps0 += s[nb][0] + s[nb][1];
            ps1 += s[nb][2] + s[nb][3];
        }
        ps0 += __shfl_xor_sync(0xffffffffu, ps0, 1);
        ps0 += __shfl_xor_sync(0xffffffffu, ps0, 2);
        ps1 += __shfl_xor_sync(0xffffffffu, ps1, 1);
        ps1 += __shfl_xor_sync(0xffffffffu, ps1, 2);
        l0 = l0 * al0 + ps0;
        l1 = l1 * al1 + ps1;

        #pragma unroll
        for (int nbv = 0; nbv < 4; nbv++) {
            o[nbv][0] *= al0; o[nbv][1] *= al0;
            o[nbv][2] *= al1; o[nbv][3] *= al1;
        }
        uint32_t ap[4][4];
        #pragma unroll
        for (int s4 = 0; s4 < 4; s4++) {
            ap[s4][0] = pack_bf16(s[2*s4  ][0], s[2*s4  ][1]);
            ap[s4][1] = pack_bf16(s[2*s4  ][2], s[2*s4  ][3]);
            ap[s4][2] = pack_bf16(s[2*s4+1][0], s[2*s4+1][1]);
            ap[s4][3] = pack_bf16(s[2*s4+1][2], s[2*s4+1][3]);
        }

        #pragma unroll
        for (int nbv = 0; nbv < 4; nbv++) {
            const char* vr = Vs[st] + (nbv*8 + g)*144;
            #pragma unroll
            for (int s4 = 0; s4 < 4; s4++) {
                uint32_t b0 = *(const uint32_t*)(vr + (16*s4 + 2*t)*2);
                uint32_t b1 = *(const uint32_t*)(vr + (16*s4 + 2*t + 8)*2);
                mma_bf16(o[nbv], ap[s4], b0, b1);
            }
        }
    }

    float inv0 = 1.0f / l0, inv1 = 1.0f / l1;
    int row0 = q0 + w*16 + g;
    #pragma unroll
    for (int nbv = 0; nbv < 4; nbv++) {
        int col = head*32 + nbv*8 + 2*t;
        *(float2*)(g_attn + (size_t)row0*HH + col)       = make_float2(o[nbv][0]*inv0, o[nbv][1]*inv0);
        *(float2*)(g_attn + (size_t)(row0+8)*HH + col)   = make_float2(o[nbv][2]*inv1, o[nbv][3]*inv1);
    }
}

// ---------------- fused output heads (warp per node: softmax3 + sigmoid10) --------
__global__ void __launch_bounds__(256) head_both(const float* __restrict__ W3,
                                                 const float* __restrict__ b3v,
                                                 const float* __restrict__ W10,
                                                 const float* __restrict__ b10,
                                                 float* __restrict__ out) {
    const int node = blockIdx.x * 8 + (threadIdx.x >> 5);
    const int lane = threadIdx.x & 31;

    float4 hv = *(const float4*)(g_hid + (size_t)node*128 + lane*4);
    float lg3[3];
    #pragma unroll
    for (int c = 0; c < 3; c++) {
        float4 wv = *(const float4*)(W3 + c*128 + lane*4);
        float d = hv.x*wv.x + hv.y*wv.y + hv.z*wv.z + hv.w*wv.w;
        #pragma unroll
        for (int m = 16; m >= 1; m >>= 1) d += __shfl_xor_sync(0xffffffffu, d, m);
        lg3[c] = d + b3v[c];
    }
    float4 hv2 = *(const float4*)(g_hid2 + (size_t)node*128 + lane*4);
    float lg10[10];
    #pragma unroll
    for (int c = 0; c < 10; c++) {
        float4 wv = *(const float4*)(W10 + c*128 + lane*4);
        float d = hv2.x*wv.x + hv2.y*wv.y + hv2.z*wv.z + hv2.w*wv.w;
        #pragma unroll
        for (int m = 16; m >= 1; m >>= 1) d += __shfl_xor_sync(0xffffffffu, d, m);
        lg10[c] = d + b10[c];
    }
    if (lane == 0) {
        float mx = fmaxf(fmaxf(lg3[0], lg3[1]), lg3[2]);
        float e0 = __expf(lg3[0]-mx), e1 = __expf(lg3[1]-mx), e2 = __expf(lg3[2]-mx);
        float inv = 1.0f / (e0 + e1 + e2);
        out[(size_t)node*3 + 0] = e0*inv;
        out[(size_t)node*3 + 1] = e1*inv;
        out[(size_t)node*3 + 2] = e2*inv;
        float* o2 = out + (size_t)NN*3 + (size_t)node*10;
        #pragma unroll
        for (int c = 0; c < 10; c++)
            o2[c] = 1.0f / (1.0f + __expf(-lg10[c]));
    }
}

// ---------------- launch ---------------------------------------------------------
extern "C" void kernel_launch(void* const* d_in, const int* in_sizes, int n_in,
                              void* d_out, int out_size)
{
    const float* x     = (const float*)d_in[0];
    const int*   ei    = (const int*)  d_in[1];
    const float* W1    = (const float*)d_in[2];
    const float* b1    = (const float*)d_in[3];
    const float* W2    = (const float*)d_in[4];
    const float* b2    = (const float*)d_in[5];
    const float* W3    = (const float*)d_in[6];
    const float* b3    = (const float*)d_in[7];
    const float* in_w  = (const float*)d_in[8];
    const float* in_b  = (const float*)d_in[9];
    const float* out_w = (const float*)d_in[10];
    const float* out_b = (const float*)d_in[11];
    const float* fp1w  = (const float*)d_in[12];
    const float* fp1b  = (const float*)d_in[13];
    const float* fp2w  = (const float*)d_in[14];
    const float* fp2b  = (const float*)d_in[15];
    const float* pd1w  = (const float*)d_in[16];
    const float* pd1b  = (const float*)d_in[17];
    const float* pd2w  = (const float*)d_in[18];
    const float* pd2b  = (const float*)d_in[19];
    const int* src = ei;
    const int* dst = ei + EE;
    float* outp = (float*)d_out;

    void *tmph;
    float *h, *h3, *deg, *attn, *hid, *hid2;
    cudaGetSymbolAddress((void**)&tmph, g_tmpH);
    cudaGetSymbolAddress((void**)&h,    g_h);
    cudaGetSymbolAddress((void**)&h3,   g_h3);
    cudaGetSymbolAddress((void**)&deg,  g_deg);
    cudaGetSymbolAddress((void**)&attn, g_attn);
    cudaGetSymbolAddress((void**)&hid,  g_hid);
    cudaGetSymbolAddress((void**)&hid2, g_hid2);

    static cudaStream_t s2 = nullptr;
    static cudaEvent_t evF = nullptr, evJ = nullptr;
    if (!s2) {
        cudaStreamCreateWithFlags(&s2, cudaStreamNonBlocking);
        cudaEventCreateWithFlags(&evF, cudaEventDisableTiming);
        cudaEventCreateWithFlags(&evJ, cudaEventDisableTiming);
    }

    const dim3 blk(256);

    // Fork: CSR build on s2  ||  GEMM1 on main stream
    cudaEventRecord(evF, 0);
    cudaStreamWaitEvent(s2, evF, 0);
    cudaMemsetAsync(deg, 0, NN * sizeof(float), s2);
    deg_count<<<EE/256, 256, 0, s2>>>(dst);
    scan_rowptr<<<1, 1024, 0, s2>>>();
    csr_scatter<<<EE/256, 256, 0, s2>>>(src, dst);
    cudaEventRecord(evJ, s2);

    gemm_tf32<false,false,false,false,false,true><<<dim3(4,32), blk>>>(
        x, W1, nullptr, nullptr, nullptr, nullptr, tmph, nullptr, NN, HH, 128);
    cudaStreamWaitEvent(0, evJ, 0);     // join before first gather

    gcn_gather<true><<<NN/8, blk>>>(b1, h);
    gemm_tf32<false,false,false,false,false,true><<<dim3(4,32), blk>>>(
        h, W2, nullptr, nullptr, nullptr, nullptr, tmph, nullptr, NN, HH, HH);
    gcn_gather<true><<<NN/8, blk>>>(b2, h);
    gemm_tf32<false,false,false,false,false,true><<<dim3(4,32), blk>>>(
        h, W3, nullptr, nullptr, nullptr, nullptr, tmph, nullptr, NN, HH, HH);
    gcn_gather<false><<<NN/8, blk>>>(b3, h3);

    // MHA: fused QKV gemm -> (g_Qb, g_Kb, g_Vb); flash attention
    gemm_tf32<true,false,false,true,false,false><<<dim3(12,32), blk>>>(
        h3, in_w, nullptr, in_b, nullptr, nullptr, nullptr, nullptr, NN, 3*HH, HH);
    flash_attn_bf16<<<dim3(NN/128, 8), blk>>>();
    gemm_tf32<true,false,true,false,false,false><<<dim3(4,32), blk>>>(
        attn, out_w, nullptr, out_b, nullptr, h3, h, nullptr, NN, HH, HH);

    // Fused dual-head GEMM + fused heads
    gemm_tf32<true,true,false,false,true,false><<<dim3(4,32), blk>>>(
        h, fp1w, pd1w, fp1b, pd1b, nullptr, hid, hid2, NN, 128, HH);
    head_both<<<NN/8, blk>>>(fp2w, fp2b, pd2w, pd2b, outp);
}

// round 11
// speedup vs baseline: 1.1314x; 1.0051x over previous
#include <cuda_runtime.h>
#include <cuda_bf16.h>
#include <cuda_fp16.h>
#include <cstdint>
#include <math.h>

#define NN 4096
#define EE 131072
#define HH 256

#define QSCALE_F (0.17677669529663687f * 1.4426950408889634f)

// ---------------- scratch (static device globals; no allocation) ----------------
__device__ __half g_tmpH[NN*HH];     // h @ W, fp16 (pre-aggregation)
__device__ float g_h   [NN*HH];
__device__ float g_h3  [NN*HH];
__device__ float g_deg [NN];
__device__ float g_dinv[NN];
__device__ float g_attn[NN*HH];
__device__ float g_hid [NN*128];
__device__ float g_hid2[NN*128];
__device__ int   g_rowptr[NN+1];
__device__ int   g_cursor[NN];
__device__ int   g_esrc [EE];
__device__ float g_enorm[EE];
__device__ __nv_bfloat16 g_Qb[8*NN*32];   // [h][n][d], pre-scaled by 1/sqrt(32)*log2e
__device__ __nv_bfloat16 g_Kb[8*NN*32];   // [h][n][d]
__device__ __half        g_Vh[8*32*NN];   // [h][d][n]  (transposed, fp16)

// ---------------- async-copy helpers ---------------------------------------------
__device__ __forceinline__ void cp_async16(void* smem, const void* gmem) {
    uint32_t s = (uint32_t)__cvta_generic_to_shared(smem);
    asm volatile("cp.async.ca.shared.global [%0], [%1], 16;\n" :: "r"(s), "l"(gmem));
}
#define CP_COMMIT() asm volatile("cp.async.commit_group;\n" ::: "memory")
#define CP_WAIT(n)  asm volatile("cp.async.wait_group %0;\n" :: "n"(n) : "memory")

// ---------------- mma wrappers ----------------------------------------------------
__device__ __forceinline__ void mma_tf32(float* c, const uint32_t* a, uint32_t b0, uint32_t b1) {
    asm volatile(
        "mma.sync.aligned.m16n8k8.row.col.f32.tf32.tf32.f32 "
        "{%0,%1,%2,%3}, {%4,%5,%6,%7}, {%8,%9}, {%0,%1,%2,%3};\n"
        : "+f"(c[0]), "+f"(c[1]), "+f"(c[2]), "+f"(c[3])
        : "r"(a[0]), "r"(a[1]), "r"(a[2]), "r"(a[3]), "r"(b0), "r"(b1));
}
__device__ __forceinline__ void mma_bf16(float* c, const uint32_t* a, uint32_t b0, uint32_t b1) {
    asm volatile(
        "mma.sync.aligned.m16n8k16.row.col.f32.bf16.bf16.f32 "
        "{%0,%1,%2,%3}, {%4,%5,%6,%7}, {%8,%9}, {%0,%1,%2,%3};\n"
        : "+f"(c[0]), "+f"(c[1]), "+f"(c[2]), "+f"(c[3])
        : "r"(a[0]), "r"(a[1]), "r"(a[2]), "r"(a[3]), "r"(b0), "r"(b1));
}
__device__ __forceinline__ void mma_f16(float* c, const uint32_t* a, uint32_t b0, uint32_t b1) {
    asm volatile(
        "mma.sync.aligned.m16n8k16.row.col.f32.f16.f16.f32 "
        "{%0,%1,%2,%3}, {%4,%5,%6,%7}, {%8,%9}, {%0,%1,%2,%3};\n"
        : "+f"(c[0]), "+f"(c[1]), "+f"(c[2]), "+f"(c[3])
        : "r"(a[0]), "r"(a[1]), "r"(a[2]), "r"(a[3]), "r"(b0), "r"(b1));
}
__device__ __forceinline__ uint32_t pack_bf16(float lo, float hi) {
    __nv_bfloat162 v = __floats2bfloat162_rn(lo, hi);
    return *(uint32_t*)&v;
}

// QKV epilogue store: n in [0,768). Block-uniform branch (64-col tiles).
// V written directly to transposed fp16 layout.
__device__ __forceinline__ void store_qkv(int row, int n, float a, float b) {
    int d = n & 31;
    int hh = (n >> 5) & 7;
    if (n < 256) {
        *(uint32_t*)(g_Qb + ((size_t)hh*NN + row)*32 + d) = pack_bf16(a*QSCALE_F, b*QSCALE_F);
    } else if (n < 512) {
        *(uint32_t*)(g_Kb + ((size_t)hh*NN + row)*32 + d) = pack_bf16(a, b);
    } else {
        g_Vh[((size_t)hh*32 + d    )*NN + row] = __float2half(a);
        g_Vh[((size_t)hh*32 + d + 1)*NN + row] = __float2half(b);
    }
}

// ---------------- pipelined tf32 GEMM (128x64, 2-stage; proven) -------------------
template<bool TRANSB, bool RELU, bool ADDSRC, bool QKV, bool DUALB, bool OUTH>
__global__ void __launch_bounds__(256) gemm_tf32(
    const float* __restrict__ A, const float* __restrict__ B,
    const float* __restrict__ B2, const float* __restrict__ bias,
    const float* __restrict__ bias2, const float* __restrict__ SRC,
    void* __restrict__ Cv, void* __restrict__ C2v, int M, int N, int K)
{
    __shared__ float As[2][128*20];
    __shared__ float Bs[2][1280];

    const int tid  = threadIdx.x;
    const int w    = tid >> 5, lane = tid & 31;
    const int g    = lane >> 2, t = lane & 3;
    const int wm   = w & 3, wn = w >> 2;
    const int m0   = blockIdx.y * 128;
    void* Cuse = Cv;
    int n0;
    if (DUALB) {
        n0 = (blockIdx.x & 1) * 64;
        if (blockIdx.x >= 2) { B = B2; bias = bias2; Cuse = C2v; }
    } else {
        n0 = blockIdx.x * 64;
    }
    const int KT   = K >> 4;

    const int ar  = tid >> 2, ac4 = (tid & 3) * 4;
    const int bnr = tid >> 2, bnc = (tid & 3) * 4;
    const int bkr = tid >> 4, bkc = (tid & 15) * 4;

    float acc[2][4][4] = {};

    {
        cp_async16(&As[0][ar*20 + ac4],        A + (size_t)(m0 + ar)*K + ac4);
        cp_async16(&As[0][(ar+64)*20 + ac4],   A + (size_t)(m0 + ar + 64)*K + ac4);
        if (TRANSB) cp_async16(&Bs[0][bnr*20 + bnc], B + (size_t)(n0 + bnr)*K + bnc);
        else        cp_async16(&Bs[0][bkr*72 + bkc], B + (size_t)bkr*N + n0 + bkc);
        CP_COMMIT();
    }

    for (int kt = 0; kt < KT; kt++) {
        const int st = kt & 1;
        if (kt + 1 < KT) {
            const int k0 = (kt + 1) << 4;
            cp_async16(&As[st^1][ar*20 + ac4],      A + (size_t)(m0 + ar)*K + k0 + ac4);
            cp_async16(&As[st^1][(ar+64)*20 + ac4], A + (size_t)(m0 + ar + 64)*K + k0 + ac4);
            if (TRANSB) cp_async16(&Bs[st^1][bnr*20 + bnc], B + (size_t)(n0 + bnr)*K + k0 + bnc);
            else        cp_async16(&Bs[st^1][bkr*72 + bkc], B + (size_t)(k0 + bkr)*N + n0 + bkc);
            CP_COMMIT();
            CP_WAIT(1);
        } else {
            CP_WAIT(0);
        }
        __syncthreads();

        const uint32_t* as = (const uint32_t*)As[st];
        const uint32_t* bs = (const uint32_t*)Bs[st];
        #pragma unroll
        for (int ks = 0; ks < 2; ks++) {
            const int kb = ks * 8;
            uint32_t a[2][4];
            #pragma unroll
            for (int mt = 0; mt < 2; mt++) {
                int row = wm*32 + mt*16 + g;
                a[mt][0] = as[(row  )*20 + kb + t];
                a[mt][1] = as[(row+8)*20 + kb + t];
                a[mt][2] = as[(row  )*20 + kb + t + 4];
                a[mt][3] = as[(row+8)*20 + kb + t + 4];
            }
            #pragma unroll
            for (int nt = 0; nt < 4; nt++) {
                int n = wn*32 + nt*8 + g;
                uint32_t b0, b1;
                if (TRANSB) { b0 = bs[n*20 + kb + t];  b1 = bs[n*20 + kb + t + 4]; }
                else        { b0 = bs[(kb+t)*72 + n];  b1 = bs[(kb+t+4)*72 + n];   }
                mma_tf32(acc[0][nt], a[0], b0, b1);
                mma_tf32(acc[1][nt], a[1], b0, b1);
            }
        }
        __syncthreads();
    }

    #pragma unroll
    for (int mt = 0; mt < 2; mt++) {
        const int r0 = m0 + wm*32 + mt*16 + g;
        #pragma unroll
        for (int nt = 0; nt < 4; nt++) {
            const int n = n0 + wn*32 + nt*8 + 2*t;
            float bb0 = bias ? bias[n] : 0.f;
            float bb1 = bias ? bias[n+1] : 0.f;
            float v00 = acc[mt][nt][0] + bb0, v01 = acc[mt][nt][1] + bb1;
            float v10 = acc[mt][nt][2] + bb0, v11 = acc[mt][nt][3] + bb1;
            if (ADDSRC) {
                v00 += SRC[(size_t)r0*N + n];     v01 += SRC[(size_t)r0*N + n + 1];
                v10 += SRC[(size_t)(r0+8)*N + n]; v11 += SRC[(size_t)(r0+8)*N + n + 1];
            }
            if (RELU) {
                v00 = fmaxf(v00, 0.f); v01 = fmaxf(v01, 0.f);
                v10 = fmaxf(v10, 0.f); v11 = fmaxf(v11, 0.f);
            }
            if (QKV) {
                store_qkv(r0,     n, v00, v01);
                store_qkv(r0 + 8, n, v10, v11);
            } else if (OUTH) {
                __half* C = (__half*)Cuse;
                __half2 h0 = __floats2half2_rn(v00, v01);
                __half2 h1 = __floats2half2_rn(v10, v11);
                *(uint32_t*)(C + (size_t)r0*N + n)     = *(uint32_t*)&h0;
                *(uint32_t*)(C + (size_t)(r0+8)*N + n) = *(uint32_t*)&h1;
            } else {
                float* C = (float*)Cuse;
                *(float2*)(C + (size_t)r0*N + n)     = make_float2(v00, v01);
                *(float2*)(C + (size_t)(r0+8)*N + n) = make_float2(v10, v11);
            }
        }
    }
}

// ---------------- graph preprocessing (CSR build) --------------------------------
__global__ void deg_count(const int* __restrict__ dst) {
    int e = blockIdx.x * 256 + threadIdx.x;
    if (e < EE) atomicAdd(&g_deg[dst[e]], 1.0f);
}

__global__ void __launch_bounds__(1024) scan_rowptr() {
    __shared__ int warpsum[32];
    const int tid = threadIdx.x;
    const int lane = tid & 31, wid = tid >> 5;
    const int base = tid * 4;
    int c[4], s = 0;
    #pragma unroll
    for (int j = 0; j < 4; j++) {
        c[j] = (int)g_deg[base + j];
        g_dinv[base + j] = rsqrtf((float)c[j] + 1.0f);
        s += c[j];
    }
    int pre = s;
    #pragma unroll
    for (int off = 1; off < 32; off <<= 1) {
        int v = __shfl_up_sync(0xffffffffu, pre, off);
        if (lane >= off) pre += v;
    }
    if (lane == 31) warpsum[wid] = pre;
    __syncthreads();
    if (wid == 0) {
        int v = warpsum[lane];
        #pragma unroll
        for (int off = 1; off < 32; off <<= 1) {
            int u = __shfl_up_sync(0xffffffffu, v, off);
            if (lane >= off) v += u;
        }
        warpsum[lane] = v;
    }
    __syncthreads();
    int excl = pre - s + (wid > 0 ? warpsum[wid-1] : 0);
    int run = excl;
    #pragma unroll
    for (int j = 0; j < 4; j++) {
        g_rowptr[base + j] = run;
        g_cursor[base + j] = run;
        run += c[j];
    }
    if (tid == 1023) g_rowptr[NN] = run;
}

__global__ void csr_scatter(const int* __restrict__ src, const int* __restrict__ dst) {
    int e = blockIdx.x * 256 + threadIdx.x;
    if (e >= EE) return;
    int s = src[e], d = dst[e];
    int p = atomicAdd(&g_cursor[d], 1);
    g_esrc[p]  = s;
    g_enorm[p] = g_dinv[s] * g_dinv[d];
}

// ---------------- GCN gather (one warp per node, fp16 source rows) ----------------
__device__ __forceinline__ void acc_row(const uint4 v, float wgt, float* a) {
    float2 f0 = __half22float2(*(const __half2*)&v.x);
    float2 f1 = __half22float2(*(const __half2*)&v.y);
    float2 f2 = __half22float2(*(const __half2*)&v.z);
    float2 f3 = __half22float2(*(const __half2*)&v.w);
    a[0] = fmaf(wgt, f0.x, a[0]); a[1] = fmaf(wgt, f0.y, a[1]);
    a[2] = fmaf(wgt, f1.x, a[2]); a[3] = fmaf(wgt, f1.y, a[3]);
    a[4] = fmaf(wgt, f2.x, a[4]); a[5] = fmaf(wgt, f2.y, a[5]);
    a[6] = fmaf(wgt, f3.x, a[6]); a[7] = fmaf(wgt, f3.y, a[7]);
}

template<bool RELU>
__global__ void __launch_bounds__(256) gcn_gather(const float* __restrict__ bias,
                                                  float* __restrict__ out) {
    const int node = blockIdx.x * 8 + (threadIdx.x >> 5);
    const int lane = threadIdx.x & 31;
    const int beg = g_rowptr[node], end = g_rowptr[node+1];

    float a[8] = {};
    int i = beg;
    for (; i + 2 <= end; i += 2) {
        int s0i = g_esrc[i],   s1i = g_esrc[i+1];
        float w0 = g_enorm[i], w1 = g_enorm[i+1];
        uint4 x = *((const uint4*)(g_tmpH + (size_t)s0i*HH) + lane);
        uint4 y = *((const uint4*)(g_tmpH + (size_t)s1i*HH) + lane);
        acc_row(x, w0, a);
        acc_row(y, w1, a);
    }
    if (i < end) {
        uint4 x = *((const uint4*)(g_tmpH + (size_t)g_esrc[i]*HH) + lane);
        acc_row(x, g_enorm[i], a);
    }
    float di = g_dinv[node];
    float sw = di * di;
    uint4 sv = *((const uint4*)(g_tmpH + (size_t)node*HH) + lane);
    acc_row(sv, sw, a);

    const float4* bp = (const float4*)(bias + lane*8);
    float4 b0 = bp[0], b1 = bp[1];
    float o0 = a[0] + b0.x, o1 = a[1] + b0.y, o2 = a[2] + b0.z, o3 = a[3] + b0.w;
    float o4 = a[4] + b1.x, o5 = a[5] + b1.y, o6 = a[6] + b1.z, o7 = a[7] + b1.w;
    if (RELU) {
        o0 = fmaxf(o0,0.f); o1 = fmaxf(o1,0.f); o2 = fmaxf(o2,0.f); o3 = fmaxf(o3,0.f);
        o4 = fmaxf(o4,0.f); o5 = fmaxf(o5,0.f); o6 = fmaxf(o6,0.f); o7 = fmaxf(o7,0.f);
    }
    float4* op = (float4*)(out + (size_t)node*HH + lane*8);
    op[0] = make_float4(o0,o1,o2,o3);
    op[1] = make_float4(o4,o5,o6,o7);
}

// ---------------- flash attention: bf16 QK, fp16x2 exp, fp16 PV, mma row-sums -----
__global__ void __launch_bounds__(256) flash_attn_bf16() {
    __shared__ __align__(16) char Ks[3][64*80];
    __shared__ __align__(16) char Vs[3][32*144];

    const int head = blockIdx.y;
    const int q0   = blockIdx.x * 128;
    const int tid  = threadIdx.x;
    const int w    = tid >> 5, lane = tid & 31;
    const int g    = lane >> 2, t = lane & 3;
    const int KT   = NN / 64;
    const uint32_t ONES2 = 0x3C003C00u;   // half2(1,1)

    const __nv_bfloat16* kg = g_Kb + (size_t)head*NN*32;
    const __half*        vg = g_Vh + (size_t)head*32*NN;

    const int kr8 = tid >> 2, kc8 = (tid & 3) * 8;
    const int vd  = tid >> 3, vk8 = (tid & 7) * 8;

    cp_async16(&Ks[0][kr8*80 + kc8*2], kg + (size_t)kr8*32 + kc8);
    cp_async16(&Vs[0][vd*144 + vk8*2], vg + (size_t)vd*NN + vk8);
    CP_COMMIT();
    cp_async16(&Ks[1][kr8*80 + kc8*2], kg + (size_t)(64 + kr8)*32 + kc8);
    cp_async16(&Vs[1][vd*144 + vk8*2], vg + (size_t)vd*NN + 64 + vk8);
    CP_COMMIT();

    uint32_t aq[2][4];
    {
        const __nv_bfloat16* qb = g_Qb + ((size_t)head*NN + q0 + w*16) * 32;
        #pragma unroll
        for (int ks = 0; ks < 2; ks++) {
            int c = ks*16 + 2*t;
            aq[ks][0] = *(const uint32_t*)(qb + (size_t)(g  )*32 + c);
            aq[ks][1] = *(const uint32_t*)(qb + (size_t)(g+8)*32 + c);
            aq[ks][2] = *(const uint32_t*)(qb + (size_t)(g  )*32 + c + 8);
            aq[ks][3] = *(const uint32_t*)(qb + (size_t)(g+8)*32 + c + 8);
        }
    }

    float m0 = -1e30f, m1 = -1e30f;
    float o[4][4] = {};
    float lacc[4] = {};     // [0]=row g sum, [2]=row g+8 sum (via ones-mma)

    for (int kt = 0; kt < KT; kt++) {
        const int st = kt % 3;
        if (kt + 1 < KT) { CP_WAIT(1); } else { CP_WAIT(0); }
        __syncthreads();
        if (kt + 2 < KT) {
            const int sp = (kt + 2) % 3;
            cp_async16(&Ks[sp][kr8*80 + kc8*2], kg + (size_t)((kt+2)*64 + kr8)*32 + kc8);
            cp_async16(&Vs[sp][vd*144 + vk8*2], vg + (size_t)vd*NN + (kt+2)*64 + vk8);
            CP_COMMIT();
        }

        float s[8][4];
        #pragma unroll
        for (int nb = 0; nb < 8; nb++) {
            s[nb][0] = s[nb][1] = s[nb][2] = s[nb][3] = 0.f;
            const char* kr = Ks[st] + (nb*8 + g)*80;
            uint32_t b0 = *(const uint32_t*)(kr + (2*t)*2);
            uint32_t b1 = *(const uint32_t*)(kr + (2*t+8)*2);
            mma_bf16(s[nb], aq[0], b0, b1);
            b0 = *(const uint32_t*)(kr + (16 + 2*t)*2);
            b1 = *(const uint32_t*)(kr + (16 + 2*t+8)*2);
            mma_bf16(s[nb], aq[1], b0, b1);
        }

        // running max (fp32, 2 shuffle levels over t-quad)
        float tm0 = -1e30f, tm1 = -1e30f;
        #pragma unroll
        for (int nb = 0; nb < 8; nb++) {
            tm0 = fmaxf(tm0, fmaxf(s[nb][0], s[nb][1]));
            tm1 = fmaxf(tm1, fmaxf(s[nb][2], s[nb][3]));
        }
        tm0 = fmaxf(tm0, __shfl_xor_sync(0xffffffffu, tm0, 1));
        tm0 = fmaxf(tm0, __shfl_xor_sync(0xffffffffu, tm0, 2));
        tm1 = fmaxf(tm1, __shfl_xor_sync(0xffffffffu, tm1, 1));
        tm1 = fmaxf(tm1, __shfl_xor_sync(0xffffffffu, tm1, 2));
        float nm0 = fmaxf(m0, tm0), nm1 = fmaxf(m1, tm1);
        float al0 = exp2f(m0 - nm0), al1 = exp2f(m1 - nm1);
        m0 = nm0; m1 = nm1;

        // P = exp2(S - m) in fp16x2 (half the MUFU ops; result IS the mma fragment)
        __half2 p01[8], p23[8];
        #pragma unroll
        for (int nb = 0; nb < 8; nb++) {
            p01[nb] = h2exp2(__floats2half2_rn(s[nb][0] - nm0, s[nb][1] - nm0));
            p23[nb] = h2exp2(__floats2half2_rn(s[nb][2] - nm1, s[nb][3] - nm1));
        }

        // rescale running O and l
        #pragma unroll
        for (int nbv = 0; nbv < 4; nbv++) {
            o[nbv][0] *= al0; o[nbv][1] *= al0;
            o[nbv][2] *= al1; o[nbv][3] *= al1;
        }
        lacc[0] *= al0; lacc[1] *= al0; lacc[2] *= al1; lacc[3] *= al1;

        uint32_t ap[4][4];
        #pragma unroll
        for (int s4 = 0; s4 < 4; s4++) {
            ap[s4][0] = *(const uint32_t*)&p01[2*s4];
            ap[s4][1] = *(const uint32_t*)&p23[2*s4];
            ap[s4][2] = *(const uint32_t*)&p01[2*s4+1];
            ap[s4][3] = *(const uint32_t*)&p23[2*s4+1];
        }

        // O += P @ V (fp16), and l += P @ 1 (row sums via tensor core)
        #pragma unroll
        for (int s4 = 0; s4 < 4; s4++) {
            mma_f16(lacc, ap[s4], ONES2, ONES2);
            #pragma unroll
            for (int nbv = 0; nbv < 4; nbv++) {
                const char* vr = Vs[st] + (nbv*8 + g)*144;
                uint32_t b0 = *(const uint32_t*)(vr + (16*s4 + 2*t)*2);
                uint32_t b1 = *(const uint32_t*)(vr + (16*s4 + 2*t + 8)*2);
                mma_f16(o[nbv], ap[s4], b0, b1);
            }
        }
    }

    float inv0 = 1.0f / lacc[0], inv1 = 1.0f / lacc[2];
    int row0 = q0 + w*16 + g;
    #pragma unroll
    for (int nbv = 0; nbv < 4; nbv++) {
        int col = head*32 + nbv*8 + 2*t;
        *(float2*)(g_attn + (size_t)row0*HH + col)       = make_float2(o[nbv][0]*inv0, o[nbv][1]*inv0);
        *(float2*)(g_attn + (size_t)(row0+8)*HH + col)   = make_float2(o[nbv][2]*inv1, o[nbv][3]*inv1);
    }
}

// ---------------- fused output heads (warp per node: softmax3 + sigmoid10) --------
__global__ void __launch_bounds__(256) head_both(const float* __restrict__ W3,
                                                 const float* __restrict__ b3v,
                                                 const float* __restrict__ W10,
                                                 const float* __restrict__ b10,
                                                 float* __restrict__ out) {
    const int node = blockIdx.x * 8 + (threadIdx.x >> 5);
    const int lane = threadIdx.x & 31;

    float4 hv = *(const float4*)(g_hid + (size_t)node*128 + lane*4);
    float lg3[3];
    #pragma unroll
    for (int c = 0; c < 3; c++) {
        float4 wv = *(const float4*)(W3 + c*128 + lane*4);
        float d = hv.x*wv.x + hv.y*wv.y + hv.z*wv.z + hv.w*wv.w;
        #pragma unroll
        for (int m = 16; m >= 1; m >>= 1) d += __shfl_xor_sync(0xffffffffu, d, m);
        lg3[c] = d + b3v[c];
    }
    float4 hv2 = *(const float4*)(g_hid2 + (size_t)node*128 + lane*4);
    float lg10[10];
    #pragma unroll
    for (int c = 0; c < 10; c++) {
        float4 wv = *(const float4*)(W10 + c*128 + lane*4);
        float d = hv2.x*wv.x + hv2.y*wv.y + hv2.z*wv.z + hv2.w*wv.w;
        #pragma unroll
        for (int m = 16; m >= 1; m >>= 1) d += __shfl_xor_sync(0xffffffffu, d, m);
        lg10[c] = d + b10[c];
    }
    if (lane == 0) {
        float mx = fmaxf(fmaxf(lg3[0], lg3[1]), lg3[2]);
        float e0 = __expf(lg3[0]-mx), e1 = __expf(lg3[1]-mx), e2 = __expf(lg3[2]-mx);
        float inv = 1.0f / (e0 + e1 + e2);
        out[(size_t)node*3 + 0] = e0*inv;
        out[(size_t)node*3 + 1] = e1*inv;
        out[(size_t)node*3 + 2] = e2*inv;
        float* o2 = out + (size_t)NN*3 + (size_t)node*10;
        #pragma unroll
        for (int c = 0; c < 10; c++)
            o2[c] = 1.0f / (1.0f + __expf(-lg10[c]));
    }
}

// ---------------- launch ---------------------------------------------------------
extern "C" void kernel_launch(void* const* d_in, const int* in_sizes, int n_in,
                              void* d_out, int out_size)
{
    const float* x     = (const float*)d_in[0];
    const int*   ei    = (const int*)  d_in[1];
    const float* W1    = (const float*)d_in[2];
    const float* b1    = (const float*)d_in[3];
    const float* W2    = (const float*)d_in[4];
    const float* b2    = (const float*)d_in[5];
    const float* W3    = (const float*)d_in[6];
    const float* b3    = (const float*)d_in[7];
    const float* in_w  = (const float*)d_in[8];
    const float* in_b  = (const float*)d_in[9];
    const float* out_w = (const float*)d_in[10];
    const float* out_b = (const float*)d_in[11];
    const float* fp1w  = (const float*)d_in[12];
    const float* fp1b  = (const float*)d_in[13];
    const float* fp2w  = (const float*)d_in[14];
    const float* fp2b  = (const float*)d_in[15];
    const float* pd1w  = (const float*)d_in[16];
    const float* pd1b  = (const float*)d_in[17];
    const float* pd2w  = (const float*)d_in[18];
    const float* pd2b  = (const float*)d_in[19];
    const int* src = ei;
    const int* dst = ei + EE;
    float* outp = (float*)d_out;

    void *tmph;
    float *h, *h3, *deg, *attn, *hid, *hid2;
    cudaGetSymbolAddress((void**)&tmph, g_tmpH);
    cudaGetSymbolAddress((void**)&h,    g_h);
    cudaGetSymbolAddress((void**)&h3,   g_h3);
    cudaGetSymbolAddress((void**)&deg,  g_deg);
    cudaGetSymbolAddress((void**)&attn, g_attn);
    cudaGetSymbolAddress((void**)&hid,  g_hid);
    cudaGetSymbolAddress((void**)&hid2, g_hid2);

    static cudaStream_t s2 = nullptr;
    static cudaEvent_t evF = nullptr, evJ = nullptr;
    if (!s2) {
        cudaStreamCreateWithFlags(&s2, cudaStreamNonBlocking);
        cudaEventCreateWithFlags(&evF, cudaEventDisableTiming);
        cudaEventCreateWithFlags(&evJ, cudaEventDisableTiming);
    }

    const dim3 blk(256);

    // Fork: CSR build on s2  ||  GEMM1 on main stream
    cudaEventRecord(evF, 0);
    cudaStreamWaitEvent(s2, evF, 0);
    cudaMemsetAsync(deg, 0, NN * sizeof(float), s2);
    deg_count<<<EE/256, 256, 0, s2>>>(dst);
    scan_rowptr<<<1, 1024, 0, s2>>>();
    csr_scatter<<<EE/256, 256, 0, s2>>>(src, dst);
    cudaEventRecord(evJ, s2);

    gemm_tf32<false,false,false,false,false,true><<<dim3(4,32), blk>>>(
        x, W1, nullptr, nullptr, nullptr, nullptr, tmph, nullptr, NN, HH, 128);
    cudaStreamWaitEvent(0, evJ, 0);     // join before first gather

    gcn_gather<true><<<NN/8, blk>>>(b1, h);
    gemm_tf32<false,false,false,false,false,true><<<dim3(4,32), blk>>>(
        h, W2, nullptr, nullptr, nullptr, nullptr, tmph, nullptr, NN, HH, HH);
    gcn_gather<true><<<NN/8, blk>>>(b2, h);
    gemm_tf32<false,false,false,false,false,true><<<dim3(4,32), blk>>>(
        h, W3, nullptr, nullptr, nullptr, nullptr, tmph, nullptr, NN, HH, HH);
    gcn_gather<false><<<NN/8, blk>>>(b3, h3);

    // MHA: fused QKV gemm -> (g_Qb, g_Kb, g_Vh); flash attention
    gemm_tf32<true,false,false,true,false,false><<<dim3(12,32), blk>>>(
        h3, in_w, nullptr, in_b, nullptr, nullptr, nullptr, nullptr, NN, 3*HH, HH);
    flash_attn_bf16<<<dim3(NN/128, 8), blk>>>();
    gemm_tf32<true,false,true,false,false,false><<<dim3(4,32), blk>>>(
        attn, out_w, nullptr, out_b, nullptr, h3, h, nullptr, NN, HH, HH);

    // Fused dual-head GEMM + fused heads
    gemm_tf32<true,true,false,false,true,false><<<dim3(4,32), blk>>>(
        h, fp1w, pd1w, fp1b, pd1b, nullptr, hid, hid2, NN, 128, HH);
    head_both<<<NN/8, blk>>>(fp2w, fp2b, pd2w, pd2b, outp);
}

// round 12
// speedup vs baseline: 1.1684x; 1.0327x over previous
#include <cuda_runtime.h>
#include <cuda_bf16.h>
#include <cuda_fp16.h>
#include <cstdint>
#include <math.h>

#define NN 4096
#define EE 131072
#define HH 256

#define QSCALE_F (0.17677669529663687f * 1.4426950408889634f)

// ---------------- scratch (static device globals; no allocation) ----------------
__device__ __half g_tmpH[NN*HH];     // h @ W, fp16 (pre-aggregation)
__device__ float g_h   [NN*HH];
__device__ float g_h3  [NN*HH];
__device__ float g_deg [NN];
__device__ float g_dinv[NN];
__device__ float g_attn[NN*HH];
__device__ float g_hid [NN*128];
__device__ float g_hid2[NN*128];
__device__ int   g_rowptr[NN+1];
__device__ int   g_cursor[NN];
__device__ int   g_esrc [EE];
__device__ float g_enorm[EE];
__device__ __nv_bfloat16 g_Qb[8*NN*32];   // [h][n][d], pre-scaled by 1/sqrt(32)*log2e
__device__ __nv_bfloat16 g_Kb[8*NN*32];   // [h][n][d]
__device__ __half        g_Vh[8*32*NN];   // [h][d][n]  (transposed, fp16)

// ---------------- async-copy helpers ---------------------------------------------
__device__ __forceinline__ void cp_async16(void* smem, const void* gmem) {
    uint32_t s = (uint32_t)__cvta_generic_to_shared(smem);
    asm volatile("cp.async.ca.shared.global [%0], [%1], 16;\n" :: "r"(s), "l"(gmem));
}
#define CP_COMMIT() asm volatile("cp.async.commit_group;\n" ::: "memory")
#define CP_WAIT(n)  asm volatile("cp.async.wait_group %0;\n" :: "n"(n) : "memory")

// ---------------- mma wrappers ----------------------------------------------------
__device__ __forceinline__ void mma_tf32(float* c, const uint32_t* a, uint32_t b0, uint32_t b1) {
    asm volatile(
        "mma.sync.aligned.m16n8k8.row.col.f32.tf32.tf32.f32 "
        "{%0,%1,%2,%3}, {%4,%5,%6,%7}, {%8,%9}, {%0,%1,%2,%3};\n"
        : "+f"(c[0]), "+f"(c[1]), "+f"(c[2]), "+f"(c[3])
        : "r"(a[0]), "r"(a[1]), "r"(a[2]), "r"(a[3]), "r"(b0), "r"(b1));
}
__device__ __forceinline__ void mma_bf16(float* c, const uint32_t* a, uint32_t b0, uint32_t b1) {
    asm volatile(
        "mma.sync.aligned.m16n8k16.row.col.f32.bf16.bf16.f32 "
        "{%0,%1,%2,%3}, {%4,%5,%6,%7}, {%8,%9}, {%0,%1,%2,%3};\n"
        : "+f"(c[0]), "+f"(c[1]), "+f"(c[2]), "+f"(c[3])
        : "r"(a[0]), "r"(a[1]), "r"(a[2]), "r"(a[3]), "r"(b0), "r"(b1));
}
__device__ __forceinline__ void mma_f16(float* c, const uint32_t* a, uint32_t b0, uint32_t b1) {
    asm volatile(
        "mma.sync.aligned.m16n8k16.row.col.f32.f16.f16.f32 "
        "{%0,%1,%2,%3}, {%4,%5,%6,%7}, {%8,%9}, {%0,%1,%2,%3};\n"
        : "+f"(c[0]), "+f"(c[1]), "+f"(c[2]), "+f"(c[3])
        : "r"(a[0]), "r"(a[1]), "r"(a[2]), "r"(a[3]), "r"(b0), "r"(b1));
}
__device__ __forceinline__ uint32_t pack_bf16(float lo, float hi) {
    __nv_bfloat162 v = __floats2bfloat162_rn(lo, hi);
    return *(uint32_t*)&v;
}

// QKV epilogue store: n in [0,768). Block-uniform branch (64-col tiles).
__device__ __forceinline__ void store_qkv(int row, int n, float a, float b) {
    int d = n & 31;
    int hh = (n >> 5) & 7;
    if (n < 256) {
        *(uint32_t*)(g_Qb + ((size_t)hh*NN + row)*32 + d) = pack_bf16(a*QSCALE_F, b*QSCALE_F);
    } else if (n < 512) {
        *(uint32_t*)(g_Kb + ((size_t)hh*NN + row)*32 + d) = pack_bf16(a, b);
    } else {
        g_Vh[((size_t)hh*32 + d    )*NN + row] = __float2half(a);
        g_Vh[((size_t)hh*32 + d + 1)*NN + row] = __float2half(b);
    }
}

// ---------------- pipelined tf32 GEMM (128x64, 3-stage ring, 1 barrier/iter) ------
template<bool TRANSB, bool RELU, bool ADDSRC, bool QKV, bool DUALB, bool OUTH>
__global__ void __launch_bounds__(256) gemm_tf32(
    const float* __restrict__ A, const float* __restrict__ B,
    const float* __restrict__ B2, const float* __restrict__ bias,
    const float* __restrict__ bias2, const float* __restrict__ SRC,
    void* __restrict__ Cv, void* __restrict__ C2v, int M, int N, int K)
{
    __shared__ float As[3][128*20];
    __shared__ float Bs[3][1280];

    const int tid  = threadIdx.x;
    const int w    = tid >> 5, lane = tid & 31;
    const int g    = lane >> 2, t = lane & 3;
    const int wm   = w & 3, wn = w >> 2;
    const int m0   = blockIdx.y * 128;
    void* Cuse = Cv;
    int n0;
    if (DUALB) {
        n0 = (blockIdx.x & 1) * 64;
        if (blockIdx.x >= 2) { B = B2; bias = bias2; Cuse = C2v; }
    } else {
        n0 = blockIdx.x * 64;
    }
    const int KT   = K >> 4;

    const int ar  = tid >> 2, ac4 = (tid & 3) * 4;
    const int bnr = tid >> 2, bnc = (tid & 3) * 4;
    const int bkr = tid >> 4, bkc = (tid & 15) * 4;

    float acc[2][4][4] = {};

    // prologue: stages 0,1
    #pragma unroll
    for (int p = 0; p < 2; p++) {
        const int k0 = p << 4;
        cp_async16(&As[p][ar*20 + ac4],      A + (size_t)(m0 + ar)*K + k0 + ac4);
        cp_async16(&As[p][(ar+64)*20 + ac4], A + (size_t)(m0 + ar + 64)*K + k0 + ac4);
        if (TRANSB) cp_async16(&Bs[p][bnr*20 + bnc], B + (size_t)(n0 + bnr)*K + k0 + bnc);
        else        cp_async16(&Bs[p][bkr*72 + bkc], B + (size_t)(k0 + bkr)*N + n0 + bkc);
        CP_COMMIT();
    }

    for (int kt = 0; kt < KT; kt++) {
        const int st = kt % 3;
        if (kt + 1 < KT) { CP_WAIT(1); } else { CP_WAIT(0); }
        __syncthreads();                // stage kt visible; stage (kt+2)%3 free
        if (kt + 2 < KT) {
            const int sp = (kt + 2) % 3;
            const int k0 = (kt + 2) << 4;
            cp_async16(&As[sp][ar*20 + ac4],      A + (size_t)(m0 + ar)*K + k0 + ac4);
            cp_async16(&As[sp][(ar+64)*20 + ac4], A + (size_t)(m0 + ar + 64)*K + k0 + ac4);
            if (TRANSB) cp_async16(&Bs[sp][bnr*20 + bnc], B + (size_t)(n0 + bnr)*K + k0 + bnc);
            else        cp_async16(&Bs[sp][bkr*72 + bkc], B + (size_t)(k0 + bkr)*N + n0 + bkc);
            CP_COMMIT();
        }

        const uint32_t* as = (const uint32_t*)As[st];
        const uint32_t* bs = (const uint32_t*)Bs[st];
        #pragma unroll
        for (int ks = 0; ks < 2; ks++) {
            const int kb = ks * 8;
            uint32_t a[2][4];
            #pragma unroll
            for (int mt = 0; mt < 2; mt++) {
                int row = wm*32 + mt*16 + g;
                a[mt][0] = as[(row  )*20 + kb + t];
                a[mt][1] = as[(row+8)*20 + kb + t];
                a[mt][2] = as[(row  )*20 + kb + t + 4];
                a[mt][3] = as[(row+8)*20 + kb + t + 4];
            }
            #pragma unroll
            for (int nt = 0; nt < 4; nt++) {
                int n = wn*32 + nt*8 + g;
                uint32_t b0, b1;
                if (TRANSB) { b0 = bs[n*20 + kb + t];  b1 = bs[n*20 + kb + t + 4]; }
                else        { b0 = bs[(kb+t)*72 + n];  b1 = bs[(kb+t+4)*72 + n];   }
                mma_tf32(acc[0][nt], a[0], b0, b1);
                mma_tf32(acc[1][nt], a[1], b0, b1);
            }
        }
    }

    #pragma unroll
    for (int mt = 0; mt < 2; mt++) {
        const int r0 = m0 + wm*32 + mt*16 + g;
        #pragma unroll
        for (int nt = 0; nt < 4; nt++) {
            const int n = n0 + wn*32 + nt*8 + 2*t;
            float bb0 = bias ? bias[n] : 0.f;
            float bb1 = bias ? bias[n+1] : 0.f;
            float v00 = acc[mt][nt][0] + bb0, v01 = acc[mt][nt][1] + bb1;
            float v10 = acc[mt][nt][2] + bb0, v11 = acc[mt][nt][3] + bb1;
            if (ADDSRC) {
                v00 += SRC[(size_t)r0*N + n];     v01 += SRC[(size_t)r0*N + n + 1];
                v10 += SRC[(size_t)(r0+8)*N + n]; v11 += SRC[(size_t)(r0+8)*N + n + 1];
            }
            if (RELU) {
                v00 = fmaxf(v00, 0.f); v01 = fmaxf(v01, 0.f);
                v10 = fmaxf(v10, 0.f); v11 = fmaxf(v11, 0.f);
            }
            if (QKV) {
                store_qkv(r0,     n, v00, v01);
                store_qkv(r0 + 8, n, v10, v11);
            } else if (OUTH) {
                __half* C = (__half*)Cuse;
                __half2 h0 = __floats2half2_rn(v00, v01);
                __half2 h1 = __floats2half2_rn(v10, v11);
                *(uint32_t*)(C + (size_t)r0*N + n)     = *(uint32_t*)&h0;
                *(uint32_t*)(C + (size_t)(r0+8)*N + n) = *(uint32_t*)&h1;
            } else {
                float* C = (float*)Cuse;
                *(float2*)(C + (size_t)r0*N + n)     = make_float2(v00, v01);
                *(float2*)(C + (size_t)(r0+8)*N + n) = make_float2(v10, v11);
            }
        }
    }
}

// ---------------- graph preprocessing (CSR build) --------------------------------
__global__ void deg_count(const int* __restrict__ dst) {
    int e = blockIdx.x * 256 + threadIdx.x;
    if (e < EE) atomicAdd(&g_deg[dst[e]], 1.0f);
}

__global__ void __launch_bounds__(1024) scan_rowptr() {
    __shared__ int warpsum[32];
    const int tid = threadIdx.x;
    const int lane = tid & 31, wid = tid >> 5;
    const int base = tid * 4;
    int c[4], s = 0;
    #pragma unroll
    for (int j = 0; j < 4; j++) {
        c[j] = (int)g_deg[base + j];
        g_dinv[base + j] = rsqrtf((float)c[j] + 1.0f);
        s += c[j];
    }
    int pre = s;
    #pragma unroll
    for (int off = 1; off < 32; off <<= 1) {
        int v = __shfl_up_sync(0xffffffffu, pre, off);
        if (lane >= off) pre += v;
    }
    if (lane == 31) warpsum[wid] = pre;
    __syncthreads();
    if (wid == 0) {
        int v = warpsum[lane];
        #pragma unroll
        for (int off = 1; off < 32; off <<= 1) {
            int u = __shfl_up_sync(0xffffffffu, v, off);
            if (lane >= off) v += u;
        }
        warpsum[lane] = v;
    }
    __syncthreads();
    int excl = pre - s + (wid > 0 ? warpsum[wid-1] : 0);
    int run = excl;
    #pragma unroll
    for (int j = 0; j < 4; j++) {
        g_rowptr[base + j] = run;
        g_cursor[base + j] = run;
        run += c[j];
    }
    if (tid == 1023) g_rowptr[NN] = run;
}

__global__ void csr_scatter(const int* __restrict__ src, const int* __restrict__ dst) {
    int e = blockIdx.x * 256 + threadIdx.x;
    if (e >= EE) return;
    int s = src[e], d = dst[e];
    int p = atomicAdd(&g_cursor[d], 1);
    g_esrc[p]  = s;
    g_enorm[p] = g_dinv[s] * g_dinv[d];
}

// ---------------- GCN gather (one warp per node, fp16 source rows) ----------------
__device__ __forceinline__ void acc_row(const uint4 v, float wgt, float* a) {
    float2 f0 = __half22float2(*(const __half2*)&v.x);
    float2 f1 = __half22float2(*(const __half2*)&v.y);
    float2 f2 = __half22float2(*(const __half2*)&v.z);
    float2 f3 = __half22float2(*(const __half2*)&v.w);
    a[0] = fmaf(wgt, f0.x, a[0]); a[1] = fmaf(wgt, f0.y, a[1]);
    a[2] = fmaf(wgt, f1.x, a[2]); a[3] = fmaf(wgt, f1.y, a[3]);
    a[4] = fmaf(wgt, f2.x, a[4]); a[5] = fmaf(wgt, f2.y, a[5]);
    a[6] = fmaf(wgt, f3.x, a[6]); a[7] = fmaf(wgt, f3.y, a[7]);
}

template<bool RELU>
__global__ void __launch_bounds__(256) gcn_gather(const float* __restrict__ bias,
                                                  float* __restrict__ out) {
    const int node = blockIdx.x * 8 + (threadIdx.x >> 5);
    const int lane = threadIdx.x & 31;
    const int beg = g_rowptr[node], end = g_rowptr[node+1];

    float a[8] = {};
    int i = beg;
    for (; i + 2 <= end; i += 2) {
        int s0i = g_esrc[i],   s1i = g_esrc[i+1];
        float w0 = g_enorm[i], w1 = g_enorm[i+1];
        uint4 x = *((const uint4*)(g_tmpH + (size_t)s0i*HH) + lane);
        uint4 y = *((const uint4*)(g_tmpH + (size_t)s1i*HH) + lane);
        acc_row(x, w0, a);
        acc_row(y, w1, a);
    }
    if (i < end) {
        uint4 x = *((const uint4*)(g_tmpH + (size_t)g_esrc[i]*HH) + lane);
        acc_row(x, g_enorm[i], a);
    }
    float di = g_dinv[node];
    float sw = di * di;
    uint4 sv = *((const uint4*)(g_tmpH + (size_t)node*HH) + lane);
    acc_row(sv, sw, a);

    const float4* bp = (const float4*)(bias + lane*8);
    float4 b0 = bp[0], b1 = bp[1];
    float o0 = a[0] + b0.x, o1 = a[1] + b0.y, o2 = a[2] + b0.z, o3 = a[3] + b0.w;
    float o4 = a[4] + b1.x, o5 = a[5] + b1.y, o6 = a[6] + b1.z, o7 = a[7] + b1.w;
    if (RELU) {
        o0 = fmaxf(o0,0.f); o1 = fmaxf(o1,0.f); o2 = fmaxf(o2,0.f); o3 = fmaxf(o3,0.f);
        o4 = fmaxf(o4,0.f); o5 = fmaxf(o5,0.f); o6 = fmaxf(o6,0.f); o7 = fmaxf(o7,0.f);
    }
    float4* op = (float4*)(out + (size_t)node*HH + lane*8);
    op[0] = make_float4(o0,o1,o2,o3);
    op[1] = make_float4(o4,o5,o6,o7);
}

// ---------------- flash attention: 256-query tiles, bf16 QK, fp16 softmax/PV ------
// grid (NN/256, 8), block 256. Each warp owns two 16-row Q fragments (qh=0,1).
__global__ void __launch_bounds__(256) flash_attn_bf16() {
    __shared__ __align__(16) char Ks[3][64*80];
    __shared__ __align__(16) char Vs[3][32*144];

    const int head = blockIdx.y;
    const int q0   = blockIdx.x * 256;
    const int tid  = threadIdx.x;
    const int w    = tid >> 5, lane = tid & 31;
    const int g    = lane >> 2, t = lane & 3;
    const int KT   = NN / 64;
    const uint32_t ONES2 = 0x3C003C00u;   // half2(1,1)

    const __nv_bfloat16* kg = g_Kb + (size_t)head*NN*32;
    const __half*        vg = g_Vh + (size_t)head*32*NN;

    const int kr8 = tid >> 2, kc8 = (tid & 3) * 8;
    const int vd  = tid >> 3, vk8 = (tid & 7) * 8;

    cp_async16(&Ks[0][kr8*80 + kc8*2], kg + (size_t)kr8*32 + kc8);
    cp_async16(&Vs[0][vd*144 + vk8*2], vg + (size_t)vd*NN + vk8);
    CP_COMMIT();
    cp_async16(&Ks[1][kr8*80 + kc8*2], kg + (size_t)(64 + kr8)*32 + kc8);
    cp_async16(&Vs[1][vd*144 + vk8*2], vg + (size_t)vd*NN + 64 + vk8);
    CP_COMMIT();

    uint32_t aq[2][2][4];
    #pragma unroll
    for (int qh = 0; qh < 2; qh++) {
        const __nv_bfloat16* qb = g_Qb + ((size_t)head*NN + q0 + qh*128 + w*16) * 32;
        #pragma unroll
        for (int ks = 0; ks < 2; ks++) {
            int c = ks*16 + 2*t;
            aq[qh][ks][0] = *(const uint32_t*)(qb + (size_t)(g  )*32 + c);
            aq[qh][ks][1] = *(const uint32_t*)(qb + (size_t)(g+8)*32 + c);
            aq[qh][ks][2] = *(const uint32_t*)(qb + (size_t)(g  )*32 + c + 8);
            aq[qh][ks][3] = *(const uint32_t*)(qb + (size_t)(g+8)*32 + c + 8);
        }
    }

    float m[2][2];
    m[0][0] = m[0][1] = m[1][0] = m[1][1] = -1e30f;
    float o[2][4][4] = {};
    float lacc[2][4] = {};

    for (int kt = 0; kt < KT; kt++) {
        const int st = kt % 3;
        if (kt + 1 < KT) { CP_WAIT(1); } else { CP_WAIT(0); }
        __syncthreads();
        if (kt + 2 < KT) {
            const int sp = (kt + 2) % 3;
            cp_async16(&Ks[sp][kr8*80 + kc8*2], kg + (size_t)((kt+2)*64 + kr8)*32 + kc8);
            cp_async16(&Vs[sp][vd*144 + vk8*2], vg + (size_t)vd*NN + (kt+2)*64 + vk8);
            CP_COMMIT();
        }

        #pragma unroll
        for (int qh = 0; qh < 2; qh++) {
            float s[8][4];
            #pragma unroll
            for (int nb = 0; nb < 8; nb++) {
                s[nb][0] = s[nb][1] = s[nb][2] = s[nb][3] = 0.f;
                const char* kr = Ks[st] + (nb*8 + g)*80;
                uint32_t b0 = *(const uint32_t*)(kr + (2*t)*2);
                uint32_t b1 = *(const uint32_t*)(kr + (2*t+8)*2);
                mma_bf16(s[nb], aq[qh][0], b0, b1);
                b0 = *(const uint32_t*)(kr + (16 + 2*t)*2);
                b1 = *(const uint32_t*)(kr + (16 + 2*t+8)*2);
                mma_bf16(s[nb], aq[qh][1], b0, b1);
            }

            float tm0 = -1e30f, tm1 = -1e30f;
            #pragma unroll
            for (int nb = 0; nb < 8; nb++) {
                tm0 = fmaxf(tm0, fmaxf(s[nb][0], s[nb][1]));
                tm1 = fmaxf(tm1, fmaxf(s[nb][2], s[nb][3]));
            }
            tm0 = fmaxf(tm0, __shfl_xor_sync(0xffffffffu, tm0, 1));
            tm0 = fmaxf(tm0, __shfl_xor_sync(0xffffffffu, tm0, 2));
            tm1 = fmaxf(tm1, __shfl_xor_sync(0xffffffffu, tm1, 1));
            tm1 = fmaxf(tm1, __shfl_xor_sync(0xffffffffu, tm1, 2));
            float nm0 = fmaxf(m[qh][0], tm0), nm1 = fmaxf(m[qh][1], tm1);
            float al0 = exp2f(m[qh][0] - nm0), al1 = exp2f(m[qh][1] - nm1);
            m[qh][0] = nm0; m[qh][1] = nm1;

            __half2 p01[8], p23[8];
            #pragma unroll
            for (int nb = 0; nb < 8; nb++) {
                p01[nb] = h2exp2(__floats2half2_rn(s[nb][0] - nm0, s[nb][1] - nm0));
                p23[nb] = h2exp2(__floats2half2_rn(s[nb][2] - nm1, s[nb][3] - nm1));
            }

            #pragma unroll
            for (int nbv = 0; nbv < 4; nbv++) {
                o[qh][nbv][0] *= al0; o[qh][nbv][1] *= al0;
                o[qh][nbv][2] *= al1; o[qh][nbv][3] *= al1;
            }
            lacc[qh][0] *= al0; lacc[qh][1] *= al0;
            lacc[qh][2] *= al1; lacc[qh][3] *= al1;

            uint32_t ap[4][4];
            #pragma unroll
            for (int s4 = 0; s4 < 4; s4++) {
                ap[s4][0] = *(const uint32_t*)&p01[2*s4];
                ap[s4][1] = *(const uint32_t*)&p23[2*s4];
                ap[s4][2] = *(const uint32_t*)&p01[2*s4+1];
                ap[s4][3] = *(const uint32_t*)&p23[2*s4+1];
            }

            #pragma unroll
            for (int s4 = 0; s4 < 4; s4++) {
                mma_f16(lacc[qh], ap[s4], ONES2, ONES2);
                #pragma unroll
                for (int nbv = 0; nbv < 4; nbv++) {
                    const char* vr = Vs[st] + (nbv*8 + g)*144;
                    uint32_t b0 = *(const uint32_t*)(vr + (16*s4 + 2*t)*2);
                    uint32_t b1 = *(const uint32_t*)(vr + (16*s4 + 2*t + 8)*2);
                    mma_f16(o[qh][nbv], ap[s4], b0, b1);
                }
            }
        }
    }

    #pragma unroll
    for (int qh = 0; qh < 2; qh++) {
        float inv0 = 1.0f / lacc[qh][0], inv1 = 1.0f / lacc[qh][2];
        int row0 = q0 + qh*128 + w*16 + g;
        #pragma unroll
        for (int nbv = 0; nbv < 4; nbv++) {
            int col = head*32 + nbv*8 + 2*t;
            *(float2*)(g_attn + (size_t)row0*HH + col)     = make_float2(o[qh][nbv][0]*inv0, o[qh][nbv][1]*inv0);
            *(float2*)(g_attn + (size_t)(row0+8)*HH + col) = make_float2(o[qh][nbv][2]*inv1, o[qh][nbv][3]*inv1);
        }
    }
}

// ---------------- fused output heads (warp per node: softmax3 + sigmoid10) --------
__global__ void __launch_bounds__(256) head_both(const float* __restrict__ W3,
                                                 const float* __restrict__ b3v,
                                                 const float* __restrict__ W10,
                                                 const float* __restrict__ b10,
                                                 float* __restrict__ out) {
    const int node = blockIdx.x * 8 + (threadIdx.x >> 5);
    const int lane = threadIdx.x & 31;

    float4 hv = *(const float4*)(g_hid + (size_t)node*128 + lane*4);
    float lg3[3];
    #pragma unroll
    for (int c = 0; c < 3; c++) {
        float4 wv = *(const float4*)(W3 + c*128 + lane*4);
        float d = hv.x*wv.x + hv.y*wv.y + hv.z*wv.z + hv.w*wv.w;
        #pragma unroll
        for (int m = 16; m >= 1; m >>= 1) d += __shfl_xor_sync(0xffffffffu, d, m);
        lg3[c] = d + b3v[c];
    }
    float4 hv2 = *(const float4*)(g_hid2 + (size_t)node*128 + lane*4);
    float lg10[10];
    #pragma unroll
    for (int c = 0; c < 10; c++) {
        float4 wv = *(const float4*)(W10 + c*128 + lane*4);
        float d = hv2.x*wv.x + hv2.y*wv.y + hv2.z*wv.z + hv2.w*wv.w;
        #pragma unroll
        for (int m = 16; m >= 1; m >>= 1) d += __shfl_xor_sync(0xffffffffu, d, m);
        lg10[c] = d + b10[c];
    }
    if (lane == 0) {
        float mx = fmaxf(fmaxf(lg3[0], lg3[1]), lg3[2]);
        float e0 = __expf(lg3[0]-mx), e1 = __expf(lg3[1]-mx), e2 = __expf(lg3[2]-mx);
        float inv = 1.0f / (e0 + e1 + e2);
        out[(size_t)node*3 + 0] = e0*inv;
        out[(size_t)node*3 + 1] = e1*inv;
        out[(size_t)node*3 + 2] = e2*inv;
        float* o2 = out + (size_t)NN*3 + (size_t)node*10;
        #pragma unroll
        for (int c = 0; c < 10; c++)
            o2[c] = 1.0f / (1.0f + __expf(-lg10[c]));
    }
}

// ---------------- launch ---------------------------------------------------------
extern "C" void kernel_launch(void* const* d_in, const int* in_sizes, int n_in,
                              void* d_out, int out_size)
{
    const float* x     = (const float*)d_in[0];
    const int*   ei    = (const int*)  d_in[1];
    const float* W1    = (const float*)d_in[2];
    const float* b1    = (const float*)d_in[3];
    const float* W2    = (const float*)d_in[4];
    const float* b2    = (const float*)d_in[5];
    const float* W3    = (const float*)d_in[6];
    const float* b3    = (const float*)d_in[7];
    const float* in_w  = (const float*)d_in[8];
    const float* in_b  = (const float*)d_in[9];
    const float* out_w = (const float*)d_in[10];
    const float* out_b = (const float*)d_in[11];
    const float* fp1w  = (const float*)d_in[12];
    const float* fp1b  = (const float*)d_in[13];
    const float* fp2w  = (const float*)d_in[14];
    const float* fp2b  = (const float*)d_in[15];
    const float* pd1w  = (const float*)d_in[16];
    const float* pd1b  = (const float*)d_in[17];
    const float* pd2w  = (const float*)d_in[18];
    const float* pd2b  = (const float*)d_in[19];
    const int* src = ei;
    const int* dst = ei + EE;
    float* outp = (float*)d_out;

    void *tmph;
    float *h, *h3, *deg, *attn, *hid, *hid2;
    cudaGetSymbolAddress((void**)&tmph, g_tmpH);
    cudaGetSymbolAddress((void**)&h,    g_h);
    cudaGetSymbolAddress((void**)&h3,   g_h3);
    cudaGetSymbolAddress((void**)&deg,  g_deg);
    cudaGetSymbolAddress((void**)&attn, g_attn);
    cudaGetSymbolAddress((void**)&hid,  g_hid);
    cudaGetSymbolAddress((void**)&hid2, g_hid2);

    static cudaStream_t s2 = nullptr;
    static cudaEvent_t evF = nullptr, evJ = nullptr;
    if (!s2) {
        cudaStreamCreateWithFlags(&s2, cudaStreamNonBlocking);
        cudaEventCreateWithFlags(&evF, cudaEventDisableTiming);
        cudaEventCreateWithFlags(&evJ, cudaEventDisableTiming);
    }

    const dim3 blk(256);

    // Fork: CSR build on s2  ||  GEMM1 on main stream
    cudaEventRecord(evF, 0);
    cudaStreamWaitEvent(s2, evF, 0);
    cudaMemsetAsync(deg, 0, NN * sizeof(float), s2);
    deg_count<<<EE/256, 256, 0, s2>>>(dst);
    scan_rowptr<<<1, 1024, 0, s2>>>();
    csr_scatter<<<EE/256, 256, 0, s2>>>(src, dst);
    cudaEventRecord(evJ, s2);

    gemm_tf32<false,false,false,false,false,true><<<dim3(4,32), blk>>>(
        x, W1, nullptr, nullptr, nullptr, nullptr, tmph, nullptr, NN, HH, 128);
    cudaStreamWaitEvent(0, evJ, 0);     // join before first gather

    gcn_gather<true><<<NN/8, blk>>>(b1, h);
    gemm_tf32<false,false,false,false,false,true><<<dim3(4,32), blk>>>(
        h, W2, nullptr, nullptr, nullptr, nullptr, tmph, nullptr, NN, HH, HH);
    gcn_gather<true><<<NN/8, blk>>>(b2, h);
    gemm_tf32<false,false,false,false,false,true><<<dim3(4,32), blk>>>(
        h, W3, nullptr, nullptr, nullptr, nullptr, tmph, nullptr, NN, HH, HH);
    gcn_gather<false><<<NN/8, blk>>>(b3, h3);

    // MHA: fused QKV gemm -> (g_Qb, g_Kb, g_Vh); flash attention (256-row tiles)
    gemm_tf32<true,false,false,true,false,false><<<dim3(12,32), blk>>>(
        h3, in_w, nullptr, in_b, nullptr, nullptr, nullptr, nullptr, NN, 3*HH, HH);
    flash_attn_bf16<<<dim3(NN/256, 8), blk>>>();
    gemm_tf32<true,false,true,false,false,false><<<dim3(4,32), blk>>>(
        attn, out_w, nullptr, out_b, nullptr, h3, h, nullptr, NN, HH, HH);

    // Fused dual-head GEMM + fused heads
    gemm_tf32<true,true,false,false,true,false><<<dim3(4,32), blk>>>(
        h, fp1w, pd1w, fp1b, pd1b, nullptr, hid, hid2, NN, 128, HH);
    head_both<<<NN/8, blk>>>(fp2w, fp2b, pd2w, pd2b, outp);
}

// round 13
// speedup vs baseline: 1.2377x; 1.0593x over previous
#include <cuda_runtime.h>
#include <cuda_bf16.h>
#include <cuda_fp16.h>
#include <cstdint>
#include <math.h>

#define NN 4096
#define EE 131072
#define HH 256

#define QSCALE_F (0.17677669529663687f * 1.4426950408889634f)

// ---------------- scratch (static device globals; no allocation) ----------------
__device__ __half g_tmpH[NN*HH];     // h @ W, fp16 (pre-aggregation)
__device__ __half g_hH  [NN*HH];     // activation (fp16 GEMM input)
__device__ __half g_h3H [NN*HH];     // h3 fp16 (QKV GEMM input)
__device__ float  g_h3  [NN*HH];     // h3 fp32 (residual SRC)
__device__ __half g_attnH[NN*HH];    // attention output fp16
__device__ float g_deg [NN];
__device__ float g_dinv[NN];
__device__ float g_hid [NN*128];
__device__ float g_hid2[NN*128];
__device__ int   g_rowptr[NN+1];
__device__ int   g_cursor[NN];
__device__ int   g_esrc [EE];
__device__ float g_enorm[EE];
__device__ __nv_bfloat16 g_Qb[8*NN*32];   // [h][n][d], pre-scaled by 1/sqrt(32)*log2e
__device__ __nv_bfloat16 g_Kb[8*NN*32];   // [h][n][d]
__device__ __half        g_Vh[8*32*NN];   // [h][d][n]  (transposed, fp16)
// fp16 operand copies (built once per launch, overlapped)
__device__ __half g_xH  [NN*128];
__device__ __half g_W1t [256*128];        // [N,K]
__device__ __half g_W2t [256*256];
__device__ __half g_W3t [256*256];
__device__ __half g_inwH[768*256];
__device__ __half g_outwH[256*256];
__device__ __half g_fp1H[128*256];
__device__ __half g_pd1H[128*256];

// ---------------- async-copy helpers ---------------------------------------------
__device__ __forceinline__ void cp_async16(void* smem, const void* gmem) {
    uint32_t s = (uint32_t)__cvta_generic_to_shared(smem);
    asm volatile("cp.async.ca.shared.global [%0], [%1], 16;\n" :: "r"(s), "l"(gmem));
}
#define CP_COMMIT() asm volatile("cp.async.commit_group;\n" ::: "memory")
#define CP_WAIT(n)  asm volatile("cp.async.wait_group %0;\n" :: "n"(n) : "memory")

// ---------------- mma wrappers ----------------------------------------------------
__device__ __forceinline__ void mma_bf16(float* c, const uint32_t* a, uint32_t b0, uint32_t b1) {
    asm volatile(
        "mma.sync.aligned.m16n8k16.row.col.f32.bf16.bf16.f32 "
        "{%0,%1,%2,%3}, {%4,%5,%6,%7}, {%8,%9}, {%0,%1,%2,%3};\n"
        : "+f"(c[0]), "+f"(c[1]), "+f"(c[2]), "+f"(c[3])
        : "r"(a[0]), "r"(a[1]), "r"(a[2]), "r"(a[3]), "r"(b0), "r"(b1));
}
__device__ __forceinline__ void mma_f16(float* c, const uint32_t* a, uint32_t b0, uint32_t b1) {
    asm volatile(
        "mma.sync.aligned.m16n8k16.row.col.f32.f16.f16.f32 "
        "{%0,%1,%2,%3}, {%4,%5,%6,%7}, {%8,%9}, {%0,%1,%2,%3};\n"
        : "+f"(c[0]), "+f"(c[1]), "+f"(c[2]), "+f"(c[3])
        : "r"(a[0]), "r"(a[1]), "r"(a[2]), "r"(a[3]), "r"(b0), "r"(b1));
}
__device__ __forceinline__ uint32_t pack_bf16(float lo, float hi) {
    __nv_bfloat162 v = __floats2bfloat162_rn(lo, hi);
    return *(uint32_t*)&v;
}

// QKV epilogue store: n in [0,768). Block-uniform branch (64-col tiles).
__device__ __forceinline__ void store_qkv(int row, int n, float a, float b) {
    int d = n & 31;
    int hh = (n >> 5) & 7;
    if (n < 256) {
        *(uint32_t*)(g_Qb + ((size_t)hh*NN + row)*32 + d) = pack_bf16(a*QSCALE_F, b*QSCALE_F);
    } else if (n < 512) {
        *(uint32_t*)(g_Kb + ((size_t)hh*NN + row)*32 + d) = pack_bf16(a, b);
    } else {
        g_Vh[((size_t)hh*32 + d    )*NN + row] = __float2half(a);
        g_Vh[((size_t)hh*32 + d + 1)*NN + row] = __float2half(b);
    }
}

// ---------------- conversion kernels (once per launch, mostly overlapped) ---------
__global__ void cvt_elem(const float* __restrict__ in, __half* __restrict__ out, int n4) {
    int i = blockIdx.x * 256 + threadIdx.x;
    if (i < n4) {
        float4 v = ((const float4*)in)[i];
        __half2 a = __floats2half2_rn(v.x, v.y), b = __floats2half2_rn(v.z, v.w);
        ((uint2*)out)[i] = make_uint2(*(uint32_t*)&a, *(uint32_t*)&b);
    }
}
// out[n*K+k] = in[k*N+n], fp32 -> fp16.  grid (N/32, K/32), block 256.
__global__ void tr_w(const float* __restrict__ in, __half* __restrict__ out, int K, int N) {
    __shared__ float t[32][33];
    int n0 = blockIdx.x * 32, k0 = blockIdx.y * 32;
    int tx = threadIdx.x & 31, ty = threadIdx.x >> 5;
    #pragma unroll
    for (int i = ty; i < 32; i += 8)
        t[i][tx] = in[(size_t)(k0 + i)*N + n0 + tx];
    __syncthreads();
    #pragma unroll
    for (int i = ty; i < 32; i += 8)
        out[(size_t)(n0 + i)*K + k0 + tx] = __float2half(t[tx][i]);
}
// convert the four [N,K]-layout weights elementwise
__global__ void cvt4(const float* w1, __half* o1, const float* w2, __half* o2,
                     const float* w3, __half* o3, const float* w4, __half* o4) {
    const int N1 = 768*256, N2 = 256*256, N3 = 128*256, N4 = 128*256;
    int i = blockIdx.x * 256 + threadIdx.x;
    if (i < N1) { o1[i] = __float2half(w1[i]); }
    if (i < N2) { o2[i] = __float2half(w2[i]); }
    if (i < N3) { o3[i] = __float2half(w3[i]); o4[i] = __float2half(w4[i]); }
}

// ---------------- pipelined fp16 GEMM (128x64, 3-stage ring, TRANSB always) -------
// C[M,N] = A[M,K] @ Bt[N,K]^T (+bias)(+SRC fp32)(relu).
// QKV: epilogue -> g_Qb/g_Kb/g_Vh.  DUALB: blockIdx.x>=2 uses Bt2/bias2/C2.
// OUTH: C is __half*, else float*.
template<bool RELU, bool ADDSRC, bool QKV, bool DUALB, bool OUTH>
__global__ void __launch_bounds__(256) gemm_f16(
    const __half* __restrict__ A, const __half* __restrict__ Bt,
    const __half* __restrict__ Bt2, const float* __restrict__ bias,
    const float* __restrict__ bias2, const float* __restrict__ SRC,
    void* __restrict__ Cv, void* __restrict__ C2v, int M, int N, int K)
{
    __shared__ __half As[3][128*24];    // [m][k], stride 24 halves (conflict-free)
    __shared__ __half Bs[3][64*24];

    const int tid  = threadIdx.x;
    const int w    = tid >> 5, lane = tid & 31;
    const int g    = lane >> 2, t = lane & 3;
    const int wm   = w & 3, wn = w >> 2;
    const int m0   = blockIdx.y * 128;
    void* Cuse = Cv;
    int n0;
    if (DUALB) {
        n0 = (blockIdx.x & 1) * 64;
        if (blockIdx.x >= 2) { Bt = Bt2; bias = bias2; Cuse = C2v; }
    } else {
        n0 = blockIdx.x * 64;
    }
    const int KT = K >> 4;

    const int arow = tid >> 1, ac8 = (tid & 1) * 8;    // A: 128 rows x 2 chunks
    const int brow = tid >> 1, bc8 = (tid & 1) * 8;    // B: 64 rows x 2 chunks (tid<128)

    float acc[2][4][4] = {};

    #pragma unroll
    for (int p = 0; p < 2; p++) {
        const int k0 = p << 4;
        cp_async16(&As[p][arow*24 + ac8], A + (size_t)(m0 + arow)*K + k0 + ac8);
        if (tid < 128)
            cp_async16(&Bs[p][brow*24 + bc8], Bt + (size_t)(n0 + brow)*K + k0 + bc8);
        CP_COMMIT();
    }

    for (int kt = 0; kt < KT; kt++) {
        const int st = kt % 3;
        if (kt + 1 < KT) { CP_WAIT(1); } else { CP_WAIT(0); }
        __syncthreads();
        if (kt + 2 < KT) {
            const int sp = (kt + 2) % 3;
            const int k0 = (kt + 2) << 4;
            cp_async16(&As[sp][arow*24 + ac8], A + (size_t)(m0 + arow)*K + k0 + ac8);
            if (tid < 128)
                cp_async16(&Bs[sp][brow*24 + bc8], Bt + (size_t)(n0 + brow)*K + k0 + bc8);
            CP_COMMIT();
        }

        const uint32_t* as = (const uint32_t*)As[st];   // 12 uint32 per row
        const uint32_t* bs = (const uint32_t*)Bs[st];
        uint32_t a[2][4];
        #pragma unroll
        for (int mt = 0; mt < 2; mt++) {
            int row = wm*32 + mt*16 + g;
            a[mt][0] = as[(row  )*12 + t];
            a[mt][1] = as[(row+8)*12 + t];
            a[mt][2] = as[(row  )*12 + t + 4];
            a[mt][3] = as[(row+8)*12 + t + 4];
        }
        #pragma unroll
        for (int nt = 0; nt < 4; nt++) {
            int n = wn*32 + nt*8 + g;
            uint32_t b0 = bs[n*12 + t];
            uint32_t b1 = bs[n*12 + t + 4];
            mma_f16(acc[0][nt], a[0], b0, b1);
            mma_f16(acc[1][nt], a[1], b0, b1);
        }
    }

    #pragma unroll
    for (int mt = 0; mt < 2; mt++) {
        const int r0 = m0 + wm*32 + mt*16 + g;
        #pragma unroll
        for (int nt = 0; nt < 4; nt++) {
            const int n = n0 + wn*32 + nt*8 + 2*t;
            float bb0 = bias ? bias[n] : 0.f;
            float bb1 = bias ? bias[n+1] : 0.f;
            float v00 = acc[mt][nt][0] + bb0, v01 = acc[mt][nt][1] + bb1;
            float v10 = acc[mt][nt][2] + bb0, v11 = acc[mt][nt][3] + bb1;
            if (ADDSRC) {
                v00 += SRC[(size_t)r0*N + n];     v01 += SRC[(size_t)r0*N + n + 1];
                v10 += SRC[(size_t)(r0+8)*N + n]; v11 += SRC[(size_t)(r0+8)*N + n + 1];
            }
            if (RELU) {
                v00 = fmaxf(v00, 0.f); v01 = fmaxf(v01, 0.f);
                v10 = fmaxf(v10, 0.f); v11 = fmaxf(v11, 0.f);
            }
            if (QKV) {
                store_qkv(r0,     n, v00, v01);
                store_qkv(r0 + 8, n, v10, v11);
            } else if (OUTH) {
                __half* C = (__half*)Cuse;
                __half2 h0 = __floats2half2_rn(v00, v01);
                __half2 h1 = __floats2half2_rn(v10, v11);
                *(uint32_t*)(C + (size_t)r0*N + n)     = *(uint32_t*)&h0;
                *(uint32_t*)(C + (size_t)(r0+8)*N + n) = *(uint32_t*)&h1;
            } else {
                float* C = (float*)Cuse;
                *(float2*)(C + (size_t)r0*N + n)     = make_float2(v00, v01);
                *(float2*)(C + (size_t)(r0+8)*N + n) = make_float2(v10, v11);
            }
        }
    }
}

// ---------------- graph preprocessing (CSR build) --------------------------------
__global__ void deg_count(const int* __restrict__ dst) {
    int e = blockIdx.x * 256 + threadIdx.x;
    if (e < EE) atomicAdd(&g_deg[dst[e]], 1.0f);
}

__global__ void __launch_bounds__(1024) scan_rowptr() {
    __shared__ int warpsum[32];
    const int tid = threadIdx.x;
    const int lane = tid & 31, wid = tid >> 5;
    const int base = tid * 4;
    int c[4], s = 0;
    #pragma unroll
    for (int j = 0; j < 4; j++) {
        c[j] = (int)g_deg[base + j];
        g_dinv[base + j] = rsqrtf((float)c[j] + 1.0f);
        s += c[j];
    }
    int pre = s;
    #pragma unroll
    for (int off = 1; off < 32; off <<= 1) {
        int v = __shfl_up_sync(0xffffffffu, pre, off);
        if (lane >= off) pre += v;
    }
    if (lane == 31) warpsum[wid] = pre;
    __syncthreads();
    if (wid == 0) {
        int v = warpsum[lane];
        #pragma unroll
        for (int off = 1; off < 32; off <<= 1) {
            int u = __shfl_up_sync(0xffffffffu, v, off);
            if (lane >= off) v += u;
        }
        warpsum[lane] = v;
    }
    __syncthreads();
    int excl = pre - s + (wid > 0 ? warpsum[wid-1] : 0);
    int run = excl;
    #pragma unroll
    for (int j = 0; j < 4; j++) {
        g_rowptr[base + j] = run;
        g_cursor[base + j] = run;
        run += c[j];
    }
    if (tid == 1023) g_rowptr[NN] = run;
}

__global__ void csr_scatter(const int* __restrict__ src, const int* __restrict__ dst) {
    int e = blockIdx.x * 256 + threadIdx.x;
    if (e >= EE) return;
    int s = src[e], d = dst[e];
    int p = atomicAdd(&g_cursor[d], 1);
    g_esrc[p]  = s;
    g_enorm[p] = g_dinv[s] * g_dinv[d];
}

// ---------------- GCN gather (fp16 in, fp16 out; H3 also writes fp32) -------------
__device__ __forceinline__ void acc_row(const uint4 v, float wgt, float* a) {
    float2 f0 = __half22float2(*(const __half2*)&v.x);
    float2 f1 = __half22float2(*(const __half2*)&v.y);
    float2 f2 = __half22float2(*(const __half2*)&v.z);
    float2 f3 = __half22float2(*(const __half2*)&v.w);
    a[0] = fmaf(wgt, f0.x, a[0]); a[1] = fmaf(wgt, f0.y, a[1]);
    a[2] = fmaf(wgt, f1.x, a[2]); a[3] = fmaf(wgt, f1.y, a[3]);
    a[4] = fmaf(wgt, f2.x, a[4]); a[5] = fmaf(wgt, f2.y, a[5]);
    a[6] = fmaf(wgt, f3.x, a[6]); a[7] = fmaf(wgt, f3.y, a[7]);
}

template<bool RELU, bool H3>
__global__ void __launch_bounds__(256) gcn_gather(const float* __restrict__ bias,
                                                  __half* __restrict__ outH,
                                                  float* __restrict__ outF) {
    const int node = blockIdx.x * 8 + (threadIdx.x >> 5);
    const int lane = threadIdx.x & 31;
    const int beg = g_rowptr[node], end = g_rowptr[node+1];

    float a[8] = {};
    int i = beg;
    for (; i + 2 <= end; i += 2) {
        int s0i = g_esrc[i],   s1i = g_esrc[i+1];
        float w0 = g_enorm[i], w1 = g_enorm[i+1];
        uint4 x = *((const uint4*)(g_tmpH + (size_t)s0i*HH) + lane);
        uint4 y = *((const uint4*)(g_tmpH + (size_t)s1i*HH) + lane);
        acc_row(x, w0, a);
        acc_row(y, w1, a);
    }
    if (i < end) {
        uint4 x = *((const uint4*)(g_tmpH + (size_t)g_esrc[i]*HH) + lane);
        acc_row(x, g_enorm[i], a);
    }
    float di = g_dinv[node];
    float sw = di * di;
    uint4 sv = *((const uint4*)(g_tmpH + (size_t)node*HH) + lane);
    acc_row(sv, sw, a);

    const float4* bp = (const float4*)(bias + lane*8);
    float4 b0 = bp[0], b1 = bp[1];
    float o0 = a[0] + b0.x, o1 = a[1] + b0.y, o2 = a[2] + b0.z, o3 = a[3] + b0.w;
    float o4 = a[4] + b1.x, o5 = a[5] + b1.y, o6 = a[6] + b1.z, o7 = a[7] + b1.w;
    if (RELU) {
        o0 = fmaxf(o0,0.f); o1 = fmaxf(o1,0.f); o2 = fmaxf(o2,0.f); o3 = fmaxf(o3,0.f);
        o4 = fmaxf(o4,0.f); o5 = fmaxf(o5,0.f); o6 = fmaxf(o6,0.f); o7 = fmaxf(o7,0.f);
    }
    __half2 ph0 = __floats2half2_rn(o0,o1), ph1 = __floats2half2_rn(o2,o3);
    __half2 ph2 = __floats2half2_rn(o4,o5), ph3 = __floats2half2_rn(o6,o7);
    *((uint4*)(outH + (size_t)node*HH) + lane) =
        make_uint4(*(uint32_t*)&ph0, *(uint32_t*)&ph1, *(uint32_t*)&ph2, *(uint32_t*)&ph3);
    if (H3) {
        float4* op = (float4*)(outF + (size_t)node*HH + lane*8);
        op[0] = make_float4(o0,o1,o2,o3);
        op[1] = make_float4(o4,o5,o6,o7);
    }
}

// ---------------- flash attention: 256-query tiles, bf16 QK, fp16 softmax/PV ------
__global__ void __launch_bounds__(256) flash_attn_bf16() {
    __shared__ __align__(16) char Ks[3][64*80];
    __shared__ __align__(16) char Vs[3][32*144];

    const int head = blockIdx.y;
    const int q0   = blockIdx.x * 256;
    const int tid  = threadIdx.x;
    const int w    = tid >> 5, lane = tid & 31;
    const int g    = lane >> 2, t = lane & 3;
    const int KT   = NN / 64;
    const uint32_t ONES2 = 0x3C003C00u;

    const __nv_bfloat16* kg = g_Kb + (size_t)head*NN*32;
    const __half*        vg = g_Vh + (size_t)head*32*NN;

    const int kr8 = tid >> 2, kc8 = (tid & 3) * 8;
    const int vd  = tid >> 3, vk8 = (tid & 7) * 8;

    cp_async16(&Ks[0][kr8*80 + kc8*2], kg + (size_t)kr8*32 + kc8);
    cp_async16(&Vs[0][vd*144 + vk8*2], vg + (size_t)vd*NN + vk8);
    CP_COMMIT();
    cp_async16(&Ks[1][kr8*80 + kc8*2], kg + (size_t)(64 + kr8)*32 + kc8);
    cp_async16(&Vs[1][vd*144 + vk8*2], vg + (size_t)vd*NN + 64 + vk8);
    CP_COMMIT();

    uint32_t aq[2][2][4];
    #pragma unroll
    for (int qh = 0; qh < 2; qh++) {
        const __nv_bfloat16* qb = g_Qb + ((size_t)head*NN + q0 + qh*128 + w*16) * 32;
        #pragma unroll
        for (int ks = 0; ks < 2; ks++) {
            int c = ks*16 + 2*t;
            aq[qh][ks][0] = *(const uint32_t*)(qb + (size_t)(g  )*32 + c);
            aq[qh][ks][1] = *(const uint32_t*)(qb + (size_t)(g+8)*32 + c);
            aq[qh][ks][2] = *(const uint32_t*)(qb + (size_t)(g  )*32 + c + 8);
            aq[qh][ks][3] = *(const uint32_t*)(qb + (size_t)(g+8)*32 + c + 8);
        }
    }

    float m[2][2];
    m[0][0] = m[0][1] = m[1][0] = m[1][1] = -1e30f;
    float o[2][4][4] = {};
    float lacc[2][4] = {};

    for (int kt = 0; kt < KT; kt++) {
        const int st = kt % 3;
        if (kt + 1 < KT) { CP_WAIT(1); } else { CP_WAIT(0); }
        __syncthreads();
        if (kt + 2 < KT) {
            const int sp = (kt + 2) % 3;
            cp_async16(&Ks[sp][kr8*80 + kc8*2], kg + (size_t)((kt+2)*64 + kr8)*32 + kc8);
            cp_async16(&Vs[sp][vd*144 + vk8*2], vg + (size_t)vd*NN + (kt+2)*64 + vk8);
            CP_COMMIT();
        }

        #pragma unroll
        for (int qh = 0; qh < 2; qh++) {
            float s[8][4];
            #pragma unroll
            for (int nb = 0; nb < 8; nb++) {
                s[nb][0] = s[nb][1] = s[nb][2] = s[nb][3] = 0.f;
                const char* kr = Ks[st] + (nb*8 + g)*80;
                uint32_t b0 = *(const uint32_t*)(kr + (2*t)*2);
                uint32_t b1 = *(const uint32_t*)(kr + (2*t+8)*2);
                mma_bf16(s[nb], aq[qh][0], b0, b1);
                b0 = *(const uint32_t*)(kr + (16 + 2*t)*2);
                b1 = *(const uint32_t*)(kr + (16 + 2*t+8)*2);
                mma_bf16(s[nb], aq[qh][1], b0, b1);
            }

            float tm0 = -1e30f, tm1 = -1e30f;
            #pragma unroll
            for (int nb = 0; nb < 8; nb++) {
                tm0 = fmaxf(tm0, fmaxf(s[nb][0], s[nb][1]));
                tm1 = fmaxf(tm1, fmaxf(s[nb][2], s[nb][3]));
            }
            tm0 = fmaxf(tm0, __shfl_xor_sync(0xffffffffu, tm0, 1));
            tm0 = fmaxf(tm0, __shfl_xor_sync(0xffffffffu, tm0, 2));
            tm1 = fmaxf(tm1, __shfl_xor_sync(0xffffffffu, tm1, 1));
            tm1 = fmaxf(tm1, __shfl_xor_sync(0xffffffffu, tm1, 2));
            float nm0 = fmaxf(m[qh][0], tm0), nm1 = fmaxf(m[qh][1], tm1);
            float al0 = exp2f(m[qh][0] - nm0), al1 = exp2f(m[qh][1] - nm1);
            m[qh][0] = nm0; m[qh][1] = nm1;

            __half2 p01[8], p23[8];
            #pragma unroll
            for (int nb = 0; nb < 8; nb++) {
                p01[nb] = h2exp2(__floats2half2_rn(s[nb][0] - nm0, s[nb][1] - nm0));
                p23[nb] = h2exp2(__floats2half2_rn(s[nb][2] - nm1, s[nb][3] - nm1));
            }

            #pragma unroll
            for (int nbv = 0; nbv < 4; nbv++) {
                o[qh][nbv][0] *= al0; o[qh][nbv][1] *= al0;
                o[qh][nbv][2] *= al1; o[qh][nbv][3] *= al1;
            }
            lacc[qh][0] *= al0; lacc[qh][1] *= al0;
            lacc[qh][2] *= al1; lacc[qh][3] *= al1;

            uint32_t ap[4][4];
            #pragma unroll
            for (int s4 = 0; s4 < 4; s4++) {
                ap[s4][0] = *(const uint32_t*)&p01[2*s4];
                ap[s4][1] = *(const uint32_t*)&p23[2*s4];
                ap[s4][2] = *(const uint32_t*)&p01[2*s4+1];
                ap[s4][3] = *(const uint32_t*)&p23[2*s4+1];
            }

            #pragma unroll
            for (int s4 = 0; s4 < 4; s4++) {
                mma_f16(lacc[qh], ap[s4], ONES2, ONES2);
                #pragma unroll
                for (int nbv = 0; nbv < 4; nbv++) {
                    const char* vr = Vs[st] + (nbv*8 + g)*144;
                    uint32_t b0 = *(const uint32_t*)(vr + (16*s4 + 2*t)*2);
                    uint32_t b1 = *(const uint32_t*)(vr + (16*s4 + 2*t + 8)*2);
                    mma_f16(o[qh][nbv], ap[s4], b0, b1);
                }
            }
        }
    }

    #pragma unroll
    for (int qh = 0; qh < 2; qh++) {
        float inv0 = 1.0f / lacc[qh][0], inv1 = 1.0f / lacc[qh][2];
        int row0 = q0 + qh*128 + w*16 + g;
        #pragma unroll
        for (int nbv = 0; nbv < 4; nbv++) {
            int col = head*32 + nbv*8 + 2*t;
            __half2 h0 = __floats2half2_rn(o[qh][nbv][0]*inv0, o[qh][nbv][1]*inv0);
            __half2 h1 = __floats2half2_rn(o[qh][nbv][2]*inv1, o[qh][nbv][3]*inv1);
            *(uint32_t*)(g_attnH + (size_t)row0*HH + col)     = *(uint32_t*)&h0;
            *(uint32_t*)(g_attnH + (size_t)(row0+8)*HH + col) = *(uint32_t*)&h1;
        }
    }
}

// ---------------- fused output heads (warp per node: softmax3 + sigmoid10) --------
__global__ void __launch_bounds__(256) head_both(const float* __restrict__ W3,
                                                 const float* __restrict__ b3v,
                                                 const float* __restrict__ W10,
                                                 const float* __restrict__ b10,
                                                 float* __restrict__ out) {
    const int node = blockIdx.x * 8 + (threadIdx.x >> 5);
    const int lane = threadIdx.x & 31;

    float4 hv = *(const float4*)(g_hid + (size_t)node*128 + lane*4);
    float lg3[3];
    #pragma unroll
    for (int c = 0; c < 3; c++) {
        float4 wv = *(const float4*)(W3 + c*128 + lane*4);
        float d = hv.x*wv.x + hv.y*wv.y + hv.z*wv.z + hv.w*wv.w;
        #pragma unroll
        for (int m = 16; m >= 1; m >>= 1) d += __shfl_xor_sync(0xffffffffu, d, m);
        lg3[c] = d + b3v[c];
    }
    float4 hv2 = *(const float4*)(g_hid2 + (size_t)node*128 + lane*4);
    float lg10[10];
    #pragma unroll
    for (int c = 0; c < 10; c++) {
        float4 wv = *(const float4*)(W10 + c*128 + lane*4);
        float d = hv2.x*wv.x + hv2.y*wv.y + hv2.z*wv.z + hv2.w*wv.w;
        #pragma unroll
        for (int m = 16; m >= 1; m >>= 1) d += __shfl_xor_sync(0xffffffffu, d, m);
        lg10[c] = d + b10[c];
    }
    if (lane == 0) {
        float mx = fmaxf(fmaxf(lg3[0], lg3[1]), lg3[2]);
        float e0 = __expf(lg3[0]-mx), e1 = __expf(lg3[1]-mx), e2 = __expf(lg3[2]-mx);
        float inv = 1.0f / (e0 + e1 + e2);
        out[(size_t)node*3 + 0] = e0*inv;
        out[(size_t)node*3 + 1] = e1*inv;
        out[(size_t)node*3 + 2] = e2*inv;
        float* o2 = out + (size_t)NN*3 + (size_t)node*10;
        #pragma unroll
        for (int c = 0; c < 10; c++)
            o2[c] = 1.0f / (1.0f + __expf(-lg10[c]));
    }
}

// ---------------- launch ---------------------------------------------------------
extern "C" void kernel_launch(void* const* d_in, const int* in_sizes, int n_in,
                              void* d_out, int out_size)
{
    const float* x     = (const float*)d_in[0];
    const int*   ei    = (const int*)  d_in[1];
    const float* W1    = (const float*)d_in[2];
    const float* b1    = (const float*)d_in[3];
    const float* W2    = (const float*)d_in[4];
    const float* b2    = (const float*)d_in[5];
    const float* W3    = (const float*)d_in[6];
    const float* b3    = (const float*)d_in[7];
    const float* in_w  = (const float*)d_in[8];
    const float* in_b  = (const float*)d_in[9];
    const float* out_w = (const float*)d_in[10];
    const float* out_b = (const float*)d_in[11];
    const float* fp1w  = (const float*)d_in[12];
    const float* fp1b  = (const float*)d_in[13];
    const float* fp2w  = (const float*)d_in[14];
    const float* fp2b  = (const float*)d_in[15];
    const float* pd1w  = (const float*)d_in[16];
    const float* pd1b  = (const float*)d_in[17];
    const float* pd2w  = (const float*)d_in[18];
    const float* pd2b  = (const float*)d_in[19];
    const int* src = ei;
    const int* dst = ei + EE;
    float* outp = (float*)d_out;

    void *tmph, *hh, *h3h, *attnh, *xh, *w1t, *w2t, *w3t, *inwh, *outwh, *fp1h, *pd1h;
    float *h3, *deg, *hid, *hid2;
    cudaGetSymbolAddress((void**)&tmph,  g_tmpH);
    cudaGetSymbolAddress((void**)&hh,    g_hH);
    cudaGetSymbolAddress((void**)&h3h,   g_h3H);
    cudaGetSymbolAddress((void**)&h3,    g_h3);
    cudaGetSymbolAddress((void**)&attnh, g_attnH);
    cudaGetSymbolAddress((void**)&deg,   g_deg);
    cudaGetSymbolAddress((void**)&hid,   g_hid);
    cudaGetSymbolAddress((void**)&hid2,  g_hid2);
    cudaGetSymbolAddress((void**)&xh,    g_xH);
    cudaGetSymbolAddress((void**)&w1t,   g_W1t);
    cudaGetSymbolAddress((void**)&w2t,   g_W2t);
    cudaGetSymbolAddress((void**)&w3t,   g_W3t);
    cudaGetSymbolAddress((void**)&inwh,  g_inwH);
    cudaGetSymbolAddress((void**)&outwh, g_outwH);
    cudaGetSymbolAddress((void**)&fp1h,  g_fp1H);
    cudaGetSymbolAddress((void**)&pd1h,  g_pd1H);

    static cudaStream_t s2 = nullptr;
    static cudaEvent_t evF = nullptr, evJ = nullptr;
    if (!s2) {
        cudaStreamCreateWithFlags(&s2, cudaStreamNonBlocking);
        cudaEventCreateWithFlags(&evF, cudaEventDisableTiming);
        cudaEventCreateWithFlags(&evJ, cudaEventDisableTiming);
    }

    const dim3 blk(256);

    // Fork: conversions + CSR build on s2  ||  x/W1 conversion + GEMM1 on main
    cudaEventRecord(evF, 0);
    cudaStreamWaitEvent(s2, evF, 0);
    tr_w<<<dim3(8,8), blk, 0, s2>>>(W2, (__half*)w2t, 256, 256);
    tr_w<<<dim3(8,8), blk, 0, s2>>>(W3, (__half*)w3t, 256, 256);
    cvt4<<<768, blk, 0, s2>>>(in_w, (__half*)inwh, out_w, (__half*)outwh,
                              fp1w, (__half*)fp1h, pd1w, (__half*)pd1h);
    cudaMemsetAsync(deg, 0, NN * sizeof(float), s2);
    deg_count<<<EE/256, 256, 0, s2>>>(dst);
    scan_rowptr<<<1, 1024, 0, s2>>>();
    csr_scatter<<<EE/256, 256, 0, s2>>>(src, dst);
    cudaEventRecord(evJ, s2);

    cvt_elem<<<NN*128/1024, blk>>>(x, (__half*)xh, NN*128/4);
    tr_w<<<dim3(8,4), blk>>>(W1, (__half*)w1t, 128, 256);
    gemm_f16<false,false,false,false,true><<<dim3(4,32), blk>>>(
        (const __half*)xh, (const __half*)w1t, nullptr, nullptr, nullptr, nullptr,
        tmph, nullptr, NN, HH, 128);
    cudaStreamWaitEvent(0, evJ, 0);     // join: CSR + remaining weights ready

    gcn_gather<true,false><<<NN/8, blk>>>(b1, (__half*)hh, nullptr);
    gemm_f16<false,false,false,false,true><<<dim3(4,32), blk>>>(
        (const __half*)hh, (const __half*)w2t, nullptr, nullptr, nullptr, nullptr,
        tmph, nullptr, NN, HH, HH);
    gcn_gather<true,false><<<NN/8, blk>>>(b2, (__half*)hh, nullptr);
    gemm_f16<false,false,false,false,true><<<dim3(4,32), blk>>>(
        (const __half*)hh, (const __half*)w3t, nullptr, nullptr, nullptr, nullptr,
        tmph, nullptr, NN, HH, HH);
    gcn_gather<false,true><<<NN/8, blk>>>(b3, (__half*)h3h, h3);

    // MHA: fused QKV gemm -> (g_Qb, g_Kb, g_Vh); flash attention (256-row tiles)
    gemm_f16<false,false,true,false,false><<<dim3(12,32), blk>>>(
        (const __half*)h3h, (const __half*)inwh, nullptr, in_b, nullptr, nullptr,
        nullptr, nullptr, NN, 3*HH, HH);
    flash_attn_bf16<<<dim3(NN/256, 8), blk>>>();
    // h = attnH @ out_w^T + out_b + h3 (fp32 SRC), output fp16 -> g_hH
    gemm_f16<false,true,false,false,true><<<dim3(4,32), blk>>>(
        (const __half*)attnh, (const __half*)outwh, nullptr, out_b, nullptr, h3,
        hh, nullptr, NN, HH, HH);

    // Fused dual-head GEMM + fused heads
    gemm_f16<true,false,false,true,false><<<dim3(4,32), blk>>>(
        (const __half*)hh, (const __half*)fp1h, (const __half*)pd1h, fp1b, pd1b, nullptr,
        hid, hid2, NN, 128, HH);
    head_both<<<NN/8, blk>>>(fp2w, fp2b, pd2w, pd2b, outp);
}

// round 14
// speedup vs baseline: 1.2666x; 1.0234x over previous
#include <cuda_runtime.h>
#include <cuda_bf16.h>
#include <cuda_fp16.h>
#include <cstdint>
#include <math.h>

#define NN 4096
#define EE 131072
#define HH 256

#define QSCALE_F (0.17677669529663687f * 1.4426950408889634f)

// ---------------- scratch (static device globals; no allocation) ----------------
__device__ __half g_tmpH[NN*HH];     // h @ W, fp16 (pre-aggregation)
__device__ __half g_hH  [NN*HH];     // activation (fp16 GEMM input)
__device__ __half g_h3H [NN*HH];     // h3 fp16 (QKV GEMM input)
__device__ float  g_h3  [NN*HH];     // h3 fp32 (residual SRC)
__device__ __half g_attnH[NN*HH];    // attention output fp16
__device__ float g_deg [NN];
__device__ float g_dinv[NN];
__device__ float g_hid [NN*128];
__device__ float g_hid2[NN*128];
__device__ int   g_rowptr[NN+1];
__device__ int   g_cursor[NN];
__device__ int   g_esrc [EE];
__device__ float g_enorm[EE];
__device__ __nv_bfloat16 g_Qb[8*NN*32];   // [h][n][d], pre-scaled by 1/sqrt(32)*log2e
__device__ __nv_bfloat16 g_Kb[8*NN*32];   // [h][n][d]
__device__ __half        g_Vh[8*32*NN];   // [h][d][n]  (transposed, fp16)
// fp16 operand copies (built once per launch, overlapped)
__device__ __half g_xH  [NN*128];
__device__ __half g_W1t [256*128];        // [N,K]
__device__ __half g_W2t [256*256];
__device__ __half g_W3t [256*256];
__device__ __half g_inwH[768*256];
__device__ __half g_outwH[256*256];
__device__ __half g_fp1H[128*256];
__device__ __half g_pd1H[128*256];

// ---------------- async-copy helpers ---------------------------------------------
__device__ __forceinline__ void cp_async16(void* smem, const void* gmem) {
    uint32_t s = (uint32_t)__cvta_generic_to_shared(smem);
    asm volatile("cp.async.ca.shared.global [%0], [%1], 16;\n" :: "r"(s), "l"(gmem));
}
#define CP_COMMIT() asm volatile("cp.async.commit_group;\n" ::: "memory")
#define CP_WAIT(n)  asm volatile("cp.async.wait_group %0;\n" :: "n"(n) : "memory")

// ---------------- mma wrappers ----------------------------------------------------
__device__ __forceinline__ void mma_bf16(float* c, const uint32_t* a, uint32_t b0, uint32_t b1) {
    asm volatile(
        "mma.sync.aligned.m16n8k16.row.col.f32.bf16.bf16.f32 "
        "{%0,%1,%2,%3}, {%4,%5,%6,%7}, {%8,%9}, {%0,%1,%2,%3};\n"
        : "+f"(c[0]), "+f"(c[1]), "+f"(c[2]), "+f"(c[3])
        : "r"(a[0]), "r"(a[1]), "r"(a[2]), "r"(a[3]), "r"(b0), "r"(b1));
}
__device__ __forceinline__ void mma_f16(float* c, const uint32_t* a, uint32_t b0, uint32_t b1) {
    asm volatile(
        "mma.sync.aligned.m16n8k16.row.col.f32.f16.f16.f32 "
        "{%0,%1,%2,%3}, {%4,%5,%6,%7}, {%8,%9}, {%0,%1,%2,%3};\n"
        : "+f"(c[0]), "+f"(c[1]), "+f"(c[2]), "+f"(c[3])
        : "r"(a[0]), "r"(a[1]), "r"(a[2]), "r"(a[3]), "r"(b0), "r"(b1));
}
__device__ __forceinline__ uint32_t pack_bf16(float lo, float hi) {
    __nv_bfloat162 v = __floats2bfloat162_rn(lo, hi);
    return *(uint32_t*)&v;
}

// QKV epilogue store: n in [0,768). Block-uniform branch (64-col tiles).
__device__ __forceinline__ void store_qkv(int row, int n, float a, float b) {
    int d = n & 31;
    int hh = (n >> 5) & 7;
    if (n < 256) {
        *(uint32_t*)(g_Qb + ((size_t)hh*NN + row)*32 + d) = pack_bf16(a*QSCALE_F, b*QSCALE_F);
    } else if (n < 512) {
        *(uint32_t*)(g_Kb + ((size_t)hh*NN + row)*32 + d) = pack_bf16(a, b);
    } else {
        g_Vh[((size_t)hh*32 + d    )*NN + row] = __float2half(a);
        g_Vh[((size_t)hh*32 + d + 1)*NN + row] = __float2half(b);
    }
}

// ---------------- conversion kernels (once per launch, mostly overlapped) ---------
__global__ void cvt_elem(const float* __restrict__ in, __half* __restrict__ out, int n4) {
    int i = blockIdx.x * 256 + threadIdx.x;
    if (i < n4) {
        float4 v = ((const float4*)in)[i];
        __half2 a = __floats2half2_rn(v.x, v.y), b = __floats2half2_rn(v.z, v.w);
        ((uint2*)out)[i] = make_uint2(*(uint32_t*)&a, *(uint32_t*)&b);
    }
}
// out[n*K+k] = in[k*N+n], fp32 -> fp16.  grid (N/32, K/32), block 256.
__global__ void tr_w(const float* __restrict__ in, __half* __restrict__ out, int K, int N) {
    __shared__ float t[32][33];
    int n0 = blockIdx.x * 32, k0 = blockIdx.y * 32;
    int tx = threadIdx.x & 31, ty = threadIdx.x >> 5;
    #pragma unroll
    for (int i = ty; i < 32; i += 8)
        t[i][tx] = in[(size_t)(k0 + i)*N + n0 + tx];
    __syncthreads();
    #pragma unroll
    for (int i = ty; i < 32; i += 8)
        out[(size_t)(n0 + i)*K + k0 + tx] = __float2half(t[tx][i]);
}
// convert the four [N,K]-layout weights elementwise
__global__ void cvt4(const float* w1, __half* o1, const float* w2, __half* o2,
                     const float* w3, __half* o3, const float* w4, __half* o4) {
    const int N1 = 768*256, N2 = 256*256, N3 = 128*256;
    int i = blockIdx.x * 256 + threadIdx.x;
    if (i < N1) { o1[i] = __float2half(w1[i]); }
    if (i < N2) { o2[i] = __float2half(w2[i]); }
    if (i < N3) { o3[i] = __float2half(w3[i]); o4[i] = __float2half(w4[i]); }
}

// ---------------- pipelined fp16 GEMM (128x64, 3-stage ring, TRANSB always) -------
template<bool RELU, bool ADDSRC, bool QKV, bool DUALB, bool OUTH>
__global__ void __launch_bounds__(256) gemm_f16(
    const __half* __restrict__ A, const __half* __restrict__ Bt,
    const __half* __restrict__ Bt2, const float* __restrict__ bias,
    const float* __restrict__ bias2, const float* __restrict__ SRC,
    void* __restrict__ Cv, void* __restrict__ C2v, int M, int N, int K)
{
    __shared__ __half As[3][128*24];    // [m][k], stride 24 halves (conflict-free)
    __shared__ __half Bs[3][64*24];

    const int tid  = threadIdx.x;
    const int w    = tid >> 5, lane = tid & 31;
    const int g    = lane >> 2, t = lane & 3;
    const int wm   = w & 3, wn = w >> 2;
    const int m0   = blockIdx.y * 128;
    void* Cuse = Cv;
    int n0;
    if (DUALB) {
        n0 = (blockIdx.x & 1) * 64;
        if (blockIdx.x >= 2) { Bt = Bt2; bias = bias2; Cuse = C2v; }
    } else {
        n0 = blockIdx.x * 64;
    }
    const int KT = K >> 4;

    const int arow = tid >> 1, ac8 = (tid & 1) * 8;
    const int brow = tid >> 1, bc8 = (tid & 1) * 8;

    float acc[2][4][4] = {};

    #pragma unroll
    for (int p = 0; p < 2; p++) {
        const int k0 = p << 4;
        cp_async16(&As[p][arow*24 + ac8], A + (size_t)(m0 + arow)*K + k0 + ac8);
        if (tid < 128)
            cp_async16(&Bs[p][brow*24 + bc8], Bt + (size_t)(n0 + brow)*K + k0 + bc8);
        CP_COMMIT();
    }

    for (int kt = 0; kt < KT; kt++) {
        const int st = kt % 3;
        if (kt + 1 < KT) { CP_WAIT(1); } else { CP_WAIT(0); }
        __syncthreads();
        if (kt + 2 < KT) {
            const int sp = (kt + 2) % 3;
            const int k0 = (kt + 2) << 4;
            cp_async16(&As[sp][arow*24 + ac8], A + (size_t)(m0 + arow)*K + k0 + ac8);
            if (tid < 128)
                cp_async16(&Bs[sp][brow*24 + bc8], Bt + (size_t)(n0 + brow)*K + k0 + bc8);
            CP_COMMIT();
        }

        const uint32_t* as = (const uint32_t*)As[st];
        const uint32_t* bs = (const uint32_t*)Bs[st];
        uint32_t a[2][4];
        #pragma unroll
        for (int mt = 0; mt < 2; mt++) {
            int row = wm*32 + mt*16 + g;
            a[mt][0] = as[(row  )*12 + t];
            a[mt][1] = as[(row+8)*12 + t];
            a[mt][2] = as[(row  )*12 + t + 4];
            a[mt][3] = as[(row+8)*12 + t + 4];
        }
        #pragma unroll
        for (int nt = 0; nt < 4; nt++) {
            int n = wn*32 + nt*8 + g;
            uint32_t b0 = bs[n*12 + t];
            uint32_t b1 = bs[n*12 + t + 4];
            mma_f16(acc[0][nt], a[0], b0, b1);
            mma_f16(acc[1][nt], a[1], b0, b1);
        }
    }

    #pragma unroll
    for (int mt = 0; mt < 2; mt++) {
        const int r0 = m0 + wm*32 + mt*16 + g;
        #pragma unroll
        for (int nt = 0; nt < 4; nt++) {
            const int n = n0 + wn*32 + nt*8 + 2*t;
            float bb0 = bias ? bias[n] : 0.f;
            float bb1 = bias ? bias[n+1] : 0.f;
            float v00 = acc[mt][nt][0] + bb0, v01 = acc[mt][nt][1] + bb1;
            float v10 = acc[mt][nt][2] + bb0, v11 = acc[mt][nt][3] + bb1;
            if (ADDSRC) {
                v00 += SRC[(size_t)r0*N + n];     v01 += SRC[(size_t)r0*N + n + 1];
                v10 += SRC[(size_t)(r0+8)*N + n]; v11 += SRC[(size_t)(r0+8)*N + n + 1];
            }
            if (RELU) {
                v00 = fmaxf(v00, 0.f); v01 = fmaxf(v01, 0.f);
                v10 = fmaxf(v10, 0.f); v11 = fmaxf(v11, 0.f);
            }
            if (QKV) {
                store_qkv(r0,     n, v00, v01);
                store_qkv(r0 + 8, n, v10, v11);
            } else if (OUTH) {
                __half* C = (__half*)Cuse;
                __half2 h0 = __floats2half2_rn(v00, v01);
                __half2 h1 = __floats2half2_rn(v10, v11);
                *(uint32_t*)(C + (size_t)r0*N + n)     = *(uint32_t*)&h0;
                *(uint32_t*)(C + (size_t)(r0+8)*N + n) = *(uint32_t*)&h1;
            } else {
                float* C = (float*)Cuse;
                *(float2*)(C + (size_t)r0*N + n)     = make_float2(v00, v01);
                *(float2*)(C + (size_t)(r0+8)*N + n) = make_float2(v10, v11);
            }
        }
    }
}

// ---------------- graph preprocessing (CSR build; 4 edges/thread, int4 loads) -----
__global__ void deg_count(const int* __restrict__ dst) {
    int i = blockIdx.x * 256 + threadIdx.x;          // EE/4 threads
    int4 d4 = ((const int4*)dst)[i];
    atomicAdd(&g_deg[d4.x], 1.0f);
    atomicAdd(&g_deg[d4.y], 1.0f);
    atomicAdd(&g_deg[d4.z], 1.0f);
    atomicAdd(&g_deg[d4.w], 1.0f);
}

__global__ void __launch_bounds__(1024) scan_rowptr() {
    __shared__ int warpsum[32];
    const int tid = threadIdx.x;
    const int lane = tid & 31, wid = tid >> 5;
    const int base = tid * 4;
    int c[4], s = 0;
    #pragma unroll
    for (int j = 0; j < 4; j++) {
        c[j] = (int)g_deg[base + j];
        g_dinv[base + j] = rsqrtf((float)c[j] + 1.0f);
        s += c[j];
    }
    int pre = s;
    #pragma unroll
    for (int off = 1; off < 32; off <<= 1) {
        int v = __shfl_up_sync(0xffffffffu, pre, off);
        if (lane >= off) pre += v;
    }
    if (lane == 31) warpsum[wid] = pre;
    __syncthreads();
    if (wid == 0) {
        int v = warpsum[lane];
        #pragma unroll
        for (int off = 1; off < 32; off <<= 1) {
            int u = __shfl_up_sync(0xffffffffu, v, off);
            if (lane >= off) v += u;
        }
        warpsum[lane] = v;
    }
    __syncthreads();
    int excl = pre - s + (wid > 0 ? warpsum[wid-1] : 0);
    int run = excl;
    #pragma unroll
    for (int j = 0; j < 4; j++) {
        g_rowptr[base + j] = run;
        g_cursor[base + j] = run;
        run += c[j];
    }
    if (tid == 1023) g_rowptr[NN] = run;
}

__global__ void csr_scatter(const int* __restrict__ src, const int* __restrict__ dst) {
    int i = blockIdx.x * 256 + threadIdx.x;          // EE/4 threads
    int4 s4 = ((const int4*)src)[i];
    int4 d4 = ((const int4*)dst)[i];
    int sv[4] = {s4.x, s4.y, s4.z, s4.w};
    int dv[4] = {d4.x, d4.y, d4.z, d4.w};
    #pragma unroll
    for (int j = 0; j < 4; j++) {
        int p = atomicAdd(&g_cursor[dv[j]], 1);
        g_esrc[p]  = sv[j];
        g_enorm[p] = g_dinv[sv[j]] * g_dinv[dv[j]];
    }
}

// ---------------- GCN gather (fp16 in, fp16 out; H3 also writes fp32) -------------
__device__ __forceinline__ void acc_row(const uint4 v, float wgt, float* a) {
    float2 f0 = __half22float2(*(const __half2*)&v.x);
    float2 f1 = __half22float2(*(const __half2*)&v.y);
    float2 f2 = __half22float2(*(const __half2*)&v.z);
    float2 f3 = __half22float2(*(const __half2*)&v.w);
    a[0] = fmaf(wgt, f0.x, a[0]); a[1] = fmaf(wgt, f0.y, a[1]);
    a[2] = fmaf(wgt, f1.x, a[2]); a[3] = fmaf(wgt, f1.y, a[3]);
    a[4] = fmaf(wgt, f2.x, a[4]); a[5] = fmaf(wgt, f2.y, a[5]);
    a[6] = fmaf(wgt, f3.x, a[6]); a[7] = fmaf(wgt, f3.y, a[7]);
}

template<bool RELU, bool H3>
__global__ void __launch_bounds__(256) gcn_gather(const float* __restrict__ bias,
                                                  __half* __restrict__ outH,
                                                  float* __restrict__ outF) {
    const int node = blockIdx.x * 8 + (threadIdx.x >> 5);
    const int lane = threadIdx.x & 31;
    const int beg = g_rowptr[node], end = g_rowptr[node+1];

    float a[8] = {};
    int i = beg;
    for (; i + 2 <= end; i += 2) {
        int s0i = g_esrc[i],   s1i = g_esrc[i+1];
        float w0 = g_enorm[i], w1 = g_enorm[i+1];
        uint4 x = *((const uint4*)(g_tmpH + (size_t)s0i*HH) + lane);
        uint4 y = *((const uint4*)(g_tmpH + (size_t)s1i*HH) + lane);
        acc_row(x, w0, a);
        acc_row(y, w1, a);
    }
    if (i < end) {
        uint4 x = *((const uint4*)(g_tmpH + (size_t)g_esrc[i]*HH) + lane);
        acc_row(x, g_enorm[i], a);
    }
    float di = g_dinv[node];
    float sw = di * di;
    uint4 sv = *((const uint4*)(g_tmpH + (size_t)node*HH) + lane);
    acc_row(sv, sw, a);

    const float4* bp = (const float4*)(bias + lane*8);
    float4 b0 = bp[0], b1 = bp[1];
    float o0 = a[0] + b0.x, o1 = a[1] + b0.y, o2 = a[2] + b0.z, o3 = a[3] + b0.w;
    float o4 = a[4] + b1.x, o5 = a[5] + b1.y, o6 = a[6] + b1.z, o7 = a[7] + b1.w;
    if (RELU) {
        o0 = fmaxf(o0,0.f); o1 = fmaxf(o1,0.f); o2 = fmaxf(o2,0.f); o3 = fmaxf(o3,0.f);
        o4 = fmaxf(o4,0.f); o5 = fmaxf(o5,0.f); o6 = fmaxf(o6,0.f); o7 = fmaxf(o7,0.f);
    }
    __half2 ph0 = __floats2half2_rn(o0,o1), ph1 = __floats2half2_rn(o2,o3);
    __half2 ph2 = __floats2half2_rn(o4,o5), ph3 = __floats2half2_rn(o6,o7);
    *((uint4*)(outH + (size_t)node*HH) + lane) =
        make_uint4(*(uint32_t*)&ph0, *(uint32_t*)&ph1, *(uint32_t*)&ph2, *(uint32_t*)&ph3);
    if (H3) {
        float4* op = (float4*)(outF + (size_t)node*HH + lane*8);
        op[0] = make_float4(o0,o1,o2,o3);
        op[1] = make_float4(o4,o5,o6,o7);
    }
}

// ---------------- flash attention: 256-query tiles, bf16 QK, fp16 softmax/PV ------
__global__ void __launch_bounds__(256) flash_attn_bf16() {
    __shared__ __align__(16) char Ks[3][64*80];
    __shared__ __align__(16) char Vs[3][32*144];

    const int head = blockIdx.y;
    const int q0   = blockIdx.x * 256;
    const int tid  = threadIdx.x;
    const int w    = tid >> 5, lane = tid & 31;
    const int g    = lane >> 2, t = lane & 3;
    const int KT   = NN / 64;
    const uint32_t ONES2 = 0x3C003C00u;

    const __nv_bfloat16* kg = g_Kb + (size_t)head*NN*32;
    const __half*        vg = g_Vh + (size_t)head*32*NN;

    const int kr8 = tid >> 2, kc8 = (tid & 3) * 8;
    const int vd  = tid >> 3, vk8 = (tid & 7) * 8;

    cp_async16(&Ks[0][kr8*80 + kc8*2], kg + (size_t)kr8*32 + kc8);
    cp_async16(&Vs[0][vd*144 + vk8*2], vg + (size_t)vd*NN + vk8);
    CP_COMMIT();
    cp_async16(&Ks[1][kr8*80 + kc8*2], kg + (size_t)(64 + kr8)*32 + kc8);
    cp_async16(&Vs[1][vd*144 + vk8*2], vg + (size_t)vd*NN + 64 + vk8);
    CP_COMMIT();

    uint32_t aq[2][2][4];
    #pragma unroll
    for (int qh = 0; qh < 2; qh++) {
        const __nv_bfloat16* qb = g_Qb + ((size_t)head*NN + q0 + qh*128 + w*16) * 32;
        #pragma unroll
        for (int ks = 0; ks < 2; ks++) {
            int c = ks*16 + 2*t;
            aq[qh][ks][0] = *(const uint32_t*)(qb + (size_t)(g  )*32 + c);
            aq[qh][ks][1] = *(const uint32_t*)(qb + (size_t)(g+8)*32 + c);
            aq[qh][ks][2] = *(const uint32_t*)(qb + (size_t)(g  )*32 + c + 8);
            aq[qh][ks][3] = *(const uint32_t*)(qb + (size_t)(g+8)*32 + c + 8);
        }
    }

    float m[2][2];
    m[0][0] = m[0][1] = m[1][0] = m[1][1] = -1e30f;
    float o[2][4][4] = {};
    float lacc[2][4] = {};

    for (int kt = 0; kt < KT; kt++) {
        const int st = kt % 3;
        if (kt + 1 < KT) { CP_WAIT(1); } else { CP_WAIT(0); }
        __syncthreads();
        if (kt + 2 < KT) {
            const int sp = (kt + 2) % 3;
            cp_async16(&Ks[sp][kr8*80 + kc8*2], kg + (size_t)((kt+2)*64 + kr8)*32 + kc8);
            cp_async16(&Vs[sp][vd*144 + vk8*2], vg + (size_t)vd*NN + (kt+2)*64 + vk8);
            CP_COMMIT();
        }

        #pragma unroll
        for (int qh = 0; qh < 2; qh++) {
            float s[8][4];
            #pragma unroll
            for (int nb = 0; nb < 8; nb++) {
                s[nb][0] = s[nb][1] = s[nb][2] = s[nb][3] = 0.f;
                const char* kr = Ks[st] + (nb*8 + g)*80;
                uint32_t b0 = *(const uint32_t*)(kr + (2*t)*2);
                uint32_t b1 = *(const uint32_t*)(kr + (2*t+8)*2);
                mma_bf16(s[nb], aq[qh][0], b0, b1);
                b0 = *(const uint32_t*)(kr + (16 + 2*t)*2);
                b1 = *(const uint32_t*)(kr + (16 + 2*t+8)*2);
                mma_bf16(s[nb], aq[qh][1], b0, b1);
            }

            float tm0 = -1e30f, tm1 = -1e30f;
            #pragma unroll
            for (int nb = 0; nb < 8; nb++) {
                tm0 = fmaxf(tm0, fmaxf(s[nb][0], s[nb][1]));
                tm1 = fmaxf(tm1, fmaxf(s[nb][2], s[nb][3]));
            }
            tm0 = fmaxf(tm0, __shfl_xor_sync(0xffffffffu, tm0, 1));
            tm0 = fmaxf(tm0, __shfl_xor_sync(0xffffffffu, tm0, 2));
            tm1 = fmaxf(tm1, __shfl_xor_sync(0xffffffffu, tm1, 1));
            tm1 = fmaxf(tm1, __shfl_xor_sync(0xffffffffu, tm1, 2));
            float nm0 = fmaxf(m[qh][0], tm0), nm1 = fmaxf(m[qh][1], tm1);
            float al0 = exp2f(m[qh][0] - nm0), al1 = exp2f(m[qh][1] - nm1);
            m[qh][0] = nm0; m[qh][1] = nm1;

            __half2 p01[8], p23[8];
            #pragma unroll
            for (int nb = 0; nb < 8; nb++) {
                p01[nb] = h2exp2(__floats2half2_rn(s[nb][0] - nm0, s[nb][1] - nm0));
                p23[nb] = h2exp2(__floats2half2_rn(s[nb][2] - nm1, s[nb][3] - nm1));
            }

            #pragma unroll
            for (int nbv = 0; nbv < 4; nbv++) {
                o[qh][nbv][0] *= al0; o[qh][nbv][1] *= al0;
                o[qh][nbv][2] *= al1; o[qh][nbv][3] *= al1;
            }
            lacc[qh][0] *= al0; lacc[qh][1] *= al0;
            lacc[qh][2] *= al1; lacc[qh][3] *= al1;

            uint32_t ap[4][4];
            #pragma unroll
            for (int s4 = 0; s4 < 4; s4++) {
                ap[s4][0] = *(const uint32_t*)&p01[2*s4];
                ap[s4][1] = *(const uint32_t*)&p23[2*s4];
                ap[s4][2] = *(const uint32_t*)&p01[2*s4+1];
                ap[s4][3] = *(const uint32_t*)&p23[2*s4+1];
            }

            #pragma unroll
            for (int s4 = 0; s4 < 4; s4++) {
                mma_f16(lacc[qh], ap[s4], ONES2, ONES2);
                #pragma unroll
                for (int nbv = 0; nbv < 4; nbv++) {
                    const char* vr = Vs[st] + (nbv*8 + g)*144;
                    uint32_t b0 = *(const uint32_t*)(vr + (16*s4 + 2*t)*2);
                    uint32_t b1 = *(const uint32_t*)(vr + (16*s4 + 2*t + 8)*2);
                    mma_f16(o[qh][nbv], ap[s4], b0, b1);
                }
            }
        }
    }

    #pragma unroll
    for (int qh = 0; qh < 2; qh++) {
        float inv0 = 1.0f / lacc[qh][0], inv1 = 1.0f / lacc[qh][2];
        int row0 = q0 + qh*128 + w*16 + g;
        #pragma unroll
        for (int nbv = 0; nbv < 4; nbv++) {
            int col = head*32 + nbv*8 + 2*t;
            __half2 h0 = __floats2half2_rn(o[qh][nbv][0]*inv0, o[qh][nbv][1]*inv0);
            __half2 h1 = __floats2half2_rn(o[qh][nbv][2]*inv1, o[qh][nbv][3]*inv1);
            *(uint32_t*)(g_attnH + (size_t)row0*HH + col)     = *(uint32_t*)&h0;
            *(uint32_t*)(g_attnH + (size_t)(row0+8)*HH + col) = *(uint32_t*)&h1;
        }
    }
}

// ---------------- fused output heads (warp per node: softmax3 + sigmoid10) --------
__global__ void __launch_bounds__(256) head_both(const float* __restrict__ W3,
                                                 const float* __restrict__ b3v,
                                                 const float* __restrict__ W10,
                                                 const float* __restrict__ b10,
                                                 float* __restrict__ out) {
    const int node = blockIdx.x * 8 + (threadIdx.x >> 5);
    const int lane = threadIdx.x & 31;

    float4 hv = *(const float4*)(g_hid + (size_t)node*128 + lane*4);
    float lg3[3];
    #pragma unroll
    for (int c = 0; c < 3; c++) {
        float4 wv = *(const float4*)(W3 + c*128 + lane*4);
        float d = hv.x*wv.x + hv.y*wv.y + hv.z*wv.z + hv.w*wv.w;
        #pragma unroll
        for (int m = 16; m >= 1; m >>= 1) d += __shfl_xor_sync(0xffffffffu, d, m);
        lg3[c] = d + b3v[c];
    }
    float4 hv2 = *(const float4*)(g_hid2 + (size_t)node*128 + lane*4);
    float lg10[10];
    #pragma unroll
    for (int c = 0; c < 10; c++) {
        float4 wv = *(const float4*)(W10 + c*128 + lane*4);
        float d = hv2.x*wv.x + hv2.y*wv.y + hv2.z*wv.z + hv2.w*wv.w;
        #pragma unroll
        for (int m = 16; m >= 1; m >>= 1) d += __shfl_xor_sync(0xffffffffu, d, m);
        lg10[c] = d + b10[c];
    }
    if (lane == 0) {
        float mx = fmaxf(fmaxf(lg3[0], lg3[1]), lg3[2]);
        float e0 = __expf(lg3[0]-mx), e1 = __expf(lg3[1]-mx), e2 = __expf(lg3[2]-mx);
        float inv = 1.0f / (e0 + e1 + e2);
        out[(size_t)node*3 + 0] = e0*inv;
        out[(size_t)node*3 + 1] = e1*inv;
        out[(size_t)node*3 + 2] = e2*inv;
        float* o2 = out + (size_t)NN*3 + (size_t)node*10;
        #pragma unroll
        for (int c = 0; c < 10; c++)
            o2[c] = 1.0f / (1.0f + __expf(-lg10[c]));
    }
}

// ---------------- launch ---------------------------------------------------------
extern "C" void kernel_launch(void* const* d_in, const int* in_sizes, int n_in,
                              void* d_out, int out_size)
{
    const float* x     = (const float*)d_in[0];
    const int*   ei    = (const int*)  d_in[1];
    const float* W1    = (const float*)d_in[2];
    const float* b1    = (const float*)d_in[3];
    const float* W2    = (const float*)d_in[4];
    const float* b2    = (const float*)d_in[5];
    const float* W3    = (const float*)d_in[6];
    const float* b3    = (const float*)d_in[7];
    const float* in_w  = (const float*)d_in[8];
    const float* in_b  = (const float*)d_in[9];
    const float* out_w = (const float*)d_in[10];
    const float* out_b = (const float*)d_in[11];
    const float* fp1w  = (const float*)d_in[12];
    const float* fp1b  = (const float*)d_in[13];
    const float* fp2w  = (const float*)d_in[14];
    const float* fp2b  = (const float*)d_in[15];
    const float* pd1w  = (const float*)d_in[16];
    const float* pd1b  = (const float*)d_in[17];
    const float* pd2w  = (const float*)d_in[18];
    const float* pd2b  = (const float*)d_in[19];
    const int* src = ei;
    const int* dst = ei + EE;
    float* outp = (float*)d_out;

    void *tmph, *hh, *h3h, *attnh, *xh, *w1t, *w2t, *w3t, *inwh, *outwh, *fp1h, *pd1h;
    float *h3, *deg, *hid, *hid2;
    cudaGetSymbolAddress((void**)&tmph,  g_tmpH);
    cudaGetSymbolAddress((void**)&hh,    g_hH);
    cudaGetSymbolAddress((void**)&h3h,   g_h3H);
    cudaGetSymbolAddress((void**)&h3,    g_h3);
    cudaGetSymbolAddress((void**)&attnh, g_attnH);
    cudaGetSymbolAddress((void**)&deg,   g_deg);
    cudaGetSymbolAddress((void**)&hid,   g_hid);
    cudaGetSymbolAddress((void**)&hid2,  g_hid2);
    cudaGetSymbolAddress((void**)&xh,    g_xH);
    cudaGetSymbolAddress((void**)&w1t,   g_W1t);
    cudaGetSymbolAddress((void**)&w2t,   g_W2t);
    cudaGetSymbolAddress((void**)&w3t,   g_W3t);
    cudaGetSymbolAddress((void**)&inwh,  g_inwH);
    cudaGetSymbolAddress((void**)&outwh, g_outwH);
    cudaGetSymbolAddress((void**)&fp1h,  g_fp1H);
    cudaGetSymbolAddress((void**)&pd1h,  g_pd1H);

    static cudaStream_t s2 = nullptr;
    static cudaEvent_t evF = nullptr, evJ = nullptr, evW = nullptr;
    if (!s2) {
        cudaStreamCreateWithFlags(&s2, cudaStreamNonBlocking);
        cudaEventCreateWithFlags(&evF, cudaEventDisableTiming);
        cudaEventCreateWithFlags(&evJ, cudaEventDisableTiming);
        cudaEventCreateWithFlags(&evW, cudaEventDisableTiming);
    }

    const dim3 blk(256);

    // Fork: CSR build FIRST on s2 (join feeds gather1), then weight conversions.
    cudaEventRecord(evF, 0);
    cudaStreamWaitEvent(s2, evF, 0);
    cudaMemsetAsync(deg, 0, NN * sizeof(float), s2);
    deg_count<<<EE/1024, 256, 0, s2>>>(dst);
    scan_rowptr<<<1, 1024, 0, s2>>>();
    csr_scatter<<<EE/1024, 256, 0, s2>>>(src, dst);
    cudaEventRecord(evJ, s2);
    tr_w<<<dim3(8,8), blk, 0, s2>>>(W2, (__half*)w2t, 256, 256);
    tr_w<<<dim3(8,8), blk, 0, s2>>>(W3, (__half*)w3t, 256, 256);
    cvt4<<<768, blk, 0, s2>>>(in_w, (__half*)inwh, out_w, (__half*)outwh,
                              fp1w, (__half*)fp1h, pd1w, (__half*)pd1h);
    cudaEventRecord(evW, s2);

    cvt_elem<<<NN*128/1024, blk>>>(x, (__half*)xh, NN*128/4);
    tr_w<<<dim3(8,4), blk>>>(W1, (__half*)w1t, 128, 256);
    gemm_f16<false,false,false,false,true><<<dim3(4,32), blk>>>(
        (const __half*)xh, (const __half*)w1t, nullptr, nullptr, nullptr, nullptr,
        tmph, nullptr, NN, HH, 128);
    cudaStreamWaitEvent(0, evJ, 0);     // CSR ready

    gcn_gather<true,false><<<NN/8, blk>>>(b1, (__half*)hh, nullptr);
    cudaStreamWaitEvent(0, evW, 0);     // weight conversions ready (overlapped w/ gather1)
    gemm_f16<false,false,false,false,true><<<dim3(4,32), blk>>>(
        (const __half*)hh, (const __half*)w2t, nullptr, nullptr, nullptr, nullptr,
        tmph, nullptr, NN, HH, HH);
    gcn_gather<true,false><<<NN/8, blk>>>(b2, (__half*)hh, nullptr);
    gemm_f16<false,false,false,false,true><<<dim3(4,32), blk>>>(
        (const __half*)hh, (const __half*)w3t, nullptr, nullptr, nullptr, nullptr,
        tmph, nullptr, NN, HH, HH);
    gcn_gather<false,true><<<NN/8, blk>>>(b3, (__half*)h3h, h3);

    // MHA: fused QKV gemm -> (g_Qb, g_Kb, g_Vh); flash attention (256-row tiles)
    gemm_f16<false,false,true,false,false><<<dim3(12,32), blk>>>(
        (const __half*)h3h, (const __half*)inwh, nullptr, in_b, nullptr, nullptr,
        nullptr, nullptr, NN, 3*HH, HH);
    flash_attn_bf16<<<dim3(NN/256, 8), blk>>>();
    gemm_f16<false,true,false,false,true><<<dim3(4,32), blk>>>(
        (const __half*)attnh, (const __half*)outwh, nullptr, out_b, nullptr, h3,
        hh, nullptr, NN, HH, HH);

    // Fused dual-head GEMM + fused heads
    gemm_f16<true,false,false,true,false><<<dim3(4,32), blk>>>(
        (const __half*)hh, (const __half*)fp1h, (const __half*)pd1h, fp1b, pd1b, nullptr,
        hid, hid2, NN, 128, HH);
    head_both<<<NN/8, blk>>>(fp2w, fp2b, pd2w, pd2b, outp);
}

// round 16
// speedup vs baseline: 1.2689x; 1.0018x over previous
#include <cuda_runtime.h>
#include <cuda_bf16.h>
#include <cuda_fp16.h>
#include <cstdint>
#include <math.h>

#define NN 4096
#define EE 131072
#define HH 256

#define QSCALE_F (0.17677669529663687f * 1.4426950408889634f)

// ---------------- scratch (static device globals; no allocation) ----------------
__device__ __half g_tmpH[NN*HH];     // h @ W, fp16 (pre-aggregation)
__device__ __half g_hH  [NN*HH];     // activation (fp16 GEMM input)
__device__ __half g_h3H [NN*HH];     // h3 fp16 (QKV GEMM input)
__device__ float  g_h3  [NN*HH];     // h3 fp32 (residual SRC)
__device__ __half g_attnH[NN*HH];    // attention output fp16
__device__ float g_deg [NN];
__device__ float g_dinv[NN];
__device__ float g_hid [NN*128];
__device__ float g_hid2[NN*128];
__device__ int   g_rowptr[NN+1];
__device__ int   g_cursor[NN];
__device__ int   g_esrc [EE];
__device__ float g_enorm[EE];
__device__ __nv_bfloat16 g_Qb[8*NN*32];   // [h][n][d], pre-scaled by 1/sqrt(32)*log2e
__device__ __nv_bfloat16 g_Kb[8*NN*32];   // [h][n][d]
__device__ __half        g_Vh[8*32*NN];   // [h][d][n]  (transposed, fp16)
// fp16 operand copies (built once per launch, overlapped)
__device__ __half g_xH  [NN*128];
__device__ __half g_W1t [256*128];        // [N,K]
__device__ __half g_W2t [256*256];
__device__ __half g_W3t [256*256];
__device__ __half g_inwH[768*256];
__device__ __half g_outwH[256*256];
__device__ __half g_fp1H[128*256];
__device__ __half g_pd1H[128*256];

// ---------------- async-copy helpers ---------------------------------------------
__device__ __forceinline__ void cp_async16(void* smem, const void* gmem) {
    uint32_t s = (uint32_t)__cvta_generic_to_shared(smem);
    asm volatile("cp.async.ca.shared.global [%0], [%1], 16;\n" :: "r"(s), "l"(gmem));
}
#define CP_COMMIT() asm volatile("cp.async.commit_group;\n" ::: "memory")
#define CP_WAIT(n)  asm volatile("cp.async.wait_group %0;\n" :: "n"(n) : "memory")

// ---------------- mma wrappers ----------------------------------------------------
__device__ __forceinline__ void mma_bf16(float* c, const uint32_t* a, uint32_t b0, uint32_t b1) {
    asm volatile(
        "mma.sync.aligned.m16n8k16.row.col.f32.bf16.bf16.f32 "
        "{%0,%1,%2,%3}, {%4,%5,%6,%7}, {%8,%9}, {%0,%1,%2,%3};\n"
        : "+f"(c[0]), "+f"(c[1]), "+f"(c[2]), "+f"(c[3])
        : "r"(a[0]), "r"(a[1]), "r"(a[2]), "r"(a[3]), "r"(b0), "r"(b1));
}
__device__ __forceinline__ void mma_f16(float* c, const uint32_t* a, uint32_t b0, uint32_t b1) {
    asm volatile(
        "mma.sync.aligned.m16n8k16.row.col.f32.f16.f16.f32 "
        "{%0,%1,%2,%3}, {%4,%5,%6,%7}, {%8,%9}, {%0,%1,%2,%3};\n"
        : "+f"(c[0]), "+f"(c[1]), "+f"(c[2]), "+f"(c[3])
        : "r"(a[0]), "r"(a[1]), "r"(a[2]), "r"(a[3]), "r"(b0), "r"(b1));
}
__device__ __forceinline__ uint32_t pack_bf16(float lo, float hi) {
    __nv_bfloat162 v = __floats2bfloat162_rn(lo, hi);
    return *(uint32_t*)&v;
}

// QKV epilogue store: n in [0,768). Block-uniform branch (64-col tiles).
__device__ __forceinline__ void store_qkv(int row, int n, float a, float b) {
    int d = n & 31;
    int hh = (n >> 5) & 7;
    if (n < 256) {
        *(uint32_t*)(g_Qb + ((size_t)hh*NN + row)*32 + d) = pack_bf16(a*QSCALE_F, b*QSCALE_F);
    } else if (n < 512) {
        *(uint32_t*)(g_Kb + ((size_t)hh*NN + row)*32 + d) = pack_bf16(a, b);
    } else {
        g_Vh[((size_t)hh*32 + d    )*NN + row] = __float2half(a);
        g_Vh[((size_t)hh*32 + d + 1)*NN + row] = __float2half(b);
    }
}

// ---------------- fused conversion kernels ----------------------------------------
__device__ __forceinline__ void tr_tile(const float* __restrict__ in, __half* __restrict__ out,
                                        int K, int N, int n0, int k0, int tid) {
    __shared__ float t[32][33];
    int tx = tid & 31, ty = tid >> 5;
    #pragma unroll
    for (int i = ty; i < 32; i += 8)
        t[i][tx] = in[(size_t)(k0 + i)*N + n0 + tx];
    __syncthreads();
    #pragma unroll
    for (int i = ty; i < 32; i += 8)
        out[(size_t)(n0 + i)*K + k0 + tx] = __float2half(t[tx][i]);
}

// prep_x: blocks [0,512) convert x -> fp16 (131072 float4s); [512,544) transpose W1.
__global__ void __launch_bounds__(256) prep_x(const float* __restrict__ x,
                                              const float* __restrict__ W1) {
    int b = blockIdx.x;
    if (b < 512) {
        int i = b * 256 + threadIdx.x;     // over NN*128/4 = 131072 float4s
        float4 v = ((const float4*)x)[i];
        __half2 a = __floats2half2_rn(v.x, v.y), c = __floats2half2_rn(v.z, v.w);
        ((uint2*)g_xH)[i] = make_uint2(*(uint32_t*)&a, *(uint32_t*)&c);
    } else {
        int bb = b - 512;                  // 32 tiles: (8 n-tiles) x (4 k-tiles)
        tr_tile(W1, g_W1t, 128, 256, (bb & 7) * 32, (bb >> 3) * 32, threadIdx.x);
    }
}

// prep_w: blocks [0,64) W2^T; [64,128) W3^T; [128,448) cvt in_w/out_w/fp1/pd1.
__global__ void __launch_bounds__(256) prep_w(const float* __restrict__ W2,
                                              const float* __restrict__ W3,
                                              const float* __restrict__ in_w,
                                              const float* __restrict__ out_w,
                                              const float* __restrict__ fp1w,
                                              const float* __restrict__ pd1w) {
    int b = blockIdx.x;
    if (b < 64) {
        tr_tile(W2, g_W2t, 256, 256, (b & 7) * 32, (b >> 3) * 32, threadIdx.x);
    } else if (b < 128) {
        int bb = b - 64;
        tr_tile(W3, g_W3t, 256, 256, (bb & 7) * 32, (bb >> 3) * 32, threadIdx.x);
    } else {
        // packed fp32->fp16, 4 elems/thread. totals: in_w 196608, out_w 65536, fp1/pd1 32768 each.
        int i = (b - 128) * 256 + threadIdx.x;      // 0 .. 81919
        if (i < 196608/4) {
            float4 v = ((const float4*)in_w)[i];
            __half2 a = __floats2half2_rn(v.x, v.y), c = __floats2half2_rn(v.z, v.w);
            ((uint2*)g_inwH)[i] = make_uint2(*(uint32_t*)&a, *(uint32_t*)&c);
        }
        if (i < 65536/4) {
            float4 v = ((const float4*)out_w)[i];
            __half2 a = __floats2half2_rn(v.x, v.y), c = __floats2half2_rn(v.z, v.w);
            ((uint2*)g_outwH)[i] = make_uint2(*(uint32_t*)&a, *(uint32_t*)&c);
        }
        if (i < 32768/4) {
            float4 v = ((const float4*)fp1w)[i];
            __half2 a = __floats2half2_rn(v.x, v.y), c = __floats2half2_rn(v.z, v.w);
            ((uint2*)g_fp1H)[i] = make_uint2(*(uint32_t*)&a, *(uint32_t*)&c);
            float4 u = ((const float4*)pd1w)[i];
            __half2 d = __floats2half2_rn(u.x, u.y), e = __floats2half2_rn(u.z, u.w);
            ((uint2*)g_pd1H)[i] = make_uint2(*(uint32_t*)&d, *(uint32_t*)&e);
        }
    }
}

// ---------------- pipelined fp16 GEMM (128x64, 3-stage ring, TRANSB always) -------
template<bool RELU, bool ADDSRC, bool QKV, bool DUALB, bool OUTH>
__global__ void __launch_bounds__(256) gemm_f16(
    const __half* __restrict__ A, const __half* __restrict__ Bt,
    const __half* __restrict__ Bt2, const float* __restrict__ bias,
    const float* __restrict__ bias2, const float* __restrict__ SRC,
    void* __restrict__ Cv, void* __restrict__ C2v, int M, int N, int K)
{
    __shared__ __half As[3][128*24];    // [m][k], stride 24 halves (conflict-free)
    __shared__ __half Bs[3][64*24];

    const int tid  = threadIdx.x;
    const int w    = tid >> 5, lane = tid & 31;
    const int g    = lane >> 2, t = lane & 3;
    const int wm   = w & 3, wn = w >> 2;
    const int m0   = blockIdx.y * 128;
    void* Cuse = Cv;
    int n0;
    if (DUALB) {
        n0 = (blockIdx.x & 1) * 64;
        if (blockIdx.x >= 2) { Bt = Bt2; bias = bias2; Cuse = C2v; }
    } else {
        n0 = blockIdx.x * 64;
    }
    const int KT = K >> 4;

    const int arow = tid >> 1, ac8 = (tid & 1) * 8;
    const int brow = tid >> 1, bc8 = (tid & 1) * 8;

    float acc[2][4][4] = {};

    #pragma unroll
    for (int p = 0; p < 2; p++) {
        const int k0 = p << 4;
        cp_async16(&As[p][arow*24 + ac8], A + (size_t)(m0 + arow)*K + k0 + ac8);
        if (tid < 128)
            cp_async16(&Bs[p][brow*24 + bc8], Bt + (size_t)(n0 + brow)*K + k0 + bc8);
        CP_COMMIT();
    }

    for (int kt = 0; kt < KT; kt++) {
        const int st = kt % 3;
        if (kt + 1 < KT) { CP_WAIT(1); } else { CP_WAIT(0); }
        __syncthreads();
        if (kt + 2 < KT) {
            const int sp = (kt + 2) % 3;
            const int k0 = (kt + 2) << 4;
            cp_async16(&As[sp][arow*24 + ac8], A + (size_t)(m0 + arow)*K + k0 + ac8);
            if (tid < 128)
                cp_async16(&Bs[sp][brow*24 + bc8], Bt + (size_t)(n0 + brow)*K + k0 + bc8);
            CP_COMMIT();
        }

        const uint32_t* as = (const uint32_t*)As[st];
        const uint32_t* bs = (const uint32_t*)Bs[st];
        uint32_t a[2][4];
        #pragma unroll
        for (int mt = 0; mt < 2; mt++) {
            int row = wm*32 + mt*16 + g;
            a[mt][0] = as[(row  )*12 + t];
            a[mt][1] = as[(row+8)*12 + t];
            a[mt][2] = as[(row  )*12 + t + 4];
            a[mt][3] = as[(row+8)*12 + t + 4];
        }
        #pragma unroll
        for (int nt = 0; nt < 4; nt++) {
            int n = wn*32 + nt*8 + g;
            uint32_t b0 = bs[n*12 + t];
            uint32_t b1 = bs[n*12 + t + 4];
            mma_f16(acc[0][nt], a[0], b0, b1);
            mma_f16(acc[1][nt], a[1], b0, b1);
        }
    }

    #pragma unroll
    for (int mt = 0; mt < 2; mt++) {
        const int r0 = m0 + wm*32 + mt*16 + g;
        #pragma unroll
        for (int nt = 0; nt < 4; nt++) {
            const int n = n0 + wn*32 + nt*8 + 2*t;
            float bb0 = bias ? bias[n] : 0.f;
            float bb1 = bias ? bias[n+1] : 0.f;
            float v00 = acc[mt][nt][0] + bb0, v01 = acc[mt][nt][1] + bb1;
            float v10 = acc[mt][nt][2] + bb0, v11 = acc[mt][nt][3] + bb1;
            if (ADDSRC) {
                v00 += SRC[(size_t)r0*N + n];     v01 += SRC[(size_t)r0*N + n + 1];
                v10 += SRC[(size_t)(r0+8)*N + n]; v11 += SRC[(size_t)(r0+8)*N + n + 1];
            }
            if (RELU) {
                v00 = fmaxf(v00, 0.f); v01 = fmaxf(v01, 0.f);
                v10 = fmaxf(v10, 0.f); v11 = fmaxf(v11, 0.f);
            }
            if (QKV) {
                store_qkv(r0,     n, v00, v01);
                store_qkv(r0 + 8, n, v10, v11);
            } else if (OUTH) {
                __half* C = (__half*)Cuse;
                __half2 h0 = __floats2half2_rn(v00, v01);
                __half2 h1 = __floats2half2_rn(v10, v11);
                *(uint32_t*)(C + (size_t)r0*N + n)     = *(uint32_t*)&h0;
                *(uint32_t*)(C + (size_t)(r0+8)*N + n) = *(uint32_t*)&h1;
            } else {
                float* C = (float*)Cuse;
                *(float2*)(C + (size_t)r0*N + n)     = make_float2(v00, v01);
                *(float2*)(C + (size_t)(r0+8)*N + n) = make_float2(v10, v11);
            }
        }
    }
}

// ---------------- graph preprocessing (CSR build; 4 edges/thread, int4 loads) -----
__global__ void deg_count(const int* __restrict__ dst) {
    int i = blockIdx.x * 256 + threadIdx.x;
    int4 d4 = ((const int4*)dst)[i];
    atomicAdd(&g_deg[d4.x], 1.0f);
    atomicAdd(&g_deg[d4.y], 1.0f);
    atomicAdd(&g_deg[d4.z], 1.0f);
    atomicAdd(&g_deg[d4.w], 1.0f);
}

__global__ void __launch_bounds__(1024) scan_rowptr() {
    __shared__ int warpsum[32];
    const int tid = threadIdx.x;
    const int lane = tid & 31, wid = tid >> 5;
    const int base = tid * 4;
    int c[4], s = 0;
    #pragma unroll
    for (int j = 0; j < 4; j++) {
        c[j] = (int)g_deg[base + j];
        g_dinv[base + j] = rsqrtf((float)c[j] + 1.0f);
        s += c[j];
    }
    int pre = s;
    #pragma unroll
    for (int off = 1; off < 32; off <<= 1) {
        int v = __shfl_up_sync(0xffffffffu, pre, off);
        if (lane >= off) pre += v;
    }
    if (lane == 31) warpsum[wid] = pre;
    __syncthreads();
    if (wid == 0) {
        int v = warpsum[lane];
        #pragma unroll
        for (int off = 1; off < 32; off <<= 1) {
            int u = __shfl_up_sync(0xffffffffu, v, off);
            if (lane >= off) v += u;
        }
        warpsum[lane] = v;
    }
    __syncthreads();
    int excl = pre - s + (wid > 0 ? warpsum[wid-1] : 0);
    int run = excl;
    #pragma unroll
    for (int j = 0; j < 4; j++) {
        g_rowptr[base + j] = run;
        g_cursor[base + j] = run;
        run += c[j];
    }
    if (tid == 1023) g_rowptr[NN] = run;
}

__global__ void csr_scatter(const int* __restrict__ src, const int* __restrict__ dst) {
    int i = blockIdx.x * 256 + threadIdx.x;
    int4 s4 = ((const int4*)src)[i];
    int4 d4 = ((const int4*)dst)[i];
    int sv[4] = {s4.x, s4.y, s4.z, s4.w};
    int dv[4] = {d4.x, d4.y, d4.z, d4.w};
    #pragma unroll
    for (int j = 0; j < 4; j++) {
        int p = atomicAdd(&g_cursor[dv[j]], 1);
        g_esrc[p]  = sv[j];
        g_enorm[p] = g_dinv[sv[j]] * g_dinv[dv[j]];
    }
}

// ---------------- GCN gather (fp16 in, fp16 out; H3 also writes fp32) -------------
__device__ __forceinline__ void acc_row(const uint4 v, float wgt, float* a) {
    float2 f0 = __half22float2(*(const __half2*)&v.x);
    float2 f1 = __half22float2(*(const __half2*)&v.y);
    float2 f2 = __half22float2(*(const __half2*)&v.z);
    float2 f3 = __half22float2(*(const __half2*)&v.w);
    a[0] = fmaf(wgt, f0.x, a[0]); a[1] = fmaf(wgt, f0.y, a[1]);
    a[2] = fmaf(wgt, f1.x, a[2]); a[3] = fmaf(wgt, f1.y, a[3]);
    a[4] = fmaf(wgt, f2.x, a[4]); a[5] = fmaf(wgt, f2.y, a[5]);
    a[6] = fmaf(wgt, f3.x, a[6]); a[7] = fmaf(wgt, f3.y, a[7]);
}

template<bool RELU, bool H3>
__global__ void __launch_bounds__(256) gcn_gather(const float* __restrict__ bias,
                                                  __half* __restrict__ outH,
                                                  float* __restrict__ outF) {
    const int node = blockIdx.x * 8 + (threadIdx.x >> 5);
    const int lane = threadIdx.x & 31;
    const int beg = g_rowptr[node], end = g_rowptr[node+1];

    float a[8] = {};
    int i = beg;
    for (; i + 2 <= end; i += 2) {
        int s0i = g_esrc[i],   s1i = g_esrc[i+1];
        float w0 = g_enorm[i], w1 = g_enorm[i+1];
        uint4 x = *((const uint4*)(g_tmpH + (size_t)s0i*HH) + lane);
        uint4 y = *((const uint4*)(g_tmpH + (size_t)s1i*HH) + lane);
        acc_row(x, w0, a);
        acc_row(y, w1, a);
    }
    if (i < end) {
        uint4 x = *((const uint4*)(g_tmpH + (size_t)g_esrc[i]*HH) + lane);
        acc_row(x, g_enorm[i], a);
    }
    float di = g_dinv[node];
    float sw = di * di;
    uint4 sv = *((const uint4*)(g_tmpH + (size_t)node*HH) + lane);
    acc_row(sv, sw, a);

    const float4* bp = (const float4*)(bias + lane*8);
    float4 b0 = bp[0], b1 = bp[1];
    float o0 = a[0] + b0.x, o1 = a[1] + b0.y, o2 = a[2] + b0.z, o3 = a[3] + b0.w;
    float o4 = a[4] + b1.x, o5 = a[5] + b1.y, o6 = a[6] + b1.z, o7 = a[7] + b1.w;
    if (RELU) {
        o0 = fmaxf(o0,0.f); o1 = fmaxf(o1,0.f); o2 = fmaxf(o2,0.f); o3 = fmaxf(o3,0.f);
        o4 = fmaxf(o4,0.f); o5 = fmaxf(o5,0.f); o6 = fmaxf(o6,0.f); o7 = fmaxf(o7,0.f);
    }
    __half2 ph0 = __floats2half2_rn(o0,o1), ph1 = __floats2half2_rn(o2,o3);
    __half2 ph2 = __floats2half2_rn(o4,o5), ph3 = __floats2half2_rn(o6,o7);
    *((uint4*)(outH + (size_t)node*HH) + lane) =
        make_uint4(*(uint32_t*)&ph0, *(uint32_t*)&ph1, *(uint32_t*)&ph2, *(uint32_t*)&ph3);
    if (H3) {
        float4* op = (float4*)(outF + (size_t)node*HH + lane*8);
        op[0] = make_float4(o0,o1,o2,o3);
        op[1] = make_float4(o4,o5,o6,o7);
    }
}

// ---------------- flash attention: 256-query tiles, bf16 QK, fp16 softmax/PV ------
__global__ void __launch_bounds__(256) flash_attn_bf16() {
    __shared__ __align__(16) char Ks[3][64*80];
    __shared__ __align__(16) char Vs[3][32*144];

    const int head = blockIdx.y;
    const int q0   = blockIdx.x * 256;
    const int tid  = threadIdx.x;
    const int w    = tid >> 5, lane = tid & 31;
    const int g    = lane >> 2, t = lane & 3;
    const int KT   = NN / 64;
    const uint32_t ONES2 = 0x3C003C00u;

    const __nv_bfloat16* kg = g_Kb + (size_t)head*NN*32;
    const __half*        vg = g_Vh + (size_t)head*32*NN;

    const int kr8 = tid >> 2, kc8 = (tid & 3) * 8;
    const int vd  = tid >> 3, vk8 = (tid & 7) * 8;

    cp_async16(&Ks[0][kr8*80 + kc8*2], kg + (size_t)kr8*32 + kc8);
    cp_async16(&Vs[0][vd*144 + vk8*2], vg + (size_t)vd*NN + vk8);
    CP_COMMIT();
    cp_async16(&Ks[1][kr8*80 + kc8*2], kg + (size_t)(64 + kr8)*32 + kc8);
    cp_async16(&Vs[1][vd*144 + vk8*2], vg + (size_t)vd*NN + 64 + vk8);
    CP_COMMIT();

    uint32_t aq[2][2][4];
    #pragma unroll
    for (int qh = 0; qh < 2; qh++) {
        const __nv_bfloat16* qb = g_Qb + ((size_t)head*NN + q0 + qh*128 + w*16) * 32;
        #pragma unroll
        for (int ks = 0; ks < 2; ks++) {
            int c = ks*16 + 2*t;
            aq[qh][ks][0] = *(const uint32_t*)(qb + (size_t)(g  )*32 + c);
            aq[qh][ks][1] = *(const uint32_t*)(qb + (size_t)(g+8)*32 + c);
            aq[qh][ks][2] = *(const uint32_t*)(qb + (size_t)(g  )*32 + c + 8);
            aq[qh][ks][3] = *(const uint32_t*)(qb + (size_t)(g+8)*32 + c + 8);
        }
    }

    float m[2][2];
    m[0][0] = m[0][1] = m[1][0] = m[1][1] = -1e30f;
    float o[2][4][4] = {};
    float lacc[2][4] = {};

    for (int kt = 0; kt < KT; kt++) {
        const int st = kt % 3;
        if (kt + 1 < KT) { CP_WAIT(1); } else { CP_WAIT(0); }
        __syncthreads();
        if (kt + 2 < KT) {
            const int sp = (kt + 2) % 3;
            cp_async16(&Ks[sp][kr8*80 + kc8*2], kg + (size_t)((kt+2)*64 + kr8)*32 + kc8);
            cp_async16(&Vs[sp][vd*144 + vk8*2], vg + (size_t)vd*NN + (kt+2)*64 + vk8);
            CP_COMMIT();
        }

        #pragma unroll
        for (int qh = 0; qh < 2; qh++) {
            float s[8][4];
            #pragma unroll
            for (int nb = 0; nb < 8; nb++) {
                s[nb][0] = s[nb][1] = s[nb][2] = s[nb][3] = 0.f;
                const char* kr = Ks[st] + (nb*8 + g)*80;
                uint32_t b0 = *(const uint32_t*)(kr + (2*t)*2);
                uint32_t b1 = *(const uint32_t*)(kr + (2*t+8)*2);
                mma_bf16(s[nb], aq[qh][0], b0, b1);
                b0 = *(const uint32_t*)(kr + (16 + 2*t)*2);
                b1 = *(const uint32_t*)(kr + (16 + 2*t+8)*2);
                mma_bf16(s[nb], aq[qh][1], b0, b1);
            }

            float tm0 = -1e30f, tm1 = -1e30f;
            #pragma unroll
            for (int nb = 0; nb < 8; nb++) {
                tm0 = fmaxf(tm0, fmaxf(s[nb][0], s[nb][1]));
                tm1 = fmaxf(tm1, fmaxf(s[nb][2], s[nb][3]));
            }
            tm0 = fmaxf(tm0, __shfl_xor_sync(0xffffffffu, tm0, 1));
            tm0 = fmaxf(tm0, __shfl_xor_sync(0xffffffffu, tm0, 2));
            tm1 = fmaxf(tm1, __shfl_xor_sync(0xffffffffu, tm1, 1));
            tm1 = fmaxf(tm1, __shfl_xor_sync(0xffffffffu, tm1, 2));
            float nm0 = fmaxf(m[qh][0], tm0), nm1 = fmaxf(m[qh][1], tm1);
            float al0 = exp2f(m[qh][0] - nm0), al1 = exp2f(m[qh][1] - nm1);
            m[qh][0] = nm0; m[qh][1] = nm1;

            __half2 p01[8], p23[8];
            #pragma unroll
            for (int nb = 0; nb < 8; nb++) {
                p01[nb] = h2exp2(__floats2half2_rn(s[nb][0] - nm0, s[nb][1] - nm0));
                p23[nb] = h2exp2(__floats2half2_rn(s[nb][2] - nm1, s[nb][3] - nm1));
            }

            #pragma unroll
            for (int nbv = 0; nbv < 4; nbv++) {
                o[qh][nbv][0] *= al0; o[qh][nbv][1] *= al0;
                o[qh][nbv][2] *= al1; o[qh][nbv][3] *= al1;
            }
            lacc[qh][0] *= al0; lacc[qh][1] *= al0;
            lacc[qh][2] *= al1; lacc[qh][3] *= al1;

            uint32_t ap[4][4];
            #pragma unroll
            for (int s4 = 0; s4 < 4; s4++) {
                ap[s4][0] = *(const uint32_t*)&p01[2*s4];
                ap[s4][1] = *(const uint32_t*)&p23[2*s4];
                ap[s4][2] = *(const uint32_t*)&p01[2*s4+1];
                ap[s4][3] = *(const uint32_t*)&p23[2*s4+1];
            }

            #pragma unroll
            for (int s4 = 0; s4 < 4; s4++) {
                mma_f16(lacc[qh], ap[s4], ONES2, ONES2);
                #pragma unroll
                for (int nbv = 0; nbv < 4; nbv++) {
                    const char* vr = Vs[st] + (nbv*8 + g)*144;
                    uint32_t b0 = *(const uint32_t*)(vr + (16*s4 + 2*t)*2);
                    uint32_t b1 = *(const uint32_t*)(vr + (16*s4 + 2*t + 8)*2);
                    mma_f16(o[qh][nbv], ap[s4], b0, b1);
                }
            }
        }
    }

    #pragma unroll
    for (int qh = 0; qh < 2; qh++) {
        float inv0 = 1.0f / lacc[qh][0], inv1 = 1.0f / lacc[qh][2];
        int row0 = q0 + qh*128 + w*16 + g;
        #pragma unroll
        for (int nbv = 0; nbv < 4; nbv++) {
            int col = head*32 + nbv*8 + 2*t;
            __half2 h0 = __floats2half2_rn(o[qh][nbv][0]*inv0, o[qh][nbv][1]*inv0);
            __half2 h1 = __floats2half2_rn(o[qh][nbv][2]*inv1, o[qh][nbv][3]*inv1);
            *(uint32_t*)(g_attnH + (size_t)row0*HH + col)     = *(uint32_t*)&h0;
            *(uint32_t*)(g_attnH + (size_t)(row0+8)*HH + col) = *(uint32_t*)&h1;
        }
    }
}

// ---------------- fused output heads (warp per node: softmax3 + sigmoid10) --------
__global__ void __launch_bounds__(256) head_both(const float* __restrict__ W3,
                                                 const float* __restrict__ b3v,
                                                 const float* __restrict__ W10,
                                                 const float* __restrict__ b10,
                                                 float* __restrict__ out) {
    const int node = blockIdx.x * 8 + (threadIdx.x >> 5);
    const int lane = threadIdx.x & 31;

    float4 hv = *(const float4*)(g_hid + (size_t)node*128 + lane*4);
    float lg3[3];
    #pragma unroll
    for (int c = 0; c < 3; c++) {
        float4 wv = *(const float4*)(W3 + c*128 + lane*4);
        float d = hv.x*wv.x + hv.y*wv.y + hv.z*wv.z + hv.w*wv.w;
        #pragma unroll
        for (int m = 16; m >= 1; m >>= 1) d += __shfl_xor_sync(0xffffffffu, d, m);
        lg3[c] = d + b3v[c];
    }
    float4 hv2 = *(const float4*)(g_hid2 + (size_t)node*128 + lane*4);
    float lg10[10];
    #pragma unroll
    for (int c = 0; c < 10; c++) {
        float4 wv = *(const float4*)(W10 + c*128 + lane*4);
        float d = hv2.x*wv.x + hv2.y*wv.y + hv2.z*wv.z + hv2.w*wv.w;
        #pragma unroll
        for (int m = 16; m >= 1; m >>= 1) d += __shfl_xor_sync(0xffffffffu, d, m);
        lg10[c] = d + b10[c];
    }
    if (lane == 0) {
        float mx = fmaxf(fmaxf(lg3[0], lg3[1]), lg3[2]);
        float e0 = __expf(lg3[0]-mx), e1 = __expf(lg3[1]-mx), e2 = __expf(lg3[2]-mx);
        float inv = 1.0f / (e0 + e1 + e2);
        out[(size_t)node*3 + 0] = e0*inv;
        out[(size_t)node*3 + 1] = e1*inv;
        out[(size_t)node*3 + 2] = e2*inv;
        float* o2 = out + (size_t)NN*3 + (size_t)node*10;
        #pragma unroll
        for (int c = 0; c < 10; c++)
            o2[c] = 1.0f / (1.0f + __expf(-lg10[c]));
    }
}

// ---------------- launch ---------------------------------------------------------
extern "C" void kernel_launch(void* const* d_in, const int* in_sizes, int n_in,
                              void* d_out, int out_size)
{
    const float* x     = (const float*)d_in[0];
    const int*   ei    = (const int*)  d_in[1];
    const float* W1    = (const float*)d_in[2];
    const float* b1    = (const float*)d_in[3];
    const float* W2    = (const float*)d_in[4];
    const float* b2    = (const float*)d_in[5];
    const float* W3    = (const float*)d_in[6];
    const float* b3    = (const float*)d_in[7];
    const float* in_w  = (const float*)d_in[8];
    const float* in_b  = (const float*)d_in[9];
    const float* out_w = (const float*)d_in[10];
    const float* out_b = (const float*)d_in[11];
    const float* fp1w  = (const float*)d_in[12];
    const float* fp1b  = (const float*)d_in[13];
    const float* fp2w  = (const float*)d_in[14];
    const float* fp2b  = (const float*)d_in[15];
    const float* pd1w  = (const float*)d_in[16];
    const float* pd1b  = (const float*)d_in[17];
    const float* pd2w  = (const float*)d_in[18];
    const float* pd2b  = (const float*)d_in[19];
    const int* src = ei;
    const int* dst = ei + EE;
    float* outp = (float*)d_out;

    void *tmph, *hh, *h3h, *attnh, *xh, *w1t, *w2t, *w3t, *inwh, *outwh, *fp1h, *pd1h;
    float *h3, *deg, *hid, *hid2;
    cudaGetSymbolAddress((void**)&tmph,  g_tmpH);
    cudaGetSymbolAddress((void**)&hh,    g_hH);
    cudaGetSymbolAddress((void**)&h3h,   g_h3H);
    cudaGetSymbolAddress((void**)&h3,    g_h3);
    cudaGetSymbolAddress((void**)&attnh, g_attnH);
    cudaGetSymbolAddress((void**)&deg,   g_deg);
    cudaGetSymbolAddress((void**)&hid,   g_hid);
    cudaGetSymbolAddress((void**)&hid2,  g_hid2);
    cudaGetSymbolAddress((void**)&xh,    g_xH);
    cudaGetSymbolAddress((void**)&w1t,   g_W1t);
    cudaGetSymbolAddress((void**)&w2t,   g_W2t);
    cudaGetSymbolAddress((void**)&w3t,   g_W3t);
    cudaGetSymbolAddress((void**)&inwh,  g_inwH);
    cudaGetSymbolAddress((void**)&outwh, g_outwH);
    cudaGetSymbolAddress((void**)&fp1h,  g_fp1H);
    cudaGetSymbolAddress((void**)&pd1h,  g_pd1H);

    static cudaStream_t s2 = nullptr;
    static cudaEvent_t evF = nullptr, evJ = nullptr, evW = nullptr;
    if (!s2) {
        cudaStreamCreateWithFlags(&s2, cudaStreamNonBlocking);
        cudaEventCreateWithFlags(&evF, cudaEventDisableTiming);
        cudaEventCreateWithFlags(&evJ, cudaEventDisableTiming);
        cudaEventCreateWithFlags(&evW, cudaEventDisableTiming);
    }

    const dim3 blk(256);

    // Fork: CSR build FIRST on s2 (join feeds gather1), then fused weight prep.
    cudaEventRecord(evF, 0);
    cudaStreamWaitEvent(s2, evF, 0);
    cudaMemsetAsync(deg, 0, NN * sizeof(float), s2);
    deg_count<<<EE/1024, 256, 0, s2>>>(dst);
    scan_rowptr<<<1, 1024, 0, s2>>>();
    csr_scatter<<<EE/1024, 256, 0, s2>>>(src, dst);
    cudaEventRecord(evJ, s2);
    prep_w<<<448, blk, 0, s2>>>(W2, W3, in_w, out_w, fp1w, pd1w);
    cudaEventRecord(evW, s2);

    prep_x<<<544, blk>>>(x, W1);
    gemm_f16<false,false,false,false,true><<<dim3(4,32), blk>>>(
        (const __half*)xh, (const __half*)w1t, nullptr, nullptr, nullptr, nullptr,
        tmph, nullptr, NN, HH, 128);
    cudaStreamWaitEvent(0, evJ, 0);     // CSR ready

    gcn_gather<true,false><<<NN/8, blk>>>(b1, (__half*)hh, nullptr);
    cudaStreamWaitEvent(0, evW, 0);     // weight prep ready (overlapped w/ gather1)
    gemm_f16<false,false,false,false,true><<<dim3(4,32), blk>>>(
        (const __half*)hh, (const __half*)w2t, nullptr, nullptr, nullptr, nullptr,
        tmph, nullptr, NN, HH, HH);
    gcn_gather<true,false><<<NN/8, blk>>>(b2, (__half*)hh, nullptr);
    gemm_f16<false,false,false,false,true><<<dim3(4,32), blk>>>(
        (const __half*)hh, (const __half*)w3t, nullptr, nullptr, nullptr, nullptr,
        tmph, nullptr, NN, HH, HH);
    gcn_gather<false,true><<<NN/8, blk>>>(b3, (__half*)h3h, h3);

    // MHA: fused QKV gemm -> (g_Qb, g_Kb, g_Vh); flash attention (256-row tiles)
    gemm_f16<false,false,true,false,false><<<dim3(12,32), blk>>>(
        (const __half*)h3h, (const __half*)inwh, nullptr, in_b, nullptr, nullptr,
        nullptr, nullptr, NN, 3*HH, HH);
    flash_attn_bf16<<<dim3(NN/256, 8), blk>>>();
    gemm_f16<false,true,false,false,true><<<dim3(4,32), blk>>>(
        (const __half*)attnh, (const __half*)outwh, nullptr, out_b, nullptr, h3,
        hh, nullptr, NN, HH, HH);

    // Fused dual-head GEMM + fused heads
    gemm_f16<true,false,false,true,false><<<dim3(4,32), blk>>>(
        (const __half*)hh, (const __half*)fp1h, (const __half*)pd1h, fp1b, pd1b, nullptr,
        hid, hid2, NN, 128, HH);
    head_both<<<NN/8, blk>>>(fp2w, fp2b, pd2w, pd2b, outp);
}